// round 1
// baseline (speedup 1.0000x reference)
#include <cuda_runtime.h>
#include <cuda_bf16.h>
#include <math.h>

// Problem constants
#define NROWS 8192
#define DDIM  128
#define WVDIM 300
#define BIGF  1e8f
#define DEPS  1.28e-14f   // D * 1e-16

// Scratch (allocation-free rule: __device__ globals)
__device__ float g_ssq[NROWS];
__device__ float g_xsq[NROWS];
__device__ int   g_fp_bits[NROWS];   // furthest positive, float bits (all >= 0)
__device__ int   g_cn_bits[NROWS];   // closest negative, float bits (all > 0)

// ---------------------------------------------------------------------------
// Kernel A: sem = alpha * (wv @ W^T + b) + (1-alpha) * x
// block: 128 threads (one per d), TM=32 rows per block, W staged in smem chunks
// ---------------------------------------------------------------------------
#define KC 50          // K-chunk of the 300-dim
#define KCP 51         // padded pitch (51 % 32 = 19, gcd(19,32)=1 -> conflict free)
#define TMA_ 32

__global__ __launch_bounds__(128) void fc_mix_kernel(
    const float* __restrict__ wv,    // [N, 300]
    const float* __restrict__ W,     // [128, 300]
    const float* __restrict__ b,     // [128]
    const float* __restrict__ alpha, // [N, 1]
    const float* __restrict__ x,     // [N, 128]
    float* __restrict__ sem_out)     // [N, 128]
{
    __shared__ float Ws[DDIM * KCP];     // 128 x 51 floats = 26.1 KB
    __shared__ float wvs[TMA_ * KC];     // 32 x 50 = 6.4 KB

    const int tid  = threadIdx.x;        // = d
    const int row0 = blockIdx.x * TMA_;

    float acc[TMA_];
    #pragma unroll
    for (int m = 0; m < TMA_; m++) acc[m] = 0.f;

    for (int c = 0; c < WVDIM / KC; c++) {
        __syncthreads();
        // stage W chunk: Ws[d][w] = W[d][c*KC + w]
        for (int l = tid; l < DDIM * KC; l += 128) {
            int d = l / KC, w = l - d * KC;
            Ws[d * KCP + w] = W[d * WVDIM + c * KC + w];
        }
        // stage wv chunk
        for (int l = tid; l < TMA_ * KC; l += 128) {
            int m = l / KC, w = l - m * KC;
            wvs[m * KC + w] = wv[(size_t)(row0 + m) * WVDIM + c * KC + w];
        }
        __syncthreads();

        #pragma unroll 2
        for (int w = 0; w < KC; w++) {
            float wd = Ws[tid * KCP + w];
            #pragma unroll
            for (int m = 0; m < TMA_; m++)
                acc[m] = fmaf(wvs[m * KC + w], wd, acc[m]);
        }
    }

    float bd = b[tid];
    #pragma unroll
    for (int m = 0; m < TMA_; m++) {
        int row = row0 + m;
        float al = alpha[row];
        float s = al * (acc[m] + bd) + (1.f - al) * x[(size_t)row * DDIM + tid];
        sem_out[(size_t)row * DDIM + tid] = s;
    }
}

// ---------------------------------------------------------------------------
// Kernel B: per-row squared norms of sem and x + init mining accumulators.
// One warp per row (128 floats = 1 float4 per lane).
// ---------------------------------------------------------------------------
__global__ __launch_bounds__(256) void norms_init_kernel(
    const float* __restrict__ sem,
    const float* __restrict__ x)
{
    int gwarp = (blockIdx.x * blockDim.x + threadIdx.x) >> 5;
    int lane  = threadIdx.x & 31;
    if (gwarp >= NROWS) return;

    const float4* s4 = reinterpret_cast<const float4*>(sem) + (size_t)gwarp * 32;
    const float4* x4 = reinterpret_cast<const float4*>(x)   + (size_t)gwarp * 32;
    float4 sv = s4[lane];
    float4 xv = x4[lane];
    float ss = sv.x*sv.x + sv.y*sv.y + sv.z*sv.z + sv.w*sv.w;
    float xs = xv.x*xv.x + xv.y*xv.y + xv.z*xv.z + xv.w*xv.w;
    #pragma unroll
    for (int o = 16; o; o >>= 1) {
        ss += __shfl_xor_sync(0xFFFFFFFFu, ss, o);
        xs += __shfl_xor_sync(0xFFFFFFFFu, xs, o);
    }
    if (lane == 0) {
        g_ssq[gwarp] = ss;
        g_xsq[gwarp] = xs;
        g_fp_bits[gwarp] = 0;            // 0.0f
        g_cn_bits[gwarp] = 0x7F7FFFFF;   // FLT_MAX
    }
}

// ---------------------------------------------------------------------------
// Kernel C: fused GEMM (sem @ x^T, K=128) + distance + batch-hard mining.
// BM = BN = 128, 256 threads, 8x8 micro-tile per thread (strided 16).
// smem: 2 tiles of [128][33] float4 (pitch 33 -> conflict-free).
// ---------------------------------------------------------------------------
#define TILE_PITCH4 33
#define DIST_SMEM (2 * 128 * TILE_PITCH4 * (int)sizeof(float4))

__global__ __launch_bounds__(256, 1) void dist_mine_kernel(
    const float* __restrict__ sem,
    const float* __restrict__ x,
    const int*   __restrict__ label)
{
    extern __shared__ float4 smem4[];
    float4* As = smem4;                         // [128][33] : sem tile, K-major
    float4* Bs = smem4 + 128 * TILE_PITCH4;     // [128][33] : x tile,   K-major

    __shared__ int   lblN[128];
    __shared__ float xsqN[128];

    const int tid = threadIdx.x;
    const int m0  = blockIdx.y * 128;
    const int n0  = blockIdx.x * 128;

    const float4* gA = reinterpret_cast<const float4*>(sem) + (size_t)m0 * 32;
    const float4* gB = reinterpret_cast<const float4*>(x)   + (size_t)n0 * 32;

    #pragma unroll
    for (int it = 0; it < 16; it++) {
        int idx = it * 256 + tid;          // 0..4095
        int r  = idx >> 5;                 // row 0..127
        int k4 = idx & 31;                 // float4-column 0..31
        As[r * TILE_PITCH4 + k4] = gA[(size_t)r * 32 + k4];
        Bs[r * TILE_PITCH4 + k4] = gB[(size_t)r * 32 + k4];
    }
    if (tid < 128) {
        lblN[tid] = label[n0 + tid];
        xsqN[tid] = g_xsq[n0 + tid];
    }
    __syncthreads();

    const int tx = tid & 15;   // n-group
    const int ty = tid >> 4;   // m-group

    float acc[8][8];
    #pragma unroll
    for (int i = 0; i < 8; i++)
        #pragma unroll
        for (int j = 0; j < 8; j++) acc[i][j] = 0.f;

    #pragma unroll 4
    for (int k4 = 0; k4 < 32; k4++) {
        float4 a[8], bfr[8];
        #pragma unroll
        for (int i = 0; i < 8; i++) a[i]   = As[(ty + 16 * i) * TILE_PITCH4 + k4];
        #pragma unroll
        for (int j = 0; j < 8; j++) bfr[j] = Bs[(tx + 16 * j) * TILE_PITCH4 + k4];
        #pragma unroll
        for (int i = 0; i < 8; i++) {
            #pragma unroll
            for (int j = 0; j < 8; j++) {
                float s = acc[i][j];
                s = fmaf(a[i].x, bfr[j].x, s);
                s = fmaf(a[i].y, bfr[j].y, s);
                s = fmaf(a[i].z, bfr[j].z, s);
                s = fmaf(a[i].w, bfr[j].w, s);
                acc[i][j] = s;
            }
        }
    }

    // Epilogue: distances + batch-hard mining
    float ssqm[8];
    int   lm[8];
    #pragma unroll
    for (int i = 0; i < 8; i++) {
        int gi = m0 + ty + 16 * i;
        ssqm[i] = g_ssq[gi];
        lm[i]   = label[gi];
    }

    #pragma unroll
    for (int i = 0; i < 8; i++) {
        int gi = m0 + ty + 16 * i;
        float fpv = 0.f;
        float cnv = 3.4e38f;
        #pragma unroll
        for (int j = 0; j < 8; j++) {
            int nj = tx + 16 * j;
            int gj = n0 + nj;
            float sq = ssqm[i] + xsqN[nj] - 2.f * acc[i][j];
            float dist = sqrtf(fmaxf(sq, 0.f) + DEPS);
            bool same = (lm[i] == lblN[nj]);
            fpv = fmaxf(fpv, (same && (gi != gj)) ? dist : 0.f);
            cnv = fminf(cnv, same ? dist + BIGF : dist);
        }
        // reduce across the 16 tx lanes (within each half-warp)
        #pragma unroll
        for (int o = 8; o; o >>= 1) {
            fpv = fmaxf(fpv, __shfl_xor_sync(0xFFFFFFFFu, fpv, o));
            cnv = fminf(cnv, __shfl_xor_sync(0xFFFFFFFFu, cnv, o));
        }
        if ((tid & 15) == 0) {
            // all candidate values are positive -> int-bit ordering == float ordering
            atomicMax(&g_fp_bits[gi], __float_as_int(fpv));
            atomicMin(&g_cn_bits[gi], __float_as_int(cnv));
        }
    }
}

// ---------------------------------------------------------------------------
// Kernel D: diff = softplus(furthest_positive - closest_negative)
// ---------------------------------------------------------------------------
__global__ __launch_bounds__(256) void finalize_kernel(float* __restrict__ diff_out)
{
    int i = blockIdx.x * blockDim.x + threadIdx.x;
    if (i >= NROWS) return;
    float fp = __int_as_float(g_fp_bits[i]);
    float cn = __int_as_float(g_cn_bits[i]);
    float z = fp - cn;
    // stable softplus: max(z,0) + log1p(exp(-|z|))
    diff_out[i] = fmaxf(z, 0.f) + log1pf(expf(-fabsf(z)));
}

// ---------------------------------------------------------------------------
// Launch
// Inputs (metadata order): x[N,128] f32, wv[N,300] f32, label[N] i32,
//                          alpha[N,1] f32, W[128,300] f32, b[128] f32
// Output: diff[N] then sem[N,128], float32, concatenated.
// ---------------------------------------------------------------------------
extern "C" void kernel_launch(void* const* d_in, const int* in_sizes, int n_in,
                              void* d_out, int out_size)
{
    const float* x     = (const float*)d_in[0];
    const float* wv    = (const float*)d_in[1];
    const int*   label = (const int*)  d_in[2];
    const float* alpha = (const float*)d_in[3];
    const float* W     = (const float*)d_in[4];
    const float* b     = (const float*)d_in[5];

    float* out  = (float*)d_out;
    float* diff = out;            // [N]
    float* sem  = out + NROWS;    // [N, 128]

    cudaFuncSetAttribute(dist_mine_kernel,
                         cudaFuncAttributeMaxDynamicSharedMemorySize, DIST_SMEM);

    fc_mix_kernel<<<NROWS / TMA_, 128>>>(wv, W, b, alpha, x, sem);
    norms_init_kernel<<<(NROWS * 32) / 256, 256>>>(sem, x);
    dist_mine_kernel<<<dim3(NROWS / 128, NROWS / 128), 256, DIST_SMEM>>>(sem, x, label);
    finalize_kernel<<<NROWS / 256, 256>>>(diff);
}

// round 4
// speedup vs baseline: 1.6550x; 1.6550x over previous
#include <cuda_runtime.h>
#include <cuda_bf16.h>
#include <math.h>
#include <stdint.h>

// Problem constants
#define NROWS 8192
#define DDIM  128
#define WVDIM 300
#define BIGF  1e8f
#define DEPS  1.28e-14f   // D * 1e-16

// ---------------------------------------------------------------------------
// Scratch (__device__ globals; no allocation allowed)
// ---------------------------------------------------------------------------
__device__ float g_ssq[NROWS];
__device__ float g_xsq[NROWS];
__device__ int   g_fp_bits[NROWS];   // furthest positive, float bits (>= 0)
__device__ int   g_cn_bits[NROWS];   // closest negative, float bits (> 0)
// bf16 hi/lo split, row-major: [row][0:128]=hi, [row][128:256]=lo  (512 B/row)
__device__ __nv_bfloat16 g_semB[NROWS * 256];
__device__ __nv_bfloat16 g_xB[NROWS * 256];

// ---------------------------------------------------------------------------
// Warp-MMA helpers (sm_80+ : compile fine for plain sm_100)
// ---------------------------------------------------------------------------
__device__ __forceinline__ uint32_t smem_u32(const void* p) {
    uint32_t a;
    asm("{ .reg .u64 t; cvta.to.shared.u64 t, %1; cvt.u32.u64 %0, t; }" : "=r"(a) : "l"(p));
    return a;
}
__device__ __forceinline__ void ldsm_x4(uint32_t* r, uint32_t addr) {
    asm volatile("ldmatrix.sync.aligned.m8n8.x4.shared.b16 {%0,%1,%2,%3}, [%4];"
                 : "=r"(r[0]), "=r"(r[1]), "=r"(r[2]), "=r"(r[3]) : "r"(addr));
}
__device__ __forceinline__ void mma16816(float* d, const uint32_t* a, const uint32_t* b) {
    asm volatile(
        "mma.sync.aligned.m16n8k16.row.col.f32.bf16.bf16.f32 "
        "{%0,%1,%2,%3}, {%4,%5,%6,%7}, {%8,%9}, {%0,%1,%2,%3};"
        : "+f"(d[0]), "+f"(d[1]), "+f"(d[2]), "+f"(d[3])
        : "r"(a[0]), "r"(a[1]), "r"(a[2]), "r"(a[3]), "r"(b[0]), "r"(b[1]));
}

// ---------------------------------------------------------------------------
// Kernel A: sem = alpha * (wv @ W^T + b) + (1-alpha) * x
// ---------------------------------------------------------------------------
#define KC 50
#define KCP 51
#define TMA_ 32

__global__ __launch_bounds__(128) void fc_mix_kernel(
    const float* __restrict__ wv, const float* __restrict__ W,
    const float* __restrict__ b, const float* __restrict__ alpha,
    const float* __restrict__ x, float* __restrict__ sem_out)
{
    __shared__ float Ws[DDIM * KCP];
    __shared__ float wvs[TMA_ * KC];

    const int tid  = threadIdx.x;
    const int row0 = blockIdx.x * TMA_;

    float acc[TMA_];
    #pragma unroll
    for (int m = 0; m < TMA_; m++) acc[m] = 0.f;

    for (int c = 0; c < WVDIM / KC; c++) {
        __syncthreads();
        for (int l = tid; l < DDIM * KC; l += 128) {
            int d = l / KC, w = l - d * KC;
            Ws[d * KCP + w] = W[d * WVDIM + c * KC + w];
        }
        for (int l = tid; l < TMA_ * KC; l += 128) {
            int m = l / KC, w = l - m * KC;
            wvs[m * KC + w] = wv[(size_t)(row0 + m) * WVDIM + c * KC + w];
        }
        __syncthreads();

        #pragma unroll 2
        for (int w = 0; w < KC; w++) {
            float wd = Ws[tid * KCP + w];
            #pragma unroll
            for (int m = 0; m < TMA_; m++)
                acc[m] = fmaf(wvs[m * KC + w], wd, acc[m]);
        }
    }

    float bd = b[tid];
    #pragma unroll
    for (int m = 0; m < TMA_; m++) {
        int row = row0 + m;
        float al = alpha[row];
        float s = al * (acc[m] + bd) + (1.f - al) * x[(size_t)row * DDIM + tid];
        sem_out[(size_t)row * DDIM + tid] = s;
    }
}

// ---------------------------------------------------------------------------
// Kernel B: bf16 hi/lo split of sem and x into g_semB / g_xB
// ---------------------------------------------------------------------------
__global__ __launch_bounds__(256) void convert_kernel(
    const float* __restrict__ sem, const float* __restrict__ x)
{
    int idx = blockIdx.x * blockDim.x + threadIdx.x;
    if (idx >= NROWS * DDIM) return;
    int row = idx >> 7;
    int d   = idx & 127;

    float sv = sem[idx];
    __nv_bfloat16 sh = __float2bfloat16(sv);
    __nv_bfloat16 sl = __float2bfloat16(sv - __bfloat162float(sh));
    g_semB[(size_t)row * 256 + d]       = sh;
    g_semB[(size_t)row * 256 + 128 + d] = sl;

    float xv = x[idx];
    __nv_bfloat16 xh = __float2bfloat16(xv);
    __nv_bfloat16 xl = __float2bfloat16(xv - __bfloat162float(xh));
    g_xB[(size_t)row * 256 + d]       = xh;
    g_xB[(size_t)row * 256 + 128 + d] = xl;
}

// ---------------------------------------------------------------------------
// Kernel C: per-row squared norms + init mining accumulators
// ---------------------------------------------------------------------------
__global__ __launch_bounds__(256) void norms_init_kernel(
    const float* __restrict__ sem, const float* __restrict__ x)
{
    int gwarp = (blockIdx.x * blockDim.x + threadIdx.x) >> 5;
    int lane  = threadIdx.x & 31;
    if (gwarp >= NROWS) return;

    const float4* s4 = reinterpret_cast<const float4*>(sem) + (size_t)gwarp * 32;
    const float4* x4 = reinterpret_cast<const float4*>(x)   + (size_t)gwarp * 32;
    float4 sv = s4[lane];
    float4 xv = x4[lane];
    float ss = sv.x*sv.x + sv.y*sv.y + sv.z*sv.z + sv.w*sv.w;
    float xs = xv.x*xv.x + xv.y*xv.y + xv.z*xv.z + xv.w*xv.w;
    #pragma unroll
    for (int o = 16; o; o >>= 1) {
        ss += __shfl_xor_sync(0xFFFFFFFFu, ss, o);
        xs += __shfl_xor_sync(0xFFFFFFFFu, xs, o);
    }
    if (lane == 0) {
        g_ssq[gwarp] = ss;
        g_xsq[gwarp] = xs;
        g_fp_bits[gwarp] = 0;
        g_cn_bits[gwarp] = 0x7F7FFFFF;
    }
}

// ---------------------------------------------------------------------------
// Kernel D: warp-MMA distance tile + batch-hard mining.
// 128x128 tile, 256 threads (8 warps: 4 in m x 2 in n); each warp 32x64.
// 3 bf16 MMA groups (hi*hi, hi*lo, lo*hi), fp32 accumulation in registers.
//
// Smem tile layout: row r (0..127) x chunk c (0..31, 16B each; c<16 = hi half,
// c>=16 = lo half).  Swizzle: chunk' = c ^ (r & 7)  -> conflict-free for the
// staging stores (one warp = one row, 32 distinct chunks) and all ldmatrix
// phases (8 rows hit 8 distinct 16B chunks).
// ---------------------------------------------------------------------------
#define TILE_BYTES 65536
#define DIST_DSMEM (2 * TILE_BYTES)

__global__ __launch_bounds__(256, 1) void dist_mine_mma(const int* __restrict__ label)
{
    extern __shared__ char dyn[];
    char* As = dyn;                // sem tile [hi|lo]
    char* Bs = dyn + TILE_BYTES;   // x   tile [hi|lo]
    __shared__ int   lblN[128];
    __shared__ float xsqN[128];

    const int tid  = threadIdx.x;
    const int wid  = tid >> 5;
    const int lane = tid & 31;
    const int m0   = blockIdx.y * 128;
    const int n0   = blockIdx.x * 128;

    // ---- stage tiles (global row-major uint4 -> swizzled smem) ----
    const uint4* gA = reinterpret_cast<const uint4*>(g_semB) + (size_t)m0 * 32;
    const uint4* gB = reinterpret_cast<const uint4*>(g_xB)   + (size_t)n0 * 32;
    #pragma unroll
    for (int it = 0; it < 16; it++) {
        int idx = it * 256 + tid;      // 0..4095
        int r = idx >> 5, c = idx & 31;
        uint32_t off = (uint32_t)(r * 512 + ((c ^ (r & 7)) << 4));
        *reinterpret_cast<uint4*>(As + off) = gA[(size_t)r * 32 + c];
        *reinterpret_cast<uint4*>(Bs + off) = gB[(size_t)r * 32 + c];
    }
    if (tid < 128) {
        lblN[tid] = label[n0 + tid];
        xsqN[tid] = g_xsq[n0 + tid];
    }
    __syncthreads();

    const uint32_t AsU = smem_u32(As);
    const uint32_t BsU = smem_u32(Bs);

    const int wm = wid & 3;        // 0..3 -> 32-row slab
    const int wn = wid >> 2;       // 0..1 -> 64-col slab
    const int m_base = wm * 32;
    const int n_base = wn * 64;

    // Per-thread ldmatrix row addresses (byte offset = row*512), swizzle key
    uint32_t a_off[2], b_off[4];
    uint32_t a_sw[2], b_sw[4];
    #pragma unroll
    for (int mt = 0; mt < 2; mt++) {
        int r = m_base + mt * 16 + (lane & 15);
        a_off[mt] = AsU + r * 512;
        a_sw[mt]  = (uint32_t)(r & 7);
    }
    #pragma unroll
    for (int p = 0; p < 4; p++) {
        int r = n_base + p * 16 + ((lane >> 4) << 3) + (lane & 7);
        b_off[p] = BsU + r * 512;
        b_sw[p]  = (uint32_t)(r & 7);
    }
    const uint32_t a_chunk_add = (uint32_t)(lane >> 4);        // 0/1
    const uint32_t b_chunk_add = (uint32_t)((lane >> 3) & 1);  // 0/1

    float c[2][8][4];
    #pragma unroll
    for (int mt = 0; mt < 2; mt++)
        #pragma unroll
        for (int nt = 0; nt < 8; nt++)
            #pragma unroll
            for (int e = 0; e < 4; e++) c[mt][nt][e] = 0.f;

    #pragma unroll
    for (int s = 0; s < 8; s++) {
        uint32_t a[2][2][4];   // [half][mt][4]
        uint32_t bfr[2][4][4]; // [half][pair][4]  (pair p covers nt 2p, 2p+1)
        #pragma unroll
        for (int h = 0; h < 2; h++) {
            uint32_t chA = (uint32_t)(h * 16 + s * 2) + a_chunk_add;
            #pragma unroll
            for (int mt = 0; mt < 2; mt++)
                ldsm_x4(a[h][mt], a_off[mt] + ((chA ^ a_sw[mt]) << 4));
            uint32_t chB = (uint32_t)(h * 16 + s * 2) + b_chunk_add;
            #pragma unroll
            for (int p = 0; p < 4; p++)
                ldsm_x4(bfr[h][p], b_off[p] + ((chB ^ b_sw[p]) << 4));
        }
        #pragma unroll
        for (int mt = 0; mt < 2; mt++) {
            #pragma unroll
            for (int nt = 0; nt < 8; nt++) {
                const uint32_t* bh = &bfr[0][nt >> 1][(nt & 1) * 2];
                const uint32_t* bl = &bfr[1][nt >> 1][(nt & 1) * 2];
                mma16816(c[mt][nt], a[0][mt], bh);   // hi*hi
                mma16816(c[mt][nt], a[0][mt], bl);   // hi*lo
                mma16816(c[mt][nt], a[1][mt], bh);   // lo*hi
            }
        }
    }

    // ---- epilogue: distances + batch-hard mining, all in registers ----
    // c-frag: regs {0,1} -> row (t/4), cols n + (t%4)*2 + {0,1};
    //         regs {2,3} -> row (t/4)+8, same cols.
    const int q  = lane >> 2;   // 0..7
    const int qt = lane & 3;    // 0..3

    #pragma unroll
    for (int mt = 0; mt < 2; mt++) {
        #pragma unroll
        for (int hr = 0; hr < 2; hr++) {
            const int gi  = m0 + m_base + mt * 16 + hr * 8 + q;
            const float ssqm = g_ssq[gi];
            const int   lm   = label[gi];
            float fpv = 0.f;
            float cnv = 3.4e38f;
            #pragma unroll
            for (int nt = 0; nt < 8; nt++) {
                #pragma unroll
                for (int w = 0; w < 2; w++) {
                    int cl  = n_base + nt * 8 + qt * 2 + w;   // local col
                    float dot  = c[mt][nt][hr * 2 + w];
                    float sq   = ssqm + xsqN[cl] - 2.f * dot;
                    float dist = sqrtf(fmaxf(sq, 0.f) + DEPS);
                    bool same  = (lm == lblN[cl]);
                    fpv = fmaxf(fpv, (same && (gi != n0 + cl)) ? dist : 0.f);
                    cnv = fminf(cnv, same ? dist + BIGF : dist);
                }
            }
            // reduce across the 4 lanes of this row's quad
            #pragma unroll
            for (int o = 1; o <= 2; o <<= 1) {
                fpv = fmaxf(fpv, __shfl_xor_sync(0xFFFFFFFFu, fpv, o));
                cnv = fminf(cnv, __shfl_xor_sync(0xFFFFFFFFu, cnv, o));
            }
            if (qt == 0) {
                atomicMax(&g_fp_bits[gi], __float_as_int(fpv));
                atomicMin(&g_cn_bits[gi], __float_as_int(cnv));
            }
        }
    }
}

// ---------------------------------------------------------------------------
// Kernel E: diff = softplus(furthest_positive - closest_negative)
// ---------------------------------------------------------------------------
__global__ __launch_bounds__(256) void finalize_kernel(float* __restrict__ diff_out)
{
    int i = blockIdx.x * blockDim.x + threadIdx.x;
    if (i >= NROWS) return;
    float fp = __int_as_float(g_fp_bits[i]);
    float cn = __int_as_float(g_cn_bits[i]);
    float z = fp - cn;
    diff_out[i] = fmaxf(z, 0.f) + log1pf(expf(-fabsf(z)));
}

// ---------------------------------------------------------------------------
// Launch
// Inputs: x[N,128] f32, wv[N,300] f32, label[N] i32, alpha[N,1] f32,
//         W[128,300] f32, b[128] f32
// Output: diff[N] then sem[N,128] (float32, concatenated)
// ---------------------------------------------------------------------------
extern "C" void kernel_launch(void* const* d_in, const int* in_sizes, int n_in,
                              void* d_out, int out_size)
{
    const float* x     = (const float*)d_in[0];
    const float* wv    = (const float*)d_in[1];
    const int*   label = (const int*)  d_in[2];
    const float* alpha = (const float*)d_in[3];
    const float* W     = (const float*)d_in[4];
    const float* b     = (const float*)d_in[5];

    float* out  = (float*)d_out;
    float* diff = out;            // [N]
    float* sem  = out + NROWS;    // [N, 128]

    static bool attr_set = false;
    if (!attr_set) {
        cudaFuncSetAttribute(dist_mine_mma,
                             cudaFuncAttributeMaxDynamicSharedMemorySize, DIST_DSMEM);
        attr_set = true;
    }

    fc_mix_kernel<<<NROWS / TMA_, 128>>>(wv, W, b, alpha, x, sem);
    convert_kernel<<<(NROWS * DDIM) / 256, 256>>>(sem, x);
    norms_init_kernel<<<(NROWS * 32) / 256, 256>>>(sem, x);
    dist_mine_mma<<<dim3(NROWS / 128, NROWS / 128), 256, DIST_DSMEM>>>(label);
    finalize_kernel<<<NROWS / 256, 256>>>(diff);
}

// round 5
// speedup vs baseline: 1.8750x; 1.1329x over previous
#include <cuda_runtime.h>
#include <cuda_bf16.h>
#include <math.h>
#include <stdint.h>

// Problem constants
#define NROWS 8192
#define DDIM  128
#define WVDIM 300
#define BIGF  1e8f
#define DEPS  1.28e-14f   // D * 1e-16

// ---------------------------------------------------------------------------
// Scratch (__device__ globals; no allocation allowed)
// ---------------------------------------------------------------------------
__device__ float g_ssq[NROWS];
__device__ float g_xsq[NROWS];
__device__ int   g_fp_bits[NROWS];   // furthest positive, float bits (>= 0)
__device__ int   g_cn_bits[NROWS];   // closest negative, float bits (> 0)
// bf16 hi/lo split, row-major: [row][0:128]=hi, [row][128:256]=lo  (512 B/row)
__device__ __nv_bfloat16 g_semB[NROWS * 256];
__device__ __nv_bfloat16 g_xB[NROWS * 256];

// ---------------------------------------------------------------------------
// Warp-MMA helpers (sm_80+). NOT volatile: lets ptxas pipeline LDSM across
// K-steps; smem ordering is anchored by __syncthreads().
// ---------------------------------------------------------------------------
__device__ __forceinline__ uint32_t smem_u32(const void* p) {
    uint32_t a;
    asm("{ .reg .u64 t; cvta.to.shared.u64 t, %1; cvt.u32.u64 %0, t; }" : "=r"(a) : "l"(p));
    return a;
}
__device__ __forceinline__ void ldsm_x4(uint32_t* r, uint32_t addr) {
    asm("ldmatrix.sync.aligned.m8n8.x4.shared.b16 {%0,%1,%2,%3}, [%4];"
        : "=r"(r[0]), "=r"(r[1]), "=r"(r[2]), "=r"(r[3]) : "r"(addr));
}
__device__ __forceinline__ void mma16816(float* d, const uint32_t* a, const uint32_t* b) {
    asm("mma.sync.aligned.m16n8k16.row.col.f32.bf16.bf16.f32 "
        "{%0,%1,%2,%3}, {%4,%5,%6,%7}, {%8,%9}, {%0,%1,%2,%3};"
        : "+f"(d[0]), "+f"(d[1]), "+f"(d[2]), "+f"(d[3])
        : "r"(a[0]), "r"(a[1]), "r"(a[2]), "r"(a[3]), "r"(b[0]), "r"(b[1]));
}

// ---------------------------------------------------------------------------
// Kernel A: sem = alpha * (wv @ W^T + b) + (1-alpha) * x
// ---------------------------------------------------------------------------
#define KC 50
#define KCP 51
#define TMA_ 32

__global__ __launch_bounds__(128) void fc_mix_kernel(
    const float* __restrict__ wv, const float* __restrict__ W,
    const float* __restrict__ b, const float* __restrict__ alpha,
    const float* __restrict__ x, float* __restrict__ sem_out)
{
    __shared__ float Ws[DDIM * KCP];
    __shared__ float wvs[TMA_ * KC];

    const int tid  = threadIdx.x;
    const int row0 = blockIdx.x * TMA_;

    float acc[TMA_];
    #pragma unroll
    for (int m = 0; m < TMA_; m++) acc[m] = 0.f;

    for (int c = 0; c < WVDIM / KC; c++) {
        __syncthreads();
        for (int l = tid; l < DDIM * KC; l += 128) {
            int d = l / KC, w = l - d * KC;
            Ws[d * KCP + w] = W[d * WVDIM + c * KC + w];
        }
        for (int l = tid; l < TMA_ * KC; l += 128) {
            int m = l / KC, w = l - m * KC;
            wvs[m * KC + w] = wv[(size_t)(row0 + m) * WVDIM + c * KC + w];
        }
        __syncthreads();

        #pragma unroll 2
        for (int w = 0; w < KC; w++) {
            float wd = Ws[tid * KCP + w];
            #pragma unroll
            for (int m = 0; m < TMA_; m++)
                acc[m] = fmaf(wvs[m * KC + w], wd, acc[m]);
        }
    }

    float bd = b[tid];
    #pragma unroll
    for (int m = 0; m < TMA_; m++) {
        int row = row0 + m;
        float al = alpha[row];
        float s = al * (acc[m] + bd) + (1.f - al) * x[(size_t)row * DDIM + tid];
        sem_out[(size_t)row * DDIM + tid] = s;
    }
}

// ---------------------------------------------------------------------------
// Kernel B (fused): hi/lo bf16 split + row norms + mining-accumulator init.
// One warp per row.
// ---------------------------------------------------------------------------
__global__ __launch_bounds__(256) void prep_kernel(
    const float* __restrict__ sem, const float* __restrict__ x)
{
    int row  = (blockIdx.x * blockDim.x + threadIdx.x) >> 5;
    int lane = threadIdx.x & 31;
    if (row >= NROWS) return;

    float4 sv = reinterpret_cast<const float4*>(sem)[(size_t)row * 32 + lane];
    float4 xv = reinterpret_cast<const float4*>(x)  [(size_t)row * 32 + lane];

    __nv_bfloat16 sh0 = __float2bfloat16(sv.x), sh1 = __float2bfloat16(sv.y);
    __nv_bfloat16 sh2 = __float2bfloat16(sv.z), sh3 = __float2bfloat16(sv.w);
    __nv_bfloat16 sl0 = __float2bfloat16(sv.x - __bfloat162float(sh0));
    __nv_bfloat16 sl1 = __float2bfloat16(sv.y - __bfloat162float(sh1));
    __nv_bfloat16 sl2 = __float2bfloat16(sv.z - __bfloat162float(sh2));
    __nv_bfloat16 sl3 = __float2bfloat16(sv.w - __bfloat162float(sh3));
    __nv_bfloat16 xh0 = __float2bfloat16(xv.x), xh1 = __float2bfloat16(xv.y);
    __nv_bfloat16 xh2 = __float2bfloat16(xv.z), xh3 = __float2bfloat16(xv.w);
    __nv_bfloat16 xl0 = __float2bfloat16(xv.x - __bfloat162float(xh0));
    __nv_bfloat16 xl1 = __float2bfloat16(xv.y - __bfloat162float(xh1));
    __nv_bfloat16 xl2 = __float2bfloat16(xv.z - __bfloat162float(xh2));
    __nv_bfloat16 xl3 = __float2bfloat16(xv.w - __bfloat162float(xh3));

    __nv_bfloat162* semB2 = reinterpret_cast<__nv_bfloat162*>(g_semB);
    __nv_bfloat162* xB2   = reinterpret_cast<__nv_bfloat162*>(g_xB);
    size_t hiIdx = (size_t)row * 128 + 2 * lane;        // bf162 units
    size_t loIdx = hiIdx + 64;
    semB2[hiIdx]     = __nv_bfloat162(sh0, sh1);
    semB2[hiIdx + 1] = __nv_bfloat162(sh2, sh3);
    semB2[loIdx]     = __nv_bfloat162(sl0, sl1);
    semB2[loIdx + 1] = __nv_bfloat162(sl2, sl3);
    xB2[hiIdx]     = __nv_bfloat162(xh0, xh1);
    xB2[hiIdx + 1] = __nv_bfloat162(xh2, xh3);
    xB2[loIdx]     = __nv_bfloat162(xl0, xl1);
    xB2[loIdx + 1] = __nv_bfloat162(xl2, xl3);

    float ss = sv.x*sv.x + sv.y*sv.y + sv.z*sv.z + sv.w*sv.w;
    float xs = xv.x*xv.x + xv.y*xv.y + xv.z*xv.z + xv.w*xv.w;
    #pragma unroll
    for (int o = 16; o; o >>= 1) {
        ss += __shfl_xor_sync(0xFFFFFFFFu, ss, o);
        xs += __shfl_xor_sync(0xFFFFFFFFu, xs, o);
    }
    if (lane == 0) {
        g_ssq[row] = ss;
        g_xsq[row] = xs;
        g_fp_bits[row] = 0;
        g_cn_bits[row] = 0x7F7FFFFF;
    }
}

// ---------------------------------------------------------------------------
// Kernel C: warp-MMA distance tile + batch-hard mining.
// 128x128 tile, 512 threads (16 warps: 4m x 4n); each warp 32x32.
// 3 bf16 MMA groups (hi*hi, hi*lo, lo*hi), fp32 accumulation in registers.
// Smem tile: row r x 16B-chunk c (0..31; c<16 hi, c>=16 lo), chunk ^= r&7.
// ---------------------------------------------------------------------------
#define TILE_BYTES 65536
#define DIST_DSMEM (2 * TILE_BYTES)

__global__ __launch_bounds__(512, 1) void dist_mine_mma(const int* __restrict__ label)
{
    extern __shared__ char dyn[];
    char* As = dyn;                // sem tile [hi|lo]
    char* Bs = dyn + TILE_BYTES;   // x   tile [hi|lo]
    __shared__ int   lblN[128];
    __shared__ float xsqN[128];

    const int tid  = threadIdx.x;
    const int wid  = tid >> 5;
    const int lane = tid & 31;
    const int m0   = blockIdx.y * 128;
    const int n0   = blockIdx.x * 128;

    // ---- stage tiles (global row-major uint4 -> swizzled smem) ----
    const uint4* gA = reinterpret_cast<const uint4*>(g_semB) + (size_t)m0 * 32;
    const uint4* gB = reinterpret_cast<const uint4*>(g_xB)   + (size_t)n0 * 32;
    #pragma unroll
    for (int it = 0; it < 8; it++) {
        int idx = it * 512 + tid;      // 0..4095
        int r = idx >> 5, c = idx & 31;
        uint32_t off = (uint32_t)(r * 512 + ((c ^ (r & 7)) << 4));
        *reinterpret_cast<uint4*>(As + off) = gA[(size_t)r * 32 + c];
        *reinterpret_cast<uint4*>(Bs + off) = gB[(size_t)r * 32 + c];
    }
    if (tid < 128) {
        lblN[tid] = label[n0 + tid];
        xsqN[tid] = g_xsq[n0 + tid];
    }
    __syncthreads();

    const uint32_t AsU = smem_u32(As);
    const uint32_t BsU = smem_u32(Bs);

    const int wm = wid & 3;        // 0..3 -> 32-row slab
    const int wn = wid >> 2;       // 0..3 -> 32-col slab
    const int m_base = wm * 32;
    const int n_base = wn * 32;

    // Per-thread ldmatrix row addresses (byte offset = row*512) + swizzle key
    uint32_t a_off[2], b_off[2];
    uint32_t a_sw[2], b_sw[2];
    #pragma unroll
    for (int mt = 0; mt < 2; mt++) {
        int r = m_base + mt * 16 + (lane & 15);
        a_off[mt] = AsU + r * 512;
        a_sw[mt]  = (uint32_t)(r & 7);
    }
    #pragma unroll
    for (int p = 0; p < 2; p++) {
        int r = n_base + p * 16 + ((lane >> 4) << 3) + (lane & 7);
        b_off[p] = BsU + r * 512;
        b_sw[p]  = (uint32_t)(r & 7);
    }
    const uint32_t a_chunk_add = (uint32_t)(lane >> 4);        // 0/1
    const uint32_t b_chunk_add = (uint32_t)((lane >> 3) & 1);  // 0/1

    float c[2][4][4];
    #pragma unroll
    for (int mt = 0; mt < 2; mt++)
        #pragma unroll
        for (int nt = 0; nt < 4; nt++)
            #pragma unroll
            for (int e = 0; e < 4; e++) c[mt][nt][e] = 0.f;

    #pragma unroll
    for (int s = 0; s < 8; s++) {
        uint32_t a[2][2][4];   // [half][mt][4]
        uint32_t bfr[2][2][4]; // [half][pair][4]  (pair p covers nt 2p, 2p+1)
        #pragma unroll
        for (int h = 0; h < 2; h++) {
            uint32_t chA = (uint32_t)(h * 16 + s * 2) + a_chunk_add;
            #pragma unroll
            for (int mt = 0; mt < 2; mt++)
                ldsm_x4(a[h][mt], a_off[mt] + ((chA ^ a_sw[mt]) << 4));
            uint32_t chB = (uint32_t)(h * 16 + s * 2) + b_chunk_add;
            #pragma unroll
            for (int p = 0; p < 2; p++)
                ldsm_x4(bfr[h][p], b_off[p] + ((chB ^ b_sw[p]) << 4));
        }
        #pragma unroll
        for (int mt = 0; mt < 2; mt++) {
            #pragma unroll
            for (int nt = 0; nt < 4; nt++) {
                const uint32_t* bh = &bfr[0][nt >> 1][(nt & 1) * 2];
                const uint32_t* bl = &bfr[1][nt >> 1][(nt & 1) * 2];
                mma16816(c[mt][nt], a[0][mt], bh);   // hi*hi
                mma16816(c[mt][nt], a[0][mt], bl);   // hi*lo
                mma16816(c[mt][nt], a[1][mt], bh);   // lo*hi
            }
        }
    }

    // ---- epilogue: distances + batch-hard mining, all in registers ----
    const int q  = lane >> 2;   // 0..7
    const int qt = lane & 3;    // 0..3

    #pragma unroll
    for (int mt = 0; mt < 2; mt++) {
        #pragma unroll
        for (int hr = 0; hr < 2; hr++) {
            const int gi  = m0 + m_base + mt * 16 + hr * 8 + q;
            const float ssqm = g_ssq[gi];
            const int   lm   = label[gi];
            float fpv = 0.f;
            float cnv = 3.4e38f;
            #pragma unroll
            for (int nt = 0; nt < 4; nt++) {
                #pragma unroll
                for (int w = 0; w < 2; w++) {
                    int cl  = n_base + nt * 8 + qt * 2 + w;   // local col
                    float dot  = c[mt][nt][hr * 2 + w];
                    float sq   = ssqm + xsqN[cl] - 2.f * dot;
                    float dist = sqrtf(fmaxf(sq, 0.f) + DEPS);
                    bool same  = (lm == lblN[cl]);
                    fpv = fmaxf(fpv, (same && (gi != n0 + cl)) ? dist : 0.f);
                    cnv = fminf(cnv, same ? dist + BIGF : dist);
                }
            }
            #pragma unroll
            for (int o = 1; o <= 2; o <<= 1) {
                fpv = fmaxf(fpv, __shfl_xor_sync(0xFFFFFFFFu, fpv, o));
                cnv = fminf(cnv, __shfl_xor_sync(0xFFFFFFFFu, cnv, o));
            }
            if (qt == 0) {
                atomicMax(&g_fp_bits[gi], __float_as_int(fpv));
                atomicMin(&g_cn_bits[gi], __float_as_int(cnv));
            }
        }
    }
}

// ---------------------------------------------------------------------------
// Kernel D: diff = softplus(furthest_positive - closest_negative)
// ---------------------------------------------------------------------------
__global__ __launch_bounds__(256) void finalize_kernel(float* __restrict__ diff_out)
{
    int i = blockIdx.x * blockDim.x + threadIdx.x;
    if (i >= NROWS) return;
    float fp = __int_as_float(g_fp_bits[i]);
    float cn = __int_as_float(g_cn_bits[i]);
    float z = fp - cn;
    diff_out[i] = fmaxf(z, 0.f) + log1pf(expf(-fabsf(z)));
}

// ---------------------------------------------------------------------------
// Launch
// Inputs: x[N,128] f32, wv[N,300] f32, label[N] i32, alpha[N,1] f32,
//         W[128,300] f32, b[128] f32
// Output: diff[N] then sem[N,128] (float32, concatenated)
// ---------------------------------------------------------------------------
extern "C" void kernel_launch(void* const* d_in, const int* in_sizes, int n_in,
                              void* d_out, int out_size)
{
    const float* x     = (const float*)d_in[0];
    const float* wv    = (const float*)d_in[1];
    const int*   label = (const int*)  d_in[2];
    const float* alpha = (const float*)d_in[3];
    const float* W     = (const float*)d_in[4];
    const float* b     = (const float*)d_in[5];

    float* out  = (float*)d_out;
    float* diff = out;            // [N]
    float* sem  = out + NROWS;    // [N, 128]

    static bool attr_set = false;
    if (!attr_set) {
        cudaFuncSetAttribute(dist_mine_mma,
                             cudaFuncAttributeMaxDynamicSharedMemorySize, DIST_DSMEM);
        attr_set = true;
    }

    fc_mix_kernel<<<NROWS / TMA_, 128>>>(wv, W, b, alpha, x, sem);
    prep_kernel<<<(NROWS * 32) / 256, 256>>>(sem, x);
    dist_mine_mma<<<dim3(NROWS / 128, NROWS / 128), 512, DIST_DSMEM>>>(label);
    finalize_kernel<<<NROWS / 256, 256>>>(diff);
}

// round 6
// speedup vs baseline: 2.3686x; 1.2633x over previous
#include <cuda_runtime.h>
#include <cuda_bf16.h>
#include <math.h>
#include <stdint.h>

// Problem constants
#define NROWS 8192
#define DDIM  128
#define WVDIM 300
#define BIGF  1e8f
#define DEPS  1.28e-14f   // D * 1e-16
#define NEGINF -3.4e38f
#define POSINF  3.4e38f

// ---------------------------------------------------------------------------
// Scratch (__device__ globals; no allocation allowed)
// ---------------------------------------------------------------------------
__device__ float g_ssq[NROWS];    // |sem_i|^2 (exact fp32)
__device__ float g_xsq[NROWS];    // |x_j|^2   (exact fp32)
// bf16 hi/lo splits, row-major [row][0:128]=hi, [row][128:256]=lo (512 B/row)
// g_semB holds the split of (-2 * sem)  -> MMA directly produces -2*sem.x
__device__ __nv_bfloat16 g_semB[NROWS * 256];
__device__ __nv_bfloat16 g_xB[NROWS * 256];

// ---------------------------------------------------------------------------
// PTX helpers
// ---------------------------------------------------------------------------
__device__ __forceinline__ uint32_t smem_u32(const void* p) {
    uint32_t a;
    asm("{ .reg .u64 t; cvta.to.shared.u64 t, %1; cvt.u32.u64 %0, t; }" : "=r"(a) : "l"(p));
    return a;
}
// "memory" clobber (ordered vs cp.async/barriers) but not volatile (schedulable)
__device__ __forceinline__ void ldsm_x4(uint32_t* r, uint32_t addr) {
    asm("ldmatrix.sync.aligned.m8n8.x4.shared.b16 {%0,%1,%2,%3}, [%4];"
        : "=r"(r[0]), "=r"(r[1]), "=r"(r[2]), "=r"(r[3]) : "r"(addr) : "memory");
}
__device__ __forceinline__ void mma16816(float* d, const uint32_t* a, const uint32_t* b) {
    asm("mma.sync.aligned.m16n8k16.row.col.f32.bf16.bf16.f32 "
        "{%0,%1,%2,%3}, {%4,%5,%6,%7}, {%8,%9}, {%0,%1,%2,%3};"
        : "+f"(d[0]), "+f"(d[1]), "+f"(d[2]), "+f"(d[3])
        : "r"(a[0]), "r"(a[1]), "r"(a[2]), "r"(a[3]), "r"(b[0]), "r"(b[1]));
}
__device__ __forceinline__ void cp16(uint32_t dst, const void* src) {
    asm volatile("cp.async.cg.shared.global [%0], [%1], 16;" :: "r"(dst), "l"(src) : "memory");
}
__device__ __forceinline__ void cp4(uint32_t dst, const void* src) {
    asm volatile("cp.async.ca.shared.global [%0], [%1], 4;" :: "r"(dst), "l"(src) : "memory");
}
__device__ __forceinline__ void cp_commit() {
    asm volatile("cp.async.commit_group;" ::: "memory");
}
__device__ __forceinline__ void cp_wait0() {
    asm volatile("cp.async.wait_group 0;" ::: "memory");
}
__device__ __forceinline__ void cp_wait1() {
    asm volatile("cp.async.wait_group 1;" ::: "memory");
}

// ---------------------------------------------------------------------------
// Kernel A: sem = alpha * (wv @ W^T + b) + (1-alpha) * x
// ---------------------------------------------------------------------------
#define KC 50
#define KCP 51
#define TMA_ 32

__global__ __launch_bounds__(128) void fc_mix_kernel(
    const float* __restrict__ wv, const float* __restrict__ W,
    const float* __restrict__ b, const float* __restrict__ alpha,
    const float* __restrict__ x, float* __restrict__ sem_out)
{
    __shared__ float Ws[DDIM * KCP];
    __shared__ float wvs[TMA_ * KC];

    const int tid  = threadIdx.x;
    const int row0 = blockIdx.x * TMA_;

    float acc[TMA_];
    #pragma unroll
    for (int m = 0; m < TMA_; m++) acc[m] = 0.f;

    for (int c = 0; c < WVDIM / KC; c++) {
        __syncthreads();
        for (int l = tid; l < DDIM * KC; l += 128) {
            int d = l / KC, w = l - d * KC;
            Ws[d * KCP + w] = W[d * WVDIM + c * KC + w];
        }
        for (int l = tid; l < TMA_ * KC; l += 128) {
            int m = l / KC, w = l - m * KC;
            wvs[m * KC + w] = wv[(size_t)(row0 + m) * WVDIM + c * KC + w];
        }
        __syncthreads();

        #pragma unroll 2
        for (int w = 0; w < KC; w++) {
            float wd = Ws[tid * KCP + w];
            #pragma unroll
            for (int m = 0; m < TMA_; m++)
                acc[m] = fmaf(wvs[m * KC + w], wd, acc[m]);
        }
    }

    float bd = b[tid];
    #pragma unroll
    for (int m = 0; m < TMA_; m++) {
        int row = row0 + m;
        float al = alpha[row];
        float s = al * (acc[m] + bd) + (1.f - al) * x[(size_t)row * DDIM + tid];
        sem_out[(size_t)row * DDIM + tid] = s;
    }
}

// ---------------------------------------------------------------------------
// Kernel B (fused prep): hi/lo split of (-2*sem) and x, plus row norms.
// One warp per row.
// ---------------------------------------------------------------------------
__global__ __launch_bounds__(256) void prep_kernel(
    const float* __restrict__ sem, const float* __restrict__ x)
{
    int row  = (blockIdx.x * blockDim.x + threadIdx.x) >> 5;
    int lane = threadIdx.x & 31;
    if (row >= NROWS) return;

    float4 sv = reinterpret_cast<const float4*>(sem)[(size_t)row * 32 + lane];
    float4 xv = reinterpret_cast<const float4*>(x)  [(size_t)row * 32 + lane];

    // A side stores the split of (-2*sem)
    float a0 = -2.f * sv.x, a1 = -2.f * sv.y, a2 = -2.f * sv.z, a3 = -2.f * sv.w;
    __nv_bfloat16 sh0 = __float2bfloat16(a0), sh1 = __float2bfloat16(a1);
    __nv_bfloat16 sh2 = __float2bfloat16(a2), sh3 = __float2bfloat16(a3);
    __nv_bfloat16 sl0 = __float2bfloat16(a0 - __bfloat162float(sh0));
    __nv_bfloat16 sl1 = __float2bfloat16(a1 - __bfloat162float(sh1));
    __nv_bfloat16 sl2 = __float2bfloat16(a2 - __bfloat162float(sh2));
    __nv_bfloat16 sl3 = __float2bfloat16(a3 - __bfloat162float(sh3));
    __nv_bfloat16 xh0 = __float2bfloat16(xv.x), xh1 = __float2bfloat16(xv.y);
    __nv_bfloat16 xh2 = __float2bfloat16(xv.z), xh3 = __float2bfloat16(xv.w);
    __nv_bfloat16 xl0 = __float2bfloat16(xv.x - __bfloat162float(xh0));
    __nv_bfloat16 xl1 = __float2bfloat16(xv.y - __bfloat162float(xh1));
    __nv_bfloat16 xl2 = __float2bfloat16(xv.z - __bfloat162float(xh2));
    __nv_bfloat16 xl3 = __float2bfloat16(xv.w - __bfloat162float(xh3));

    __nv_bfloat162* semB2 = reinterpret_cast<__nv_bfloat162*>(g_semB);
    __nv_bfloat162* xB2   = reinterpret_cast<__nv_bfloat162*>(g_xB);
    size_t hiIdx = (size_t)row * 128 + 2 * lane;
    size_t loIdx = hiIdx + 64;
    semB2[hiIdx]     = __nv_bfloat162(sh0, sh1);
    semB2[hiIdx + 1] = __nv_bfloat162(sh2, sh3);
    semB2[loIdx]     = __nv_bfloat162(sl0, sl1);
    semB2[loIdx + 1] = __nv_bfloat162(sl2, sl3);
    xB2[hiIdx]     = __nv_bfloat162(xh0, xh1);
    xB2[hiIdx + 1] = __nv_bfloat162(xh2, xh3);
    xB2[loIdx]     = __nv_bfloat162(xl0, xl1);
    xB2[loIdx + 1] = __nv_bfloat162(xl2, xl3);

    float ss = sv.x*sv.x + sv.y*sv.y + sv.z*sv.z + sv.w*sv.w;
    float xs = xv.x*xv.x + xv.y*xv.y + xv.z*xv.z + xv.w*xv.w;
    #pragma unroll
    for (int o = 16; o; o >>= 1) {
        ss += __shfl_xor_sync(0xFFFFFFFFu, ss, o);
        xs += __shfl_xor_sync(0xFFFFFFFFu, xs, o);
    }
    if (lane == 0) {
        g_ssq[row] = ss;
        g_xsq[row] = xs;
    }
}

// ---------------------------------------------------------------------------
// Kernel C: persistent distance + batch-hard mining.
// 128 CTAs; CTA owns a 64-row m-strip, sweeps all 64 n-tiles (128 cols each).
// A-fragments for all K-steps preloaded into registers (smem A read once).
// B double-buffered via cp.async. Mining on u = xsq + (-2 sem.x), no sqrt in
// hot loop, no global atomics; softplus written directly.
//
// Smem layout (dynamic):
//   [0, 32768)          A tile:  64 rows x 512B, chunk^=(r&7) swizzle
//   [32768, 98304)      B stage0: 128 rows x 512B
//   [98304, 163840)     B stage1
//   then: lbl[2][128] int, xsq[2][128] float, agg fp/cn [4][64] floats
// ---------------------------------------------------------------------------
#define A_BYTES   32768
#define B_BYTES   65536
#define OFF_B     A_BYTES
#define OFF_LBL   (A_BYTES + 2 * B_BYTES)            // 163840
#define OFF_XSQ   (OFF_LBL + 2 * 128 * 4)            // +1024
#define OFF_AGG   (OFF_XSQ + 2 * 128 * 4)            // +1024
#define DIST_DSMEM (OFF_AGG + 2 * 4 * 64 * 4)        // +2048 = 167936

#define NSTEPS 64

__global__ __launch_bounds__(256) void dist_persist(
    const int* __restrict__ label, float* __restrict__ diff_out)
{
    extern __shared__ char dyn[];
    char*  As   = dyn;
    char*  Bs   = dyn + OFF_B;
    int*   lblS = reinterpret_cast<int*>(dyn + OFF_LBL);
    float* xsqS = reinterpret_cast<float*>(dyn + OFF_XSQ);
    float* aggF = reinterpret_cast<float*>(dyn + OFF_AGG);            // [4][64]
    float* aggC = reinterpret_cast<float*>(dyn + OFF_AGG + 4*64*4);   // [4][64]

    const int tid  = threadIdx.x;
    const int wid  = tid >> 5;
    const int lane = tid & 31;
    const int rowbase = blockIdx.x * 64;

    // ---- stage A strip (64 rows x 32 chunks), swizzled ----
    {
        const uint4* gA = reinterpret_cast<const uint4*>(g_semB) + (size_t)rowbase * 32;
        #pragma unroll
        for (int it = 0; it < 8; it++) {
            int idx = it * 256 + tid;         // 0..2047
            int r = idx >> 5, cch = idx & 31;
            uint32_t off = (uint32_t)(r * 512 + ((cch ^ (r & 7)) << 4));
            *reinterpret_cast<uint4*>(As + off) = gA[(size_t)r * 32 + cch];
        }
    }
    __syncthreads();

    const uint32_t AsU = smem_u32(As);
    const uint32_t BsU = smem_u32(Bs);

    const int wm = wid & 1;        // 2 m-slabs of 32
    const int wn = wid >> 1;       // 4 n-slabs of 32
    const int m_base = wm * 32;
    const int n_base = wn * 32;

    // ---- preload ALL A fragments into registers ----
    uint32_t aF[8][2][2][4];       // [kstep][half][mt][4]
    {
        const uint32_t a_chunk_add = (uint32_t)(lane >> 4);   // 0/1
        #pragma unroll
        for (int mt = 0; mt < 2; mt++) {
            int r = m_base + mt * 16 + (lane & 15);
            uint32_t base = AsU + r * 512;
            uint32_t sw   = (uint32_t)(r & 7);
            #pragma unroll
            for (int s = 0; s < 8; s++) {
                #pragma unroll
                for (int h = 0; h < 2; h++) {
                    uint32_t ch = (uint32_t)(h * 16 + s * 2) + a_chunk_add;
                    ldsm_x4(aF[s][h][mt], base + ((ch ^ sw) << 4));
                }
            }
        }
    }

    // B ldmatrix addressing (per stage; add buf*B_BYTES)
    uint32_t b_off[2], b_sw[2];
    #pragma unroll
    for (int p = 0; p < 2; p++) {
        int r = n_base + p * 16 + ((lane >> 4) << 3) + (lane & 7);
        b_off[p] = BsU + r * 512;
        b_sw[p]  = (uint32_t)(r & 7);
    }
    const uint32_t b_chunk_add = (uint32_t)((lane >> 3) & 1);

    // per-thread row info
    const int q  = lane >> 2;      // 0..7
    const int qt = lane & 3;       // 0..3
    int   row_gi[2][2];
    int   lmv[2][2];
    #pragma unroll
    for (int mt = 0; mt < 2; mt++)
        #pragma unroll
        for (int hr = 0; hr < 2; hr++) {
            row_gi[mt][hr] = rowbase + m_base + mt * 16 + hr * 8 + q;
            lmv[mt][hr]    = label[row_gi[mt][hr]];
        }

    float fpU[2][2], cnU[2][2];
    #pragma unroll
    for (int mt = 0; mt < 2; mt++)
        #pragma unroll
        for (int hr = 0; hr < 2; hr++) { fpU[mt][hr] = NEGINF; cnU[mt][hr] = POSINF; }

    // ---- B tile staging via cp.async ----
    auto stage_tile = [&](int t, int buf) {
        int n0 = t * 128;
        const char* gB = reinterpret_cast<const char*>(g_xB) + (size_t)n0 * 512;
        uint32_t bb = BsU + buf * B_BYTES;
        #pragma unroll
        for (int it = 0; it < 16; it++) {
            int idx = it * 256 + tid;        // 0..4095
            int r = idx >> 5, cch = idx & 31;
            uint32_t dst = bb + (uint32_t)(r * 512 + ((cch ^ (r & 7)) << 4));
            cp16(dst, gB + (size_t)r * 512 + cch * 16);
        }
        if (tid < 128) {
            cp4(smem_u32(lblS + buf * 128 + tid), label + n0 + tid);
        } else {
            int t2 = tid - 128;
            cp4(smem_u32(xsqS + buf * 128 + t2), g_xsq + n0 + t2);
        }
    };

    stage_tile(0, 0);
    cp_commit();

    for (int t = 0; t < NSTEPS; t++) {
        const int buf = t & 1;
        const int n0  = t * 128;
        if (t + 1 < NSTEPS) {
            stage_tile(t + 1, buf ^ 1);
            cp_commit();
            cp_wait1();
        } else {
            cp_wait0();
        }
        __syncthreads();

        // ---- GEMM for this tile ----
        float c[2][4][4];
        #pragma unroll
        for (int mt = 0; mt < 2; mt++)
            #pragma unroll
            for (int nt = 0; nt < 4; nt++)
                #pragma unroll
                for (int e = 0; e < 4; e++) c[mt][nt][e] = 0.f;

        const uint32_t bufAdd = (uint32_t)(buf * B_BYTES);
        #pragma unroll
        for (int s = 0; s < 8; s++) {
            uint32_t bfr[2][2][4];   // [half][pair][4]
            #pragma unroll
            for (int h = 0; h < 2; h++) {
                uint32_t chB = (uint32_t)(h * 16 + s * 2) + b_chunk_add;
                #pragma unroll
                for (int p = 0; p < 2; p++)
                    ldsm_x4(bfr[h][p], b_off[p] + bufAdd + ((chB ^ b_sw[p]) << 4));
            }
            #pragma unroll
            for (int mt = 0; mt < 2; mt++) {
                #pragma unroll
                for (int nt = 0; nt < 4; nt++) {
                    const uint32_t* bh = &bfr[0][nt >> 1][(nt & 1) * 2];
                    const uint32_t* bl = &bfr[1][nt >> 1][(nt & 1) * 2];
                    mma16816(c[mt][nt], aF[s][0][mt], bh);   // hi*hi
                    mma16816(c[mt][nt], aF[s][0][mt], bl);   // hi*lo
                    mma16816(c[mt][nt], aF[s][1][mt], bh);   // lo*hi
                }
            }
        }

        // ---- mining on u = xsq[col] + (-2 sem.x) ----
        const int*   lblT = lblS + buf * 128;
        const float* xsqT = xsqS + buf * 128;
        float xq[8]; int lb[8];
        #pragma unroll
        for (int k = 0; k < 8; k++) {
            int cl = n_base + (k >> 1) * 8 + qt * 2 + (k & 1);
            xq[k] = xsqT[cl];
            lb[k] = lblT[cl];
        }
        #pragma unroll
        for (int mt = 0; mt < 2; mt++) {
            #pragma unroll
            for (int hr = 0; hr < 2; hr++) {
                const int gi = row_gi[mt][hr];
                const int lm = lmv[mt][hr];
                float fb = fpU[mt][hr], cb = cnU[mt][hr];
                #pragma unroll
                for (int nt = 0; nt < 4; nt++) {
                    #pragma unroll
                    for (int w = 0; w < 2; w++) {
                        int k  = nt * 2 + w;
                        int cl = n_base + nt * 8 + qt * 2 + w;
                        float u = xq[k] + c[mt][nt][hr * 2 + w];
                        bool same = (lm == lb[k]);
                        bool self = ((n0 + cl) == gi);
                        fb = fmaxf(fb, (same && !self) ? u : NEGINF);
                        cb = fminf(cb, same ? POSINF : u);
                    }
                }
                fpU[mt][hr] = fb;
                cnU[mt][hr] = cb;
            }
        }
        __syncthreads();   // protect buf before next-next stage overwrites it
    }

    // ---- final reduction: qt lanes -> smem across wn warps -> softplus ----
    #pragma unroll
    for (int mt = 0; mt < 2; mt++) {
        #pragma unroll
        for (int hr = 0; hr < 2; hr++) {
            float fb = fpU[mt][hr], cb = cnU[mt][hr];
            #pragma unroll
            for (int o = 1; o <= 2; o <<= 1) {
                fb = fmaxf(fb, __shfl_xor_sync(0xFFFFFFFFu, fb, o));
                cb = fminf(cb, __shfl_xor_sync(0xFFFFFFFFu, cb, o));
            }
            if (qt == 0) {
                int r = m_base + mt * 16 + hr * 8 + q;   // 0..63
                aggF[wn * 64 + r] = fb;
                aggC[wn * 64 + r] = cb;
            }
        }
    }
    __syncthreads();

    if (tid < 64) {
        float fb = NEGINF, cb = POSINF;
        #pragma unroll
        for (int wnn = 0; wnn < 4; wnn++) {
            fb = fmaxf(fb, aggF[wnn * 64 + tid]);
            cb = fminf(cb, aggC[wnn * 64 + tid]);
        }
        float ssqm = g_ssq[rowbase + tid];
        float fp = (fb < -1e37f) ? 0.f : sqrtf(fmaxf(ssqm + fb, 0.f) + DEPS);
        float cn = sqrtf(fmaxf(ssqm + cb, 0.f) + DEPS);
        float z = fp - cn;
        diff_out[rowbase + tid] = fmaxf(z, 0.f) + log1pf(expf(-fabsf(z)));
    }
}

// ---------------------------------------------------------------------------
// Launch
// Inputs: x[N,128] f32, wv[N,300] f32, label[N] i32, alpha[N,1] f32,
//         W[128,300] f32, b[128] f32
// Output: diff[N] then sem[N,128] (float32, concatenated)
// ---------------------------------------------------------------------------
extern "C" void kernel_launch(void* const* d_in, const int* in_sizes, int n_in,
                              void* d_out, int out_size)
{
    const float* x     = (const float*)d_in[0];
    const float* wv    = (const float*)d_in[1];
    const int*   label = (const int*)  d_in[2];
    const float* alpha = (const float*)d_in[3];
    const float* W     = (const float*)d_in[4];
    const float* b     = (const float*)d_in[5];

    float* out  = (float*)d_out;
    float* diff = out;            // [N]
    float* sem  = out + NROWS;    // [N, 128]

    static bool attr_set = false;
    if (!attr_set) {
        cudaFuncSetAttribute(dist_persist,
                             cudaFuncAttributeMaxDynamicSharedMemorySize, DIST_DSMEM);
        attr_set = true;
    }

    fc_mix_kernel<<<NROWS / TMA_, 128>>>(wv, W, b, alpha, x, sem);
    prep_kernel<<<(NROWS * 32) / 256, 256>>>(sem, x);
    dist_persist<<<NROWS / 64, 256, DIST_DSMEM>>>(label, diff);
}

// round 7
// speedup vs baseline: 2.4364x; 1.0286x over previous
#include <cuda_runtime.h>
#include <cuda_bf16.h>
#include <math.h>
#include <stdint.h>

// Problem constants
#define NROWS 8192
#define DDIM  128
#define WVDIM 300
#define BIGF  1e8f
#define DEPS  1.28e-14f   // D * 1e-16
#define NEGINF -3.4e38f
#define POSINF  3.4e38f

// ---------------------------------------------------------------------------
// Scratch (__device__ globals; no allocation allowed)
// ---------------------------------------------------------------------------
__device__ float g_ssq[NROWS];    // |sem_i|^2 (exact fp32)
__device__ float g_xsq[NROWS];    // |x_j|^2   (exact fp32)
// bf16 hi/lo splits, row-major [row][0:128]=hi, [row][128:256]=lo (512 B/row)
// g_semB holds the split of (-2 * sem)  -> MMA directly produces -2*sem.x
__device__ __nv_bfloat16 g_semB[NROWS * 256];
__device__ __nv_bfloat16 g_xB[NROWS * 256];

// ---------------------------------------------------------------------------
// PTX helpers
// ---------------------------------------------------------------------------
__device__ __forceinline__ uint32_t smem_u32(const void* p) {
    uint32_t a;
    asm("{ .reg .u64 t; cvta.to.shared.u64 t, %1; cvt.u32.u64 %0, t; }" : "=r"(a) : "l"(p));
    return a;
}
__device__ __forceinline__ void ldsm_x4(uint32_t* r, uint32_t addr) {
    asm("ldmatrix.sync.aligned.m8n8.x4.shared.b16 {%0,%1,%2,%3}, [%4];"
        : "=r"(r[0]), "=r"(r[1]), "=r"(r[2]), "=r"(r[3]) : "r"(addr) : "memory");
}
__device__ __forceinline__ void mma16816(float* d, const uint32_t* a, const uint32_t* b) {
    asm("mma.sync.aligned.m16n8k16.row.col.f32.bf16.bf16.f32 "
        "{%0,%1,%2,%3}, {%4,%5,%6,%7}, {%8,%9}, {%0,%1,%2,%3};"
        : "+f"(d[0]), "+f"(d[1]), "+f"(d[2]), "+f"(d[3])
        : "r"(a[0]), "r"(a[1]), "r"(a[2]), "r"(a[3]), "r"(b[0]), "r"(b[1]));
}
__device__ __forceinline__ void cp16(uint32_t dst, const void* src) {
    asm volatile("cp.async.cg.shared.global [%0], [%1], 16;" :: "r"(dst), "l"(src) : "memory");
}
__device__ __forceinline__ void cp4(uint32_t dst, const void* src) {
    asm volatile("cp.async.ca.shared.global [%0], [%1], 4;" :: "r"(dst), "l"(src) : "memory");
}
__device__ __forceinline__ void cp_commit() {
    asm volatile("cp.async.commit_group;" ::: "memory");
}
__device__ __forceinline__ void cp_wait0() {
    asm volatile("cp.async.wait_group 0;" ::: "memory");
}
__device__ __forceinline__ void cp_wait1() {
    asm volatile("cp.async.wait_group 1;" ::: "memory");
}

// ---------------------------------------------------------------------------
// Kernel A (fused): sem = alpha*(wv@W^T + b) + (1-alpha)*x,  PLUS:
//   - sem written to output
//   - hi/lo bf16 split of (-2*sem) -> g_semB, of x -> g_xB
//   - row norms g_ssq, g_xsq
// Register-tiled GEMM: CTA = 64 rows x 128 cols, 256 threads (16 ty x 16 tx),
// thread tile 4m x 8d. K=300 in 6 chunks of 50, staged K-major in smem so the
// inner loop is 3x LDS.128 + 32 FMA.
// ---------------------------------------------------------------------------
#define FC_ROWS   64
#define FC_KC     50
#define WT_PITCH  132    // floats; mult of 4 (16B aligned rows), padded vs 128
#define WV_PITCH  68     // floats; mult of 4

__global__ __launch_bounds__(256) void fc_mix_fused(
    const float* __restrict__ wv, const float* __restrict__ W,
    const float* __restrict__ b, const float* __restrict__ alpha,
    const float* __restrict__ x, float* __restrict__ sem_out)
{
    __shared__ float Wt[FC_KC * WT_PITCH];    // [k][d]  26.4 KB
    __shared__ float wvt[FC_KC * WV_PITCH];   // [k][m]  13.6 KB

    const int tid  = threadIdx.x;
    const int tx   = tid & 15;     // d-group
    const int ty   = tid >> 4;     // m-group
    const int row0 = blockIdx.x * FC_ROWS;
    const int d0   = tx * 8;

    float acc[4][8];
    #pragma unroll
    for (int i = 0; i < 4; i++)
        #pragma unroll
        for (int j = 0; j < 8; j++) acc[i][j] = 0.f;

    for (int c = 0; c < WVDIM / FC_KC; c++) {
        __syncthreads();
        // stage W chunk transposed: Wt[k][d] = W[d][c*50+k]
        for (int l = tid; l < DDIM * FC_KC; l += 256) {
            int d = l / FC_KC, k = l - d * FC_KC;
            Wt[k * WT_PITCH + d] = W[d * WVDIM + c * FC_KC + k];
        }
        // stage wv chunk transposed: wvt[k][m] = wv[row0+m][c*50+k]
        for (int l = tid; l < FC_ROWS * FC_KC; l += 256) {
            int m = l / FC_KC, k = l - m * FC_KC;
            wvt[k * WV_PITCH + m] = wv[(size_t)(row0 + m) * WVDIM + c * FC_KC + k];
        }
        __syncthreads();

        #pragma unroll 2
        for (int k = 0; k < FC_KC; k++) {
            float4 wvv = *reinterpret_cast<const float4*>(&wvt[k * WV_PITCH + ty * 4]);
            float4 w0  = *reinterpret_cast<const float4*>(&Wt[k * WT_PITCH + d0]);
            float4 w1  = *reinterpret_cast<const float4*>(&Wt[k * WT_PITCH + d0 + 4]);
            float wm[4] = {wvv.x, wvv.y, wvv.z, wvv.w};
            float wd[8] = {w0.x, w0.y, w0.z, w0.w, w1.x, w1.y, w1.z, w1.w};
            #pragma unroll
            for (int i = 0; i < 4; i++)
                #pragma unroll
                for (int j = 0; j < 8; j++)
                    acc[i][j] = fmaf(wm[i], wd[j], acc[i][j]);
        }
    }

    // ---- fused epilogue: mix, splits, norms ----
    float bd[8];
    #pragma unroll
    for (int j = 0; j < 8; j++) bd[j] = b[d0 + j];

    #pragma unroll
    for (int i = 0; i < 4; i++) {
        const int row = row0 + ty * 4 + i;
        const float al = alpha[row];
        float4 xa = reinterpret_cast<const float4*>(x)[(size_t)row * 32 + tx * 2];
        float4 xb = reinterpret_cast<const float4*>(x)[(size_t)row * 32 + tx * 2 + 1];
        float xv[8] = {xa.x, xa.y, xa.z, xa.w, xb.x, xb.y, xb.z, xb.w};

        float sv[8];
        float pssq = 0.f, pxsq = 0.f;
        #pragma unroll
        for (int j = 0; j < 8; j++) {
            float s = al * (acc[i][j] + bd[j]) + (1.f - al) * xv[j];
            sv[j] = s;
            pssq = fmaf(s, s, pssq);
            pxsq = fmaf(xv[j], xv[j], pxsq);
        }

        // write sem (2x float4)
        float4 o0 = {sv[0], sv[1], sv[2], sv[3]};
        float4 o1 = {sv[4], sv[5], sv[6], sv[7]};
        reinterpret_cast<float4*>(sem_out)[(size_t)row * 32 + tx * 2]     = o0;
        reinterpret_cast<float4*>(sem_out)[(size_t)row * 32 + tx * 2 + 1] = o1;

        // hi/lo split of (-2*sem) and x, packed as 8 bf16 = 16B each
        __nv_bfloat162 sh[4], sl[4], xh[4], xl[4];
        #pragma unroll
        for (int j2 = 0; j2 < 4; j2++) {
            float a0 = -2.f * sv[2*j2], a1 = -2.f * sv[2*j2+1];
            __nv_bfloat16 h0 = __float2bfloat16(a0), h1 = __float2bfloat16(a1);
            sh[j2] = __nv_bfloat162(h0, h1);
            sl[j2] = __nv_bfloat162(__float2bfloat16(a0 - __bfloat162float(h0)),
                                    __float2bfloat16(a1 - __bfloat162float(h1)));
            float b0 = xv[2*j2], b1 = xv[2*j2+1];
            __nv_bfloat16 g0 = __float2bfloat16(b0), g1 = __float2bfloat16(b1);
            xh[j2] = __nv_bfloat162(g0, g1);
            xl[j2] = __nv_bfloat162(__float2bfloat16(b0 - __bfloat162float(g0)),
                                    __float2bfloat16(b1 - __bfloat162float(g1)));
        }
        uint4* semB4 = reinterpret_cast<uint4*>(g_semB + (size_t)row * 256);
        uint4* xB4   = reinterpret_cast<uint4*>(g_xB   + (size_t)row * 256);
        semB4[tx]      = *reinterpret_cast<uint4*>(sh);   // hi at [row][d0..d0+8)
        semB4[16 + tx] = *reinterpret_cast<uint4*>(sl);   // lo at [row][128+d0..)
        xB4[tx]        = *reinterpret_cast<uint4*>(xh);
        xB4[16 + tx]   = *reinterpret_cast<uint4*>(xl);

        // reduce norms across the 16 tx lanes (xor 1,2,4,8 stays in half-warp)
        #pragma unroll
        for (int o = 1; o <= 8; o <<= 1) {
            pssq += __shfl_xor_sync(0xFFFFFFFFu, pssq, o);
            pxsq += __shfl_xor_sync(0xFFFFFFFFu, pxsq, o);
        }
        if (tx == 0) {
            g_ssq[row] = pssq;
            g_xsq[row] = pxsq;
        }
    }
}

// ---------------------------------------------------------------------------
// Kernel B: persistent distance + batch-hard mining (unchanged from R6).
// 128 CTAs; CTA owns a 64-row m-strip, sweeps all 64 n-tiles (128 cols each).
// A-fragments preloaded into registers; B double-buffered via cp.async.
// Mining on u = xsq + (-2 sem.x); softplus written directly.
// ---------------------------------------------------------------------------
#define A_BYTES   32768
#define B_BYTES   65536
#define OFF_B     A_BYTES
#define OFF_LBL   (A_BYTES + 2 * B_BYTES)            // 163840
#define OFF_XSQ   (OFF_LBL + 2 * 128 * 4)            // +1024
#define OFF_AGG   (OFF_XSQ + 2 * 128 * 4)            // +1024
#define DIST_DSMEM (OFF_AGG + 2 * 4 * 64 * 4)        // = 167936

#define NSTEPS 64

__global__ __launch_bounds__(256) void dist_persist(
    const int* __restrict__ label, float* __restrict__ diff_out)
{
    extern __shared__ char dyn[];
    char*  As   = dyn;
    char*  Bs   = dyn + OFF_B;
    int*   lblS = reinterpret_cast<int*>(dyn + OFF_LBL);
    float* xsqS = reinterpret_cast<float*>(dyn + OFF_XSQ);
    float* aggF = reinterpret_cast<float*>(dyn + OFF_AGG);            // [4][64]
    float* aggC = reinterpret_cast<float*>(dyn + OFF_AGG + 4*64*4);   // [4][64]

    const int tid  = threadIdx.x;
    const int wid  = tid >> 5;
    const int lane = tid & 31;
    const int rowbase = blockIdx.x * 64;

    // ---- stage A strip (64 rows x 32 chunks), swizzled ----
    {
        const uint4* gA = reinterpret_cast<const uint4*>(g_semB) + (size_t)rowbase * 32;
        #pragma unroll
        for (int it = 0; it < 8; it++) {
            int idx = it * 256 + tid;         // 0..2047
            int r = idx >> 5, cch = idx & 31;
            uint32_t off = (uint32_t)(r * 512 + ((cch ^ (r & 7)) << 4));
            *reinterpret_cast<uint4*>(As + off) = gA[(size_t)r * 32 + cch];
        }
    }
    __syncthreads();

    const uint32_t AsU = smem_u32(As);
    const uint32_t BsU = smem_u32(Bs);

    const int wm = wid & 1;        // 2 m-slabs of 32
    const int wn = wid >> 1;       // 4 n-slabs of 32
    const int m_base = wm * 32;
    const int n_base = wn * 32;

    // ---- preload ALL A fragments into registers ----
    uint32_t aF[8][2][2][4];       // [kstep][half][mt][4]
    {
        const uint32_t a_chunk_add = (uint32_t)(lane >> 4);   // 0/1
        #pragma unroll
        for (int mt = 0; mt < 2; mt++) {
            int r = m_base + mt * 16 + (lane & 15);
            uint32_t base = AsU + r * 512;
            uint32_t sw   = (uint32_t)(r & 7);
            #pragma unroll
            for (int s = 0; s < 8; s++) {
                #pragma unroll
                for (int h = 0; h < 2; h++) {
                    uint32_t ch = (uint32_t)(h * 16 + s * 2) + a_chunk_add;
                    ldsm_x4(aF[s][h][mt], base + ((ch ^ sw) << 4));
                }
            }
        }
    }

    // B ldmatrix addressing (per stage; add buf*B_BYTES)
    uint32_t b_off[2], b_sw[2];
    #pragma unroll
    for (int p = 0; p < 2; p++) {
        int r = n_base + p * 16 + ((lane >> 4) << 3) + (lane & 7);
        b_off[p] = BsU + r * 512;
        b_sw[p]  = (uint32_t)(r & 7);
    }
    const uint32_t b_chunk_add = (uint32_t)((lane >> 3) & 1);

    // per-thread row info
    const int q  = lane >> 2;      // 0..7
    const int qt = lane & 3;       // 0..3
    int   row_gi[2][2];
    int   lmv[2][2];
    #pragma unroll
    for (int mt = 0; mt < 2; mt++)
        #pragma unroll
        for (int hr = 0; hr < 2; hr++) {
            row_gi[mt][hr] = rowbase + m_base + mt * 16 + hr * 8 + q;
            lmv[mt][hr]    = label[row_gi[mt][hr]];
        }

    float fpU[2][2], cnU[2][2];
    #pragma unroll
    for (int mt = 0; mt < 2; mt++)
        #pragma unroll
        for (int hr = 0; hr < 2; hr++) { fpU[mt][hr] = NEGINF; cnU[mt][hr] = POSINF; }

    // ---- B tile staging via cp.async ----
    auto stage_tile = [&](int t, int buf) {
        int n0 = t * 128;
        const char* gB = reinterpret_cast<const char*>(g_xB) + (size_t)n0 * 512;
        uint32_t bb = BsU + buf * B_BYTES;
        #pragma unroll
        for (int it = 0; it < 16; it++) {
            int idx = it * 256 + tid;        // 0..4095
            int r = idx >> 5, cch = idx & 31;
            uint32_t dst = bb + (uint32_t)(r * 512 + ((cch ^ (r & 7)) << 4));
            cp16(dst, gB + (size_t)r * 512 + cch * 16);
        }
        if (tid < 128) {
            cp4(smem_u32(lblS + buf * 128 + tid), label + n0 + tid);
        } else {
            int t2 = tid - 128;
            cp4(smem_u32(xsqS + buf * 128 + t2), g_xsq + n0 + t2);
        }
    };

    stage_tile(0, 0);
    cp_commit();

    for (int t = 0; t < NSTEPS; t++) {
        const int buf = t & 1;
        const int n0  = t * 128;
        if (t + 1 < NSTEPS) {
            stage_tile(t + 1, buf ^ 1);
            cp_commit();
            cp_wait1();
        } else {
            cp_wait0();
        }
        __syncthreads();

        // ---- GEMM for this tile ----
        float c[2][4][4];
        #pragma unroll
        for (int mt = 0; mt < 2; mt++)
            #pragma unroll
            for (int nt = 0; nt < 4; nt++)
                #pragma unroll
                for (int e = 0; e < 4; e++) c[mt][nt][e] = 0.f;

        const uint32_t bufAdd = (uint32_t)(buf * B_BYTES);
        #pragma unroll
        for (int s = 0; s < 8; s++) {
            uint32_t bfr[2][2][4];   // [half][pair][4]
            #pragma unroll
            for (int h = 0; h < 2; h++) {
                uint32_t chB = (uint32_t)(h * 16 + s * 2) + b_chunk_add;
                #pragma unroll
                for (int p = 0; p < 2; p++)
                    ldsm_x4(bfr[h][p], b_off[p] + bufAdd + ((chB ^ b_sw[p]) << 4));
            }
            #pragma unroll
            for (int mt = 0; mt < 2; mt++) {
                #pragma unroll
                for (int nt = 0; nt < 4; nt++) {
                    const uint32_t* bh = &bfr[0][nt >> 1][(nt & 1) * 2];
                    const uint32_t* bl = &bfr[1][nt >> 1][(nt & 1) * 2];
                    mma16816(c[mt][nt], aF[s][0][mt], bh);   // hi*hi
                    mma16816(c[mt][nt], aF[s][0][mt], bl);   // hi*lo
                    mma16816(c[mt][nt], aF[s][1][mt], bh);   // lo*hi
                }
            }
        }

        // ---- mining on u = xsq[col] + (-2 sem.x) ----
        const int*   lblT = lblS + buf * 128;
        const float* xsqT = xsqS + buf * 128;
        float xq[8]; int lb[8];
        #pragma unroll
        for (int k = 0; k < 8; k++) {
            int cl = n_base + (k >> 1) * 8 + qt * 2 + (k & 1);
            xq[k] = xsqT[cl];
            lb[k] = lblT[cl];
        }
        #pragma unroll
        for (int mt = 0; mt < 2; mt++) {
            #pragma unroll
            for (int hr = 0; hr < 2; hr++) {
                const int gi = row_gi[mt][hr];
                const int lm = lmv[mt][hr];
                float fb = fpU[mt][hr], cb = cnU[mt][hr];
                #pragma unroll
                for (int nt = 0; nt < 4; nt++) {
                    #pragma unroll
                    for (int w = 0; w < 2; w++) {
                        int k  = nt * 2 + w;
                        int cl = n_base + nt * 8 + qt * 2 + w;
                        float u = xq[k] + c[mt][nt][hr * 2 + w];
                        bool same = (lm == lb[k]);
                        bool self = ((n0 + cl) == gi);
                        fb = fmaxf(fb, (same && !self) ? u : NEGINF);
                        cb = fminf(cb, same ? POSINF : u);
                    }
                }
                fpU[mt][hr] = fb;
                cnU[mt][hr] = cb;
            }
        }
        __syncthreads();   // protect buf before next-next stage overwrites it
    }

    // ---- final reduction: qt lanes -> smem across wn warps -> softplus ----
    #pragma unroll
    for (int mt = 0; mt < 2; mt++) {
        #pragma unroll
        for (int hr = 0; hr < 2; hr++) {
            float fb = fpU[mt][hr], cb = cnU[mt][hr];
            #pragma unroll
            for (int o = 1; o <= 2; o <<= 1) {
                fb = fmaxf(fb, __shfl_xor_sync(0xFFFFFFFFu, fb, o));
                cb = fminf(cb, __shfl_xor_sync(0xFFFFFFFFu, cb, o));
            }
            if (qt == 0) {
                int r = m_base + mt * 16 + hr * 8 + q;   // 0..63
                aggF[wn * 64 + r] = fb;
                aggC[wn * 64 + r] = cb;
            }
        }
    }
    __syncthreads();

    if (tid < 64) {
        float fb = NEGINF, cb = POSINF;
        #pragma unroll
        for (int wnn = 0; wnn < 4; wnn++) {
            fb = fmaxf(fb, aggF[wnn * 64 + tid]);
            cb = fminf(cb, aggC[wnn * 64 + tid]);
        }
        float ssqm = g_ssq[rowbase + tid];
        float fp = (fb < -1e37f) ? 0.f : sqrtf(fmaxf(ssqm + fb, 0.f) + DEPS);
        float cn = sqrtf(fmaxf(ssqm + cb, 0.f) + DEPS);
        float z = fp - cn;
        diff_out[rowbase + tid] = fmaxf(z, 0.f) + log1pf(expf(-fabsf(z)));
    }
}

// ---------------------------------------------------------------------------
// Launch
// Inputs: x[N,128] f32, wv[N,300] f32, label[N] i32, alpha[N,1] f32,
//         W[128,300] f32, b[128] f32
// Output: diff[N] then sem[N,128] (float32, concatenated)
// ---------------------------------------------------------------------------
extern "C" void kernel_launch(void* const* d_in, const int* in_sizes, int n_in,
                              void* d_out, int out_size)
{
    const float* x     = (const float*)d_in[0];
    const float* wv    = (const float*)d_in[1];
    const int*   label = (const int*)  d_in[2];
    const float* alpha = (const float*)d_in[3];
    const float* W     = (const float*)d_in[4];
    const float* b     = (const float*)d_in[5];

    float* out  = (float*)d_out;
    float* diff = out;            // [N]
    float* sem  = out + NROWS;    // [N, 128]

    static bool attr_set = false;
    if (!attr_set) {
        cudaFuncSetAttribute(dist_persist,
                             cudaFuncAttributeMaxDynamicSharedMemorySize, DIST_DSMEM);
        attr_set = true;
    }

    fc_mix_fused<<<NROWS / FC_ROWS, 256>>>(wv, W, b, alpha, x, sem);
    dist_persist<<<NROWS / 64, 256, DIST_DSMEM>>>(label, diff);
}

// round 8
// speedup vs baseline: 2.7625x; 1.1338x over previous
#include <cuda_runtime.h>
#include <cuda_bf16.h>
#include <math.h>
#include <stdint.h>

// Problem constants
#define NROWS 8192
#define DDIM  128
#define WVDIM 300
#define BIGF  1e8f
#define DEPS  1.28e-14f   // D * 1e-16
#define NEGINF -3.4e38f
#define POSINF  3.4e38f

// ---------------------------------------------------------------------------
// Scratch (__device__ globals; no allocation allowed)
// ---------------------------------------------------------------------------
__device__ float g_ssq[NROWS];    // |sem_i|^2 (exact fp32)
__device__ float g_xsq[NROWS];    // |x_j|^2   (exact fp32)
// bf16 hi/lo splits, row-major [row][0:128]=hi, [row][128:256]=lo (512 B/row)
// g_semB holds the split of (-2 * sem)  -> MMA directly produces -2*sem.x
__device__ __nv_bfloat16 g_semB[NROWS * 256];
__device__ __nv_bfloat16 g_xB[NROWS * 256];

// ---------------------------------------------------------------------------
// PTX helpers
// ---------------------------------------------------------------------------
__device__ __forceinline__ uint32_t smem_u32(const void* p) {
    uint32_t a;
    asm("{ .reg .u64 t; cvta.to.shared.u64 t, %1; cvt.u32.u64 %0, t; }" : "=r"(a) : "l"(p));
    return a;
}
__device__ __forceinline__ void ldsm_x4(uint32_t* r, uint32_t addr) {
    asm("ldmatrix.sync.aligned.m8n8.x4.shared.b16 {%0,%1,%2,%3}, [%4];"
        : "=r"(r[0]), "=r"(r[1]), "=r"(r[2]), "=r"(r[3]) : "r"(addr) : "memory");
}
__device__ __forceinline__ void mma16816(float* d, const uint32_t* a, const uint32_t* b) {
    asm("mma.sync.aligned.m16n8k16.row.col.f32.bf16.bf16.f32 "
        "{%0,%1,%2,%3}, {%4,%5,%6,%7}, {%8,%9}, {%0,%1,%2,%3};"
        : "+f"(d[0]), "+f"(d[1]), "+f"(d[2]), "+f"(d[3])
        : "r"(a[0]), "r"(a[1]), "r"(a[2]), "r"(a[3]), "r"(b[0]), "r"(b[1]));
}
__device__ __forceinline__ void cp16(uint32_t dst, const void* src) {
    asm volatile("cp.async.cg.shared.global [%0], [%1], 16;" :: "r"(dst), "l"(src) : "memory");
}
__device__ __forceinline__ void cp4(uint32_t dst, const void* src) {
    asm volatile("cp.async.ca.shared.global [%0], [%1], 4;" :: "r"(dst), "l"(src) : "memory");
}
__device__ __forceinline__ void cp_commit() {
    asm volatile("cp.async.commit_group;" ::: "memory");
}
__device__ __forceinline__ void cp_wait0() {
    asm volatile("cp.async.wait_group 0;" ::: "memory");
}

// ---------------------------------------------------------------------------
// Kernel A (fused): sem = alpha*(wv@W^T + b) + (1-alpha)*x,  PLUS:
//   sem -> output, hi/lo split of (-2*sem) -> g_semB, x -> g_xB, row norms.
// Register-tiled GEMM, 64 rows x 128 cols per CTA, 256 threads, 4m x 8d tile.
// K=300 in 6 chunks of 50; chunks double-buffered via cp.async so chunk c+1
// streams from DRAM/L2 while chunk c computes. One __syncthreads per chunk.
// ---------------------------------------------------------------------------
#define FC_ROWS   64
#define FC_KC     50
#define WT_PITCH  132
#define WV_PITCH  68
#define WT_FLOATS (FC_KC * WT_PITCH)   // 6600
#define WV_FLOATS (FC_KC * WV_PITCH)   // 3400
#define FC_SMEM   (2 * (WT_FLOATS + WV_FLOATS) * 4)   // 80000 B

__global__ __launch_bounds__(256) void fc_mix_fused(
    const float* __restrict__ wv, const float* __restrict__ W,
    const float* __restrict__ b, const float* __restrict__ alpha,
    const float* __restrict__ x, float* __restrict__ sem_out)
{
    extern __shared__ float fsm[];
    float* Wt  = fsm;                      // [2][50][132]
    float* wvt = fsm + 2 * WT_FLOATS;      // [2][50][68]

    const int tid  = threadIdx.x;
    const int tx   = tid & 15;     // d-group
    const int ty   = tid >> 4;     // m-group
    const int row0 = blockIdx.x * FC_ROWS;
    const int d0   = tx * 8;

    auto stage_chunk = [&](int c, int buf) {
        float* Wd  = Wt  + buf * WT_FLOATS;
        float* wvd = wvt + buf * WV_FLOATS;
        for (int l = tid; l < DDIM * FC_KC; l += 256) {
            int d = l / FC_KC, k = l - d * FC_KC;
            cp4(smem_u32(&Wd[k * WT_PITCH + d]), &W[d * WVDIM + c * FC_KC + k]);
        }
        for (int l = tid; l < FC_ROWS * FC_KC; l += 256) {
            int m = l / FC_KC, k = l - m * FC_KC;
            cp4(smem_u32(&wvd[k * WV_PITCH + m]),
                &wv[(size_t)(row0 + m) * WVDIM + c * FC_KC + k]);
        }
    };

    float acc[4][8];
    #pragma unroll
    for (int i = 0; i < 4; i++)
        #pragma unroll
        for (int j = 0; j < 8; j++) acc[i][j] = 0.f;

    stage_chunk(0, 0);
    cp_commit();

    for (int c = 0; c < WVDIM / FC_KC; c++) {
        const int buf = c & 1;
        cp_wait0();
        __syncthreads();
        if (c + 1 < WVDIM / FC_KC) {
            stage_chunk(c + 1, buf ^ 1);
            cp_commit();
        }
        const float* Wd  = Wt  + buf * WT_FLOATS;
        const float* wvd = wvt + buf * WV_FLOATS;

        #pragma unroll 2
        for (int k = 0; k < FC_KC; k++) {
            float4 wvv = *reinterpret_cast<const float4*>(&wvd[k * WV_PITCH + ty * 4]);
            float4 w0  = *reinterpret_cast<const float4*>(&Wd[k * WT_PITCH + d0]);
            float4 w1  = *reinterpret_cast<const float4*>(&Wd[k * WT_PITCH + d0 + 4]);
            float wm[4] = {wvv.x, wvv.y, wvv.z, wvv.w};
            float wd[8] = {w0.x, w0.y, w0.z, w0.w, w1.x, w1.y, w1.z, w1.w};
            #pragma unroll
            for (int i = 0; i < 4; i++)
                #pragma unroll
                for (int j = 0; j < 8; j++)
                    acc[i][j] = fmaf(wm[i], wd[j], acc[i][j]);
        }
    }

    // ---- fused epilogue: mix, splits, norms ----
    float bd[8];
    #pragma unroll
    for (int j = 0; j < 8; j++) bd[j] = b[d0 + j];

    #pragma unroll
    for (int i = 0; i < 4; i++) {
        const int row = row0 + ty * 4 + i;
        const float al = alpha[row];
        float4 xa = reinterpret_cast<const float4*>(x)[(size_t)row * 32 + tx * 2];
        float4 xb = reinterpret_cast<const float4*>(x)[(size_t)row * 32 + tx * 2 + 1];
        float xv[8] = {xa.x, xa.y, xa.z, xa.w, xb.x, xb.y, xb.z, xb.w};

        float sv[8];
        float pssq = 0.f, pxsq = 0.f;
        #pragma unroll
        for (int j = 0; j < 8; j++) {
            float s = al * (acc[i][j] + bd[j]) + (1.f - al) * xv[j];
            sv[j] = s;
            pssq = fmaf(s, s, pssq);
            pxsq = fmaf(xv[j], xv[j], pxsq);
        }

        float4 o0 = {sv[0], sv[1], sv[2], sv[3]};
        float4 o1 = {sv[4], sv[5], sv[6], sv[7]};
        reinterpret_cast<float4*>(sem_out)[(size_t)row * 32 + tx * 2]     = o0;
        reinterpret_cast<float4*>(sem_out)[(size_t)row * 32 + tx * 2 + 1] = o1;

        __nv_bfloat162 sh[4], sl[4], xh[4], xl[4];
        #pragma unroll
        for (int j2 = 0; j2 < 4; j2++) {
            float a0 = -2.f * sv[2*j2], a1 = -2.f * sv[2*j2+1];
            __nv_bfloat16 h0 = __float2bfloat16(a0), h1 = __float2bfloat16(a1);
            sh[j2] = __nv_bfloat162(h0, h1);
            sl[j2] = __nv_bfloat162(__float2bfloat16(a0 - __bfloat162float(h0)),
                                    __float2bfloat16(a1 - __bfloat162float(h1)));
            float b0 = xv[2*j2], b1 = xv[2*j2+1];
            __nv_bfloat16 g0 = __float2bfloat16(b0), g1 = __float2bfloat16(b1);
            xh[j2] = __nv_bfloat162(g0, g1);
            xl[j2] = __nv_bfloat162(__float2bfloat16(b0 - __bfloat162float(g0)),
                                    __float2bfloat16(b1 - __bfloat162float(g1)));
        }
        uint4* semB4 = reinterpret_cast<uint4*>(g_semB + (size_t)row * 256);
        uint4* xB4   = reinterpret_cast<uint4*>(g_xB   + (size_t)row * 256);
        semB4[tx]      = *reinterpret_cast<uint4*>(sh);
        semB4[16 + tx] = *reinterpret_cast<uint4*>(sl);
        xB4[tx]        = *reinterpret_cast<uint4*>(xh);
        xB4[16 + tx]   = *reinterpret_cast<uint4*>(xl);

        #pragma unroll
        for (int o = 1; o <= 8; o <<= 1) {
            pssq += __shfl_xor_sync(0xFFFFFFFFu, pssq, o);
            pxsq += __shfl_xor_sync(0xFFFFFFFFu, pxsq, o);
        }
        if (tx == 0) {
            g_ssq[row] = pssq;
            g_xsq[row] = pxsq;
        }
    }
}

// ---------------------------------------------------------------------------
// Kernel B: persistent distance + batch-hard mining.
// 128 CTAs; CTA = 64-row m-strip, sweeps 64 n-tiles of 128 cols.
// A-fragments (all K) preloaded to registers. B double-buffered via cp.async.
// NEW vs R7: one __syncthreads per tile; explicit B-fragment ping-pong so
// step s+1's ldsm issue under step s's MMAs; mining metadata loaded early.
// ---------------------------------------------------------------------------
#define A_BYTES   32768
#define B_BYTES   65536
#define OFF_B     A_BYTES
#define OFF_LBL   (A_BYTES + 2 * B_BYTES)
#define OFF_XSQ   (OFF_LBL + 2 * 128 * 4)
#define OFF_AGG   (OFF_XSQ + 2 * 128 * 4)
#define DIST_DSMEM (OFF_AGG + 2 * 4 * 64 * 4)   // 167936

#define NSTEPS 64

__global__ __launch_bounds__(256) void dist_persist(
    const int* __restrict__ label, float* __restrict__ diff_out)
{
    extern __shared__ char dyn[];
    char*  As   = dyn;
    char*  Bs   = dyn + OFF_B;
    int*   lblS = reinterpret_cast<int*>(dyn + OFF_LBL);
    float* xsqS = reinterpret_cast<float*>(dyn + OFF_XSQ);
    float* aggF = reinterpret_cast<float*>(dyn + OFF_AGG);            // [4][64]
    float* aggC = reinterpret_cast<float*>(dyn + OFF_AGG + 4*64*4);   // [4][64]

    const int tid  = threadIdx.x;
    const int wid  = tid >> 5;
    const int lane = tid & 31;
    const int rowbase = blockIdx.x * 64;

    // ---- stage A strip (64 rows x 32 chunks), swizzled ----
    {
        const uint4* gA = reinterpret_cast<const uint4*>(g_semB) + (size_t)rowbase * 32;
        #pragma unroll
        for (int it = 0; it < 8; it++) {
            int idx = it * 256 + tid;
            int r = idx >> 5, cch = idx & 31;
            uint32_t off = (uint32_t)(r * 512 + ((cch ^ (r & 7)) << 4));
            *reinterpret_cast<uint4*>(As + off) = gA[(size_t)r * 32 + cch];
        }
    }
    __syncthreads();

    const uint32_t AsU = smem_u32(As);
    const uint32_t BsU = smem_u32(Bs);

    const int wm = wid & 1;        // 2 m-slabs of 32
    const int wn = wid >> 1;       // 4 n-slabs of 32
    const int m_base = wm * 32;
    const int n_base = wn * 32;

    // ---- preload ALL A fragments into registers ----
    uint32_t aF[8][2][2][4];       // [kstep][half][mt][4]
    {
        const uint32_t a_chunk_add = (uint32_t)(lane >> 4);
        #pragma unroll
        for (int mt = 0; mt < 2; mt++) {
            int r = m_base + mt * 16 + (lane & 15);
            uint32_t base = AsU + r * 512;
            uint32_t sw   = (uint32_t)(r & 7);
            #pragma unroll
            for (int s = 0; s < 8; s++) {
                #pragma unroll
                for (int h = 0; h < 2; h++) {
                    uint32_t ch = (uint32_t)(h * 16 + s * 2) + a_chunk_add;
                    ldsm_x4(aF[s][h][mt], base + ((ch ^ sw) << 4));
                }
            }
        }
    }

    // B ldmatrix addressing (per stage; add buf*B_BYTES)
    uint32_t b_off[2], b_sw[2];
    #pragma unroll
    for (int p = 0; p < 2; p++) {
        int r = n_base + p * 16 + ((lane >> 4) << 3) + (lane & 7);
        b_off[p] = BsU + r * 512;
        b_sw[p]  = (uint32_t)(r & 7);
    }
    const uint32_t b_chunk_add = (uint32_t)((lane >> 3) & 1);

    // per-thread row info
    const int q  = lane >> 2;
    const int qt = lane & 3;
    int row_gi[2][2];
    int lmv[2][2];
    #pragma unroll
    for (int mt = 0; mt < 2; mt++)
        #pragma unroll
        for (int hr = 0; hr < 2; hr++) {
            row_gi[mt][hr] = rowbase + m_base + mt * 16 + hr * 8 + q;
            lmv[mt][hr]    = label[row_gi[mt][hr]];
        }

    float fpU[2][2], cnU[2][2];
    #pragma unroll
    for (int mt = 0; mt < 2; mt++)
        #pragma unroll
        for (int hr = 0; hr < 2; hr++) { fpU[mt][hr] = NEGINF; cnU[mt][hr] = POSINF; }

    auto stage_tile = [&](int t, int buf) {
        int n0 = t * 128;
        const char* gB = reinterpret_cast<const char*>(g_xB) + (size_t)n0 * 512;
        uint32_t bb = BsU + buf * B_BYTES;
        #pragma unroll
        for (int it = 0; it < 16; it++) {
            int idx = it * 256 + tid;
            int r = idx >> 5, cch = idx & 31;
            uint32_t dst = bb + (uint32_t)(r * 512 + ((cch ^ (r & 7)) << 4));
            cp16(dst, gB + (size_t)r * 512 + cch * 16);
        }
        if (tid < 128) {
            cp4(smem_u32(lblS + buf * 128 + tid), label + n0 + tid);
        } else {
            int t2 = tid - 128;
            cp4(smem_u32(xsqS + buf * 128 + t2), g_xsq + n0 + t2);
        }
    };

    stage_tile(0, 0);
    cp_commit();

    for (int t = 0; t < NSTEPS; t++) {
        const int buf = t & 1;
        const int n0  = t * 128;
        cp_wait0();          // tile t fully staged (only outstanding group)
        __syncthreads();     // visibility + all warps done with buf^1 (tile t-1)
        if (t + 1 < NSTEPS) {
            stage_tile(t + 1, buf ^ 1);   // overwrites t-1's buffers: safe
            cp_commit();
        }

        // mining metadata early (latency hidden under MMA loop)
        const int*   lblT = lblS + buf * 128;
        const float* xsqT = xsqS + buf * 128;
        float xq[8]; int lb[8];
        #pragma unroll
        for (int k = 0; k < 8; k++) {
            int cl = n_base + (k >> 1) * 8 + qt * 2 + (k & 1);
            xq[k] = xsqT[cl];
            lb[k] = lblT[cl];
        }

        float c[2][4][4];
        #pragma unroll
        for (int mt = 0; mt < 2; mt++)
            #pragma unroll
            for (int nt = 0; nt < 4; nt++)
                #pragma unroll
                for (int e = 0; e < 4; e++) c[mt][nt][e] = 0.f;

        const uint32_t bufAdd = (uint32_t)(buf * B_BYTES);

        // B-fragment ping-pong: prefetch step s+1 while step s's MMAs issue
        uint32_t bfr[2][2][2][4];   // [parity][half][pair][4]
        #pragma unroll
        for (int h = 0; h < 2; h++) {
            uint32_t chB = (uint32_t)(h * 16) + b_chunk_add;
            #pragma unroll
            for (int p = 0; p < 2; p++)
                ldsm_x4(bfr[0][h][p], b_off[p] + bufAdd + ((chB ^ b_sw[p]) << 4));
        }
        #pragma unroll
        for (int s = 0; s < 8; s++) {
            const int cur = s & 1;
            if (s < 7) {
                #pragma unroll
                for (int h = 0; h < 2; h++) {
                    uint32_t chB = (uint32_t)(h * 16 + (s + 1) * 2) + b_chunk_add;
                    #pragma unroll
                    for (int p = 0; p < 2; p++)
                        ldsm_x4(bfr[cur ^ 1][h][p],
                                b_off[p] + bufAdd + ((chB ^ b_sw[p]) << 4));
                }
            }
            #pragma unroll
            for (int mt = 0; mt < 2; mt++) {
                #pragma unroll
                for (int nt = 0; nt < 4; nt++) {
                    const uint32_t* bh = &bfr[cur][0][nt >> 1][(nt & 1) * 2];
                    const uint32_t* bl = &bfr[cur][1][nt >> 1][(nt & 1) * 2];
                    mma16816(c[mt][nt], aF[s][0][mt], bh);   // hi*hi
                    mma16816(c[mt][nt], aF[s][0][mt], bl);   // hi*lo
                    mma16816(c[mt][nt], aF[s][1][mt], bh);   // lo*hi
                }
            }
        }

        // ---- mining on u = xsq[col] + (-2 sem.x) ----
        #pragma unroll
        for (int mt = 0; mt < 2; mt++) {
            #pragma unroll
            for (int hr = 0; hr < 2; hr++) {
                const int gi = row_gi[mt][hr];
                const int lm = lmv[mt][hr];
                float fb = fpU[mt][hr], cb = cnU[mt][hr];
                #pragma unroll
                for (int nt = 0; nt < 4; nt++) {
                    #pragma unroll
                    for (int w = 0; w < 2; w++) {
                        int k  = nt * 2 + w;
                        int cl = n_base + nt * 8 + qt * 2 + w;
                        float u = xq[k] + c[mt][nt][hr * 2 + w];
                        bool same = (lm == lb[k]);
                        bool self = ((n0 + cl) == gi);
                        fb = fmaxf(fb, (same && !self) ? u : NEGINF);
                        cb = fminf(cb, same ? POSINF : u);
                    }
                }
                fpU[mt][hr] = fb;
                cnU[mt][hr] = cb;
            }
        }
    }

    // ---- final reduction: quad lanes -> smem across wn warps -> softplus ----
    #pragma unroll
    for (int mt = 0; mt < 2; mt++) {
        #pragma unroll
        for (int hr = 0; hr < 2; hr++) {
            float fb = fpU[mt][hr], cb = cnU[mt][hr];
            #pragma unroll
            for (int o = 1; o <= 2; o <<= 1) {
                fb = fmaxf(fb, __shfl_xor_sync(0xFFFFFFFFu, fb, o));
                cb = fminf(cb, __shfl_xor_sync(0xFFFFFFFFu, cb, o));
            }
            if (qt == 0) {
                int r = m_base + mt * 16 + hr * 8 + q;
                aggF[wn * 64 + r] = fb;
                aggC[wn * 64 + r] = cb;
            }
        }
    }
    __syncthreads();

    if (tid < 64) {
        float fb = NEGINF, cb = POSINF;
        #pragma unroll
        for (int wnn = 0; wnn < 4; wnn++) {
            fb = fmaxf(fb, aggF[wnn * 64 + tid]);
            cb = fminf(cb, aggC[wnn * 64 + tid]);
        }
        float ssqm = g_ssq[rowbase + tid];
        float fp = (fb < -1e37f) ? 0.f : sqrtf(fmaxf(ssqm + fb, 0.f) + DEPS);
        float cn = sqrtf(fmaxf(ssqm + cb, 0.f) + DEPS);
        float z = fp - cn;
        diff_out[rowbase + tid] = fmaxf(z, 0.f) + log1pf(expf(-fabsf(z)));
    }
}

// ---------------------------------------------------------------------------
// Launch
// Inputs: x[N,128] f32, wv[N,300] f32, label[N] i32, alpha[N,1] f32,
//         W[128,300] f32, b[128] f32
// Output: diff[N] then sem[N,128] (float32, concatenated)
// ---------------------------------------------------------------------------
extern "C" void kernel_launch(void* const* d_in, const int* in_sizes, int n_in,
                              void* d_out, int out_size)
{
    const float* x     = (const float*)d_in[0];
    const float* wv    = (const float*)d_in[1];
    const int*   label = (const int*)  d_in[2];
    const float* alpha = (const float*)d_in[3];
    const float* W     = (const float*)d_in[4];
    const float* b     = (const float*)d_in[5];

    float* out  = (float*)d_out;
    float* diff = out;            // [N]
    float* sem  = out + NROWS;    // [N, 128]

    static bool attr_set = false;
    if (!attr_set) {
        cudaFuncSetAttribute(dist_persist,
                             cudaFuncAttributeMaxDynamicSharedMemorySize, DIST_DSMEM);
        cudaFuncSetAttribute(fc_mix_fused,
                             cudaFuncAttributeMaxDynamicSharedMemorySize, FC_SMEM);
        attr_set = true;
    }

    fc_mix_fused<<<NROWS / FC_ROWS, 256, FC_SMEM>>>(wv, W, b, alpha, x, sem);
    dist_persist<<<NROWS / 64, 256, DIST_DSMEM>>>(label, diff);
}

// round 9
// speedup vs baseline: 2.8062x; 1.0158x over previous
#include <cuda_runtime.h>
#include <cuda_bf16.h>
#include <math.h>
#include <stdint.h>

// Problem constants
#define NROWS 8192
#define DDIM  128
#define WVDIM 300
#define BIGF  1e8f
#define DEPS  1.28e-14f   // D * 1e-16
#define NEGINF -3.4e38f
#define POSINF  3.4e38f

// ---------------------------------------------------------------------------
// Scratch (__device__ globals; no allocation allowed)
// ---------------------------------------------------------------------------
__device__ float g_ssq[NROWS];
__device__ float g_xsq[NROWS];
// A side: hi/lo split of (-2*sem), row-major [row][0:128]=hi,[128:256]=lo (512B/row)
__device__ __nv_bfloat16 g_semB[NROWS * 256];
// B side (x): FRAGMENT-MAJOR layout, 4 MB:
//   brick = 8 n-rows x 16 k (one mma B operand tile per half)
//   addr = ((h*1024 + nb)*4 + sp)*512 + lane*16 + sw*8 + khalf*4
//   h: 0=hi,1=lo; nb = n>>3 (0..1023); sp = k-step pair (0..3); lane = (n&7)*4 + kpair;
//   lane entry 16B = [b0(s=2sp), b1(2sp), b0(2sp+1), b1(2sp+1)]
//   b0 = 2 bf16 at k = s*16 + kpair*2; b1 = same + 8.
__device__ __nv_bfloat16 g_xB[NROWS * 256];

// ---------------------------------------------------------------------------
// PTX helpers
// ---------------------------------------------------------------------------
__device__ __forceinline__ uint32_t smem_u32(const void* p) {
    uint32_t a;
    asm("{ .reg .u64 t; cvta.to.shared.u64 t, %1; cvt.u32.u64 %0, t; }" : "=r"(a) : "l"(p));
    return a;
}
__device__ __forceinline__ void ldsm_x4(uint32_t* r, uint32_t addr) {
    asm("ldmatrix.sync.aligned.m8n8.x4.shared.b16 {%0,%1,%2,%3}, [%4];"
        : "=r"(r[0]), "=r"(r[1]), "=r"(r[2]), "=r"(r[3]) : "r"(addr) : "memory");
}
__device__ __forceinline__ void mma16816(float* d, const uint32_t* a, const uint32_t* b) {
    asm("mma.sync.aligned.m16n8k16.row.col.f32.bf16.bf16.f32 "
        "{%0,%1,%2,%3}, {%4,%5,%6,%7}, {%8,%9}, {%0,%1,%2,%3};"
        : "+f"(d[0]), "+f"(d[1]), "+f"(d[2]), "+f"(d[3])
        : "r"(a[0]), "r"(a[1]), "r"(a[2]), "r"(a[3]), "r"(b[0]), "r"(b[1]));
}
__device__ __forceinline__ void cp4(uint32_t dst, const void* src) {
    asm volatile("cp.async.ca.shared.global [%0], [%1], 4;" :: "r"(dst), "l"(src) : "memory");
}
__device__ __forceinline__ void cp_commit() {
    asm volatile("cp.async.commit_group;" ::: "memory");
}
__device__ __forceinline__ void cp_wait0() {
    asm volatile("cp.async.wait_group 0;" ::: "memory");
}

// ---------------------------------------------------------------------------
// Kernel A (fused): sem = alpha*(wv@W^T + b) + (1-alpha)*x,  PLUS:
//   sem -> output, hi/lo split of (-2*sem) -> g_semB (row-major),
//   hi/lo split of x -> g_xB (fragment-major), row norms.
// K=300 double-buffered via cp.async; 64 rows x 128 cols per CTA.
// ---------------------------------------------------------------------------
#define FC_ROWS   64
#define FC_KC     50
#define WT_PITCH  132
#define WV_PITCH  68
#define WT_FLOATS (FC_KC * WT_PITCH)
#define WV_FLOATS (FC_KC * WV_PITCH)
#define FC_SMEM   (2 * (WT_FLOATS + WV_FLOATS) * 4)   // 80000 B

__global__ __launch_bounds__(256) void fc_mix_fused(
    const float* __restrict__ wv, const float* __restrict__ W,
    const float* __restrict__ b, const float* __restrict__ alpha,
    const float* __restrict__ x, float* __restrict__ sem_out)
{
    extern __shared__ float fsm[];
    float* Wt  = fsm;
    float* wvt = fsm + 2 * WT_FLOATS;

    const int tid  = threadIdx.x;
    const int tx   = tid & 15;
    const int ty   = tid >> 4;
    const int row0 = blockIdx.x * FC_ROWS;
    const int d0   = tx * 8;

    auto stage_chunk = [&](int c, int buf) {
        float* Wd  = Wt  + buf * WT_FLOATS;
        float* wvd = wvt + buf * WV_FLOATS;
        for (int l = tid; l < DDIM * FC_KC; l += 256) {
            int d = l / FC_KC, k = l - d * FC_KC;
            cp4(smem_u32(&Wd[k * WT_PITCH + d]), &W[d * WVDIM + c * FC_KC + k]);
        }
        for (int l = tid; l < FC_ROWS * FC_KC; l += 256) {
            int m = l / FC_KC, k = l - m * FC_KC;
            cp4(smem_u32(&wvd[k * WV_PITCH + m]),
                &wv[(size_t)(row0 + m) * WVDIM + c * FC_KC + k]);
        }
    };

    float acc[4][8];
    #pragma unroll
    for (int i = 0; i < 4; i++)
        #pragma unroll
        for (int j = 0; j < 8; j++) acc[i][j] = 0.f;

    stage_chunk(0, 0);
    cp_commit();

    for (int c = 0; c < WVDIM / FC_KC; c++) {
        const int buf = c & 1;
        cp_wait0();
        __syncthreads();
        if (c + 1 < WVDIM / FC_KC) {
            stage_chunk(c + 1, buf ^ 1);
            cp_commit();
        }
        const float* Wd  = Wt  + buf * WT_FLOATS;
        const float* wvd = wvt + buf * WV_FLOATS;

        #pragma unroll 2
        for (int k = 0; k < FC_KC; k++) {
            float4 wvv = *reinterpret_cast<const float4*>(&wvd[k * WV_PITCH + ty * 4]);
            float4 w0  = *reinterpret_cast<const float4*>(&Wd[k * WT_PITCH + d0]);
            float4 w1  = *reinterpret_cast<const float4*>(&Wd[k * WT_PITCH + d0 + 4]);
            float wm[4] = {wvv.x, wvv.y, wvv.z, wvv.w};
            float wd[8] = {w0.x, w0.y, w0.z, w0.w, w1.x, w1.y, w1.z, w1.w};
            #pragma unroll
            for (int i = 0; i < 4; i++)
                #pragma unroll
                for (int j = 0; j < 8; j++)
                    acc[i][j] = fmaf(wm[i], wd[j], acc[i][j]);
        }
    }

    // ---- fused epilogue: mix, splits, norms ----
    float bd[8];
    #pragma unroll
    for (int j = 0; j < 8; j++) bd[j] = b[d0 + j];

    // fragment-major addressing pieces for this thread's k-range
    const int sbv   = tx >> 1;        // k16-step 0..7
    const int khalf = tx & 1;         // 0 -> b0 slot, 1 -> b1 slot
    const int sp2   = sbv >> 1;       // k-step pair 0..3
    const int sw    = sbv & 1;        // which step within pair
    char* xbase = reinterpret_cast<char*>(g_xB);

    #pragma unroll
    for (int i = 0; i < 4; i++) {
        const int row = row0 + ty * 4 + i;
        const float al = alpha[row];
        float4 xa = reinterpret_cast<const float4*>(x)[(size_t)row * 32 + tx * 2];
        float4 xb = reinterpret_cast<const float4*>(x)[(size_t)row * 32 + tx * 2 + 1];
        float xv[8] = {xa.x, xa.y, xa.z, xa.w, xb.x, xb.y, xb.z, xb.w};

        float sv[8];
        float pssq = 0.f, pxsq = 0.f;
        #pragma unroll
        for (int j = 0; j < 8; j++) {
            float s = al * (acc[i][j] + bd[j]) + (1.f - al) * xv[j];
            sv[j] = s;
            pssq = fmaf(s, s, pssq);
            pxsq = fmaf(xv[j], xv[j], pxsq);
        }

        float4 o0 = {sv[0], sv[1], sv[2], sv[3]};
        float4 o1 = {sv[4], sv[5], sv[6], sv[7]};
        reinterpret_cast<float4*>(sem_out)[(size_t)row * 32 + tx * 2]     = o0;
        reinterpret_cast<float4*>(sem_out)[(size_t)row * 32 + tx * 2 + 1] = o1;

        // A side: hi/lo split of (-2*sem), row-major
        __nv_bfloat162 sh[4], sl[4];
        #pragma unroll
        for (int j2 = 0; j2 < 4; j2++) {
            float a0 = -2.f * sv[2*j2], a1 = -2.f * sv[2*j2+1];
            __nv_bfloat16 h0 = __float2bfloat16(a0), h1 = __float2bfloat16(a1);
            sh[j2] = __nv_bfloat162(h0, h1);
            sl[j2] = __nv_bfloat162(__float2bfloat16(a0 - __bfloat162float(h0)),
                                    __float2bfloat16(a1 - __bfloat162float(h1)));
        }
        uint4* semB4 = reinterpret_cast<uint4*>(g_semB + (size_t)row * 256);
        semB4[tx]      = *reinterpret_cast<uint4*>(sh);
        semB4[16 + tx] = *reinterpret_cast<uint4*>(sl);

        // B side: hi/lo split of x, fragment-major scatter (8x STG.32)
        const int nb  = row >> 3;
        const int ln8 = row & 7;
        #pragma unroll
        for (int p = 0; p < 4; p++) {
            float b0f = xv[2*p], b1f = xv[2*p+1];
            __nv_bfloat16 g0 = __float2bfloat16(b0f), g1 = __float2bfloat16(b1f);
            __nv_bfloat162 hi2(g0, g1);
            __nv_bfloat162 lo2(__float2bfloat16(b0f - __bfloat162float(g0)),
                               __float2bfloat16(b1f - __bfloat162float(g1)));
            size_t offH = ((size_t)((0 * 1024 + nb) * 4 + sp2)) * 512
                        + (ln8 * 4 + p) * 16 + sw * 8 + khalf * 4;
            size_t offL = ((size_t)((1 * 1024 + nb) * 4 + sp2)) * 512
                        + (ln8 * 4 + p) * 16 + sw * 8 + khalf * 4;
            *reinterpret_cast<uint32_t*>(xbase + offH) = *reinterpret_cast<uint32_t*>(&hi2);
            *reinterpret_cast<uint32_t*>(xbase + offL) = *reinterpret_cast<uint32_t*>(&lo2);
        }

        #pragma unroll
        for (int o = 1; o <= 8; o <<= 1) {
            pssq += __shfl_xor_sync(0xFFFFFFFFu, pssq, o);
            pxsq += __shfl_xor_sync(0xFFFFFFFFu, pxsq, o);
        }
        if (tx == 0) {
            g_ssq[row] = pssq;
            g_xsq[row] = pxsq;
        }
    }
}

// ---------------------------------------------------------------------------
// Kernel B: persistent distance + batch-hard mining, BARRIER-FREE main loop.
// 128 CTAs; CTA = 64-row m-strip, sweeps 64 n-tiles of 128 cols.
// A-fragments (all K) in registers (one-time smem staging + ldsm).
// B-fragments loaded straight from global fragment-major layout via LDG.128
// (L2-resident, L1-hot); double-buffered per k-step pair. No smem B, no
// cp.async, no __syncthreads in the tile loop -> warps drift out of phase
// and mining/loads of one warp overlap MMAs of others.
// ---------------------------------------------------------------------------
#define DIST_DSMEM 32768      // A staging only
#define NSTEPS 64

__global__ __launch_bounds__(256) void dist_persist(
    const int* __restrict__ label, float* __restrict__ diff_out)
{
    extern __shared__ char dyn[];          // A staging (reused region)
    __shared__ float aggF[4 * 64];
    __shared__ float aggC[4 * 64];

    const int tid  = threadIdx.x;
    const int wid  = tid >> 5;
    const int lane = tid & 31;
    const int rowbase = blockIdx.x * 64;

    // ---- stage A strip (64 rows x 32 chunks), swizzled ----
    {
        const uint4* gA = reinterpret_cast<const uint4*>(g_semB) + (size_t)rowbase * 32;
        #pragma unroll
        for (int it = 0; it < 8; it++) {
            int idx = it * 256 + tid;
            int r = idx >> 5, cch = idx & 31;
            uint32_t off = (uint32_t)(r * 512 + ((cch ^ (r & 7)) << 4));
            *reinterpret_cast<uint4*>(dyn + off) = gA[(size_t)r * 32 + cch];
        }
    }
    __syncthreads();

    const uint32_t AsU = smem_u32(dyn);

    const int wm = wid & 1;        // 2 m-slabs of 32
    const int wn = wid >> 1;       // 4 n-slabs of 32
    const int m_base = wm * 32;
    const int n_base = wn * 32;

    // ---- preload ALL A fragments into registers ----
    uint32_t aF[8][2][2][4];       // [kstep][half][mt][4]
    {
        const uint32_t a_chunk_add = (uint32_t)(lane >> 4);
        #pragma unroll
        for (int mt = 0; mt < 2; mt++) {
            int r = m_base + mt * 16 + (lane & 15);
            uint32_t base = AsU + r * 512;
            uint32_t sw   = (uint32_t)(r & 7);
            #pragma unroll
            for (int s = 0; s < 8; s++) {
                #pragma unroll
                for (int h = 0; h < 2; h++) {
                    uint32_t ch = (uint32_t)(h * 16 + s * 2) + a_chunk_add;
                    ldsm_x4(aF[s][h][mt], base + ((ch ^ sw) << 4));
                }
            }
        }
    }

    // per-thread row info
    const int q  = lane >> 2;
    const int qt = lane & 3;
    int row_gi[2][2];
    int lmv[2][2];
    #pragma unroll
    for (int mt = 0; mt < 2; mt++)
        #pragma unroll
        for (int hr = 0; hr < 2; hr++) {
            row_gi[mt][hr] = rowbase + m_base + mt * 16 + hr * 8 + q;
            lmv[mt][hr]    = label[row_gi[mt][hr]];
        }

    float fpU[2][2], cnU[2][2];
    #pragma unroll
    for (int mt = 0; mt < 2; mt++)
        #pragma unroll
        for (int hr = 0; hr < 2; hr++) { fpU[mt][hr] = NEGINF; cnU[mt][hr] = POSINF; }

    // B fragment-major base pointers: h=0 hi, h=1 lo.
    // addr(h, nb, sp) = ((h*1024 + nb)*4 + sp)*512 + lane*16
    const char* BF = reinterpret_cast<const char*>(g_xB);
    const char* bPtrH = BF + (size_t)lane * 16;
    const char* bPtrL = BF + (size_t)1024 * 4 * 512 + (size_t)lane * 16;
    // per warp: nb = t*16 + wn*4 + nt

    uint32_t bReg[2][2][4][4];     // [buf][h][nt][4]  (16B = 2 k-steps)
    auto loadB = [&](int t, int sp, int buf) {
        const size_t tileOff = (size_t)t * 16 * 2048 + (size_t)wn * 4 * 2048
                             + (size_t)sp * 512;
        #pragma unroll
        for (int nt = 0; nt < 4; nt++) {
            const uint4 vh = *reinterpret_cast<const uint4*>(bPtrH + tileOff + nt * 2048);
            const uint4 vl = *reinterpret_cast<const uint4*>(bPtrL + tileOff + nt * 2048);
            bReg[buf][0][nt][0] = vh.x; bReg[buf][0][nt][1] = vh.y;
            bReg[buf][0][nt][2] = vh.z; bReg[buf][0][nt][3] = vh.w;
            bReg[buf][1][nt][0] = vl.x; bReg[buf][1][nt][1] = vl.y;
            bReg[buf][1][nt][2] = vl.z; bReg[buf][1][nt][3] = vl.w;
        }
    };

    loadB(0, 0, 0);
    int buf = 0;

    for (int t = 0; t < NSTEPS; t++) {
        const int n0 = t * 128;

        // mining metadata early (L1-hot; latency hides under MMAs)
        float xq[8]; int lb[8];
        #pragma unroll
        for (int k = 0; k < 8; k++) {
            int cl = n0 + n_base + (k >> 1) * 8 + qt * 2 + (k & 1);
            xq[k] = g_xsq[cl];
            lb[k] = label[cl];
        }

        float c[2][4][4];
        #pragma unroll
        for (int mt = 0; mt < 2; mt++)
            #pragma unroll
            for (int nt = 0; nt < 4; nt++)
                #pragma unroll
                for (int e = 0; e < 4; e++) c[mt][nt][e] = 0.f;

        #pragma unroll
        for (int sp = 0; sp < 4; sp++) {
            // prefetch next sp-pair (or next tile's first)
            if (sp < 3)              loadB(t, sp + 1, buf ^ 1);
            else if (t + 1 < NSTEPS) loadB(t + 1, 0, buf ^ 1);

            #pragma unroll
            for (int ks = 0; ks < 2; ks++) {
                const int s = sp * 2 + ks;
                #pragma unroll
                for (int mt = 0; mt < 2; mt++) {
                    #pragma unroll
                    for (int nt = 0; nt < 4; nt++) {
                        const uint32_t* bh = &bReg[buf][0][nt][ks * 2];
                        const uint32_t* bl = &bReg[buf][1][nt][ks * 2];
                        mma16816(c[mt][nt], aF[s][0][mt], bh);   // hi*hi
                        mma16816(c[mt][nt], aF[s][0][mt], bl);   // hi*lo
                        mma16816(c[mt][nt], aF[s][1][mt], bh);   // lo*hi
                    }
                }
            }
            buf ^= 1;
        }

        // ---- mining on u = xsq[col] + (-2 sem.x) ----
        #pragma unroll
        for (int mt = 0; mt < 2; mt++) {
            #pragma unroll
            for (int hr = 0; hr < 2; hr++) {
                const int gi = row_gi[mt][hr];
                const int lm = lmv[mt][hr];
                float fb = fpU[mt][hr], cb = cnU[mt][hr];
                #pragma unroll
                for (int nt = 0; nt < 4; nt++) {
                    #pragma unroll
                    for (int w = 0; w < 2; w++) {
                        int k  = nt * 2 + w;
                        int cl = n0 + n_base + nt * 8 + qt * 2 + w;
                        float u = xq[k] + c[mt][nt][hr * 2 + w];
                        bool same = (lm == lb[k]);
                        bool self = (cl == gi);
                        fb = fmaxf(fb, (same && !self) ? u : NEGINF);
                        cb = fminf(cb, same ? POSINF : u);
                    }
                }
                fpU[mt][hr] = fb;
                cnU[mt][hr] = cb;
            }
        }
    }

    // ---- final reduction: quad lanes -> smem across wn warps -> softplus ----
    #pragma unroll
    for (int mt = 0; mt < 2; mt++) {
        #pragma unroll
        for (int hr = 0; hr < 2; hr++) {
            float fb = fpU[mt][hr], cb = cnU[mt][hr];
            #pragma unroll
            for (int o = 1; o <= 2; o <<= 1) {
                fb = fmaxf(fb, __shfl_xor_sync(0xFFFFFFFFu, fb, o));
                cb = fminf(cb, __shfl_xor_sync(0xFFFFFFFFu, cb, o));
            }
            if (qt == 0) {
                int r = m_base + mt * 16 + hr * 8 + q;
                aggF[wn * 64 + r] = fb;
                aggC[wn * 64 + r] = cb;
            }
        }
    }
    __syncthreads();

    if (tid < 64) {
        float fb = NEGINF, cb = POSINF;
        #pragma unroll
        for (int wnn = 0; wnn < 4; wnn++) {
            fb = fmaxf(fb, aggF[wnn * 64 + tid]);
            cb = fminf(cb, aggC[wnn * 64 + tid]);
        }
        float ssqm = g_ssq[rowbase + tid];
        float fp = (fb < -1e37f) ? 0.f : sqrtf(fmaxf(ssqm + fb, 0.f) + DEPS);
        float cn = sqrtf(fmaxf(ssqm + cb, 0.f) + DEPS);
        float z = fp - cn;
        diff_out[rowbase + tid] = fmaxf(z, 0.f) + log1pf(expf(-fabsf(z)));
    }
}

// ---------------------------------------------------------------------------
// Launch
// Inputs: x[N,128] f32, wv[N,300] f32, label[N] i32, alpha[N,1] f32,
//         W[128,300] f32, b[128] f32
// Output: diff[N] then sem[N,128] (float32, concatenated)
// ---------------------------------------------------------------------------
extern "C" void kernel_launch(void* const* d_in, const int* in_sizes, int n_in,
                              void* d_out, int out_size)
{
    const float* x     = (const float*)d_in[0];
    const float* wv    = (const float*)d_in[1];
    const int*   label = (const int*)  d_in[2];
    const float* alpha = (const float*)d_in[3];
    const float* W     = (const float*)d_in[4];
    const float* b     = (const float*)d_in[5];

    float* out  = (float*)d_out;
    float* diff = out;            // [N]
    float* sem  = out + NROWS;    // [N, 128]

    static bool attr_set = false;
    if (!attr_set) {
        cudaFuncSetAttribute(dist_persist,
                             cudaFuncAttributeMaxDynamicSharedMemorySize, DIST_DSMEM);
        cudaFuncSetAttribute(fc_mix_fused,
                             cudaFuncAttributeMaxDynamicSharedMemorySize, FC_SMEM);
        attr_set = true;
    }

    fc_mix_fused<<<NROWS / FC_ROWS, 256, FC_SMEM>>>(wv, W, b, alpha, x, sem);
    dist_persist<<<NROWS / 64, 256, DIST_DSMEM>>>(label, diff);
}

// round 10
// speedup vs baseline: 2.8811x; 1.0267x over previous
#include <cuda_runtime.h>
#include <cuda_bf16.h>
#include <math.h>
#include <stdint.h>

// Problem constants
#define NROWS 8192
#define DDIM  128
#define WVDIM 300
#define BIGF  1e8f
#define DEPS  1.28e-14f   // D * 1e-16
#define NEGINF -3.4e38f
#define POSINF  3.4e38f

// ---------------------------------------------------------------------------
// Scratch (__device__ globals; no allocation allowed)
// ---------------------------------------------------------------------------
__device__ float g_ssq[NROWS];
__device__ float g_xsq[NROWS];
// hi/lo bf16 splits, row-major [row][0:128]=hi,[128:256]=lo (512 B/row)
// g_semB holds the split of (-2*sem)
__device__ __nv_bfloat16 g_semB[NROWS * 256];
__device__ __nv_bfloat16 g_xB[NROWS * 256];

// ---------------------------------------------------------------------------
// PTX helpers
// ---------------------------------------------------------------------------
__device__ __forceinline__ uint32_t smem_u32(const void* p) {
    uint32_t a;
    asm("{ .reg .u64 t; cvta.to.shared.u64 t, %1; cvt.u32.u64 %0, t; }" : "=r"(a) : "l"(p));
    return a;
}
__device__ __forceinline__ void ldsm_x4(uint32_t* r, uint32_t addr) {
    asm("ldmatrix.sync.aligned.m8n8.x4.shared.b16 {%0,%1,%2,%3}, [%4];"
        : "=r"(r[0]), "=r"(r[1]), "=r"(r[2]), "=r"(r[3]) : "r"(addr) : "memory");
}
__device__ __forceinline__ void mma16816(float* d, const uint32_t* a, const uint32_t* b) {
    asm("mma.sync.aligned.m16n8k16.row.col.f32.bf16.bf16.f32 "
        "{%0,%1,%2,%3}, {%4,%5,%6,%7}, {%8,%9}, {%0,%1,%2,%3};"
        : "+f"(d[0]), "+f"(d[1]), "+f"(d[2]), "+f"(d[3])
        : "r"(a[0]), "r"(a[1]), "r"(a[2]), "r"(a[3]), "r"(b[0]), "r"(b[1]));
}
__device__ __forceinline__ void cp16(uint32_t dst, const void* src) {
    asm volatile("cp.async.cg.shared.global [%0], [%1], 16;" :: "r"(dst), "l"(src) : "memory");
}
__device__ __forceinline__ void cp4(uint32_t dst, const void* src) {
    asm volatile("cp.async.ca.shared.global [%0], [%1], 4;" :: "r"(dst), "l"(src) : "memory");
}
__device__ __forceinline__ void cp_commit() {
    asm volatile("cp.async.commit_group;" ::: "memory");
}
__device__ __forceinline__ void cp_wait0() {
    asm volatile("cp.async.wait_group 0;" ::: "memory");
}
__device__ __forceinline__ void cp_wait1() {
    asm volatile("cp.async.wait_group 1;" ::: "memory");
}
__device__ __forceinline__ void bar_named(int id, int nthreads) {
    asm volatile("bar.sync %0, %1;" :: "r"(id), "r"(nthreads) : "memory");
}

// ---------------------------------------------------------------------------
// Kernel A (fused): sem = alpha*(wv@W^T + b) + (1-alpha)*x,  PLUS:
//   sem -> output, hi/lo split of (-2*sem) -> g_semB, x -> g_xB, row norms.
// K=300 double-buffered via cp.async; 64 rows x 128 cols per CTA.  (R8 ver.)
// ---------------------------------------------------------------------------
#define FC_ROWS   64
#define FC_KC     50
#define WT_PITCH  132
#define WV_PITCH  68
#define WT_FLOATS (FC_KC * WT_PITCH)
#define WV_FLOATS (FC_KC * WV_PITCH)
#define FC_SMEM   (2 * (WT_FLOATS + WV_FLOATS) * 4)   // 80000 B

__global__ __launch_bounds__(256) void fc_mix_fused(
    const float* __restrict__ wv, const float* __restrict__ W,
    const float* __restrict__ b, const float* __restrict__ alpha,
    const float* __restrict__ x, float* __restrict__ sem_out)
{
    extern __shared__ float fsm[];
    float* Wt  = fsm;
    float* wvt = fsm + 2 * WT_FLOATS;

    const int tid  = threadIdx.x;
    const int tx   = tid & 15;
    const int ty   = tid >> 4;
    const int row0 = blockIdx.x * FC_ROWS;
    const int d0   = tx * 8;

    auto stage_chunk = [&](int c, int buf) {
        float* Wd  = Wt  + buf * WT_FLOATS;
        float* wvd = wvt + buf * WV_FLOATS;
        for (int l = tid; l < DDIM * FC_KC; l += 256) {
            int d = l / FC_KC, k = l - d * FC_KC;
            cp4(smem_u32(&Wd[k * WT_PITCH + d]), &W[d * WVDIM + c * FC_KC + k]);
        }
        for (int l = tid; l < FC_ROWS * FC_KC; l += 256) {
            int m = l / FC_KC, k = l - m * FC_KC;
            cp4(smem_u32(&wvd[k * WV_PITCH + m]),
                &wv[(size_t)(row0 + m) * WVDIM + c * FC_KC + k]);
        }
    };

    float acc[4][8];
    #pragma unroll
    for (int i = 0; i < 4; i++)
        #pragma unroll
        for (int j = 0; j < 8; j++) acc[i][j] = 0.f;

    stage_chunk(0, 0);
    cp_commit();

    for (int c = 0; c < WVDIM / FC_KC; c++) {
        const int buf = c & 1;
        cp_wait0();
        __syncthreads();
        if (c + 1 < WVDIM / FC_KC) {
            stage_chunk(c + 1, buf ^ 1);
            cp_commit();
        }
        const float* Wd  = Wt  + buf * WT_FLOATS;
        const float* wvd = wvt + buf * WV_FLOATS;

        #pragma unroll 2
        for (int k = 0; k < FC_KC; k++) {
            float4 wvv = *reinterpret_cast<const float4*>(&wvd[k * WV_PITCH + ty * 4]);
            float4 w0  = *reinterpret_cast<const float4*>(&Wd[k * WT_PITCH + d0]);
            float4 w1  = *reinterpret_cast<const float4*>(&Wd[k * WT_PITCH + d0 + 4]);
            float wm[4] = {wvv.x, wvv.y, wvv.z, wvv.w};
            float wd[8] = {w0.x, w0.y, w0.z, w0.w, w1.x, w1.y, w1.z, w1.w};
            #pragma unroll
            for (int i = 0; i < 4; i++)
                #pragma unroll
                for (int j = 0; j < 8; j++)
                    acc[i][j] = fmaf(wm[i], wd[j], acc[i][j]);
        }
    }

    float bd[8];
    #pragma unroll
    for (int j = 0; j < 8; j++) bd[j] = b[d0 + j];

    #pragma unroll
    for (int i = 0; i < 4; i++) {
        const int row = row0 + ty * 4 + i;
        const float al = alpha[row];
        float4 xa = reinterpret_cast<const float4*>(x)[(size_t)row * 32 + tx * 2];
        float4 xb = reinterpret_cast<const float4*>(x)[(size_t)row * 32 + tx * 2 + 1];
        float xv[8] = {xa.x, xa.y, xa.z, xa.w, xb.x, xb.y, xb.z, xb.w};

        float sv[8];
        float pssq = 0.f, pxsq = 0.f;
        #pragma unroll
        for (int j = 0; j < 8; j++) {
            float s = al * (acc[i][j] + bd[j]) + (1.f - al) * xv[j];
            sv[j] = s;
            pssq = fmaf(s, s, pssq);
            pxsq = fmaf(xv[j], xv[j], pxsq);
        }

        float4 o0 = {sv[0], sv[1], sv[2], sv[3]};
        float4 o1 = {sv[4], sv[5], sv[6], sv[7]};
        reinterpret_cast<float4*>(sem_out)[(size_t)row * 32 + tx * 2]     = o0;
        reinterpret_cast<float4*>(sem_out)[(size_t)row * 32 + tx * 2 + 1] = o1;

        __nv_bfloat162 sh[4], sl[4], xh[4], xl[4];
        #pragma unroll
        for (int j2 = 0; j2 < 4; j2++) {
            float a0 = -2.f * sv[2*j2], a1 = -2.f * sv[2*j2+1];
            __nv_bfloat16 h0 = __float2bfloat16(a0), h1 = __float2bfloat16(a1);
            sh[j2] = __nv_bfloat162(h0, h1);
            sl[j2] = __nv_bfloat162(__float2bfloat16(a0 - __bfloat162float(h0)),
                                    __float2bfloat16(a1 - __bfloat162float(h1)));
            float b0 = xv[2*j2], b1 = xv[2*j2+1];
            __nv_bfloat16 g0 = __float2bfloat16(b0), g1 = __float2bfloat16(b1);
            xh[j2] = __nv_bfloat162(g0, g1);
            xl[j2] = __nv_bfloat162(__float2bfloat16(b0 - __bfloat162float(g0)),
                                    __float2bfloat16(b1 - __bfloat162float(g1)));
        }
        uint4* semB4 = reinterpret_cast<uint4*>(g_semB + (size_t)row * 256);
        uint4* xB4   = reinterpret_cast<uint4*>(g_xB   + (size_t)row * 256);
        semB4[tx]      = *reinterpret_cast<uint4*>(sh);
        semB4[16 + tx] = *reinterpret_cast<uint4*>(sl);
        xB4[tx]        = *reinterpret_cast<uint4*>(xh);
        xB4[16 + tx]   = *reinterpret_cast<uint4*>(xl);

        #pragma unroll
        for (int o = 1; o <= 8; o <<= 1) {
            pssq += __shfl_xor_sync(0xFFFFFFFFu, pssq, o);
            pxsq += __shfl_xor_sync(0xFFFFFFFFu, pxsq, o);
        }
        if (tx == 0) {
            g_ssq[row] = pssq;
            g_xsq[row] = pxsq;
        }
    }
}

// ---------------------------------------------------------------------------
// Kernel B: persistent distance + batch-hard mining, PAIR-DECOUPLED.
// 128 CTAs; CTA = 64-row m-strip, 64 n-tiles of 128 cols.
// A-fragments (all K) in registers.  B is staged per wn-PAIR: the two warps
// (wm=0,1) sharing an n-slab cooperatively cp.async their own 32-col slab
// into a pair-private double-buffered 16KB region and sync via a named
// 64-thread barrier.  NO CTA-wide __syncthreads in the tile loop -> the 4
// pairs drift out of phase; one pair's LDSM/mining overlaps another's MMAs.
// ---------------------------------------------------------------------------
#define A_BYTES    32768
#define SLAB       16384                    // 32 rows x 512 B
#define PAIR_BYTES (2 * SLAB)
#define DIST_DSMEM (A_BYTES + 4 * PAIR_BYTES)   // 163840

#define NSTEPS 64

__global__ __launch_bounds__(256) void dist_persist(
    const int* __restrict__ label, float* __restrict__ diff_out)
{
    extern __shared__ char dyn[];
    __shared__ float aggF[4 * 64];
    __shared__ float aggC[4 * 64];

    const int tid  = threadIdx.x;
    const int wid  = tid >> 5;
    const int lane = tid & 31;
    const int rowbase = blockIdx.x * 64;

    // ---- stage A strip (64 rows x 32 chunks), swizzled ----
    {
        const uint4* gA = reinterpret_cast<const uint4*>(g_semB) + (size_t)rowbase * 32;
        #pragma unroll
        for (int it = 0; it < 8; it++) {
            int idx = it * 256 + tid;
            int r = idx >> 5, cch = idx & 31;
            uint32_t off = (uint32_t)(r * 512 + ((cch ^ (r & 7)) << 4));
            *reinterpret_cast<uint4*>(dyn + off) = gA[(size_t)r * 32 + cch];
        }
    }
    __syncthreads();

    const uint32_t AsU = smem_u32(dyn);

    const int wm = wid & 1;            // 2 m-slabs of 32
    const int wn = wid >> 1;           // 4 n-slabs of 32 (= pair id)
    const int m_base = wm * 32;
    const int n_base = wn * 32;
    const int pt     = wm * 32 + lane; // pair-local thread 0..63
    const int barid  = 1 + wn;         // named barrier per pair

    const uint32_t pairU = AsU + A_BYTES + wn * PAIR_BYTES;

    // ---- preload ALL A fragments into registers ----
    uint32_t aF[8][2][2][4];           // [kstep][half][mt][4]
    {
        const uint32_t a_chunk_add = (uint32_t)(lane >> 4);
        #pragma unroll
        for (int mt = 0; mt < 2; mt++) {
            int r = m_base + mt * 16 + (lane & 15);
            uint32_t base = AsU + r * 512;
            uint32_t sw   = (uint32_t)(r & 7);
            #pragma unroll
            for (int s = 0; s < 8; s++) {
                #pragma unroll
                for (int h = 0; h < 2; h++) {
                    uint32_t ch = (uint32_t)(h * 16 + s * 2) + a_chunk_add;
                    ldsm_x4(aF[s][h][mt], base + ((ch ^ sw) << 4));
                }
            }
        }
    }

    // B ldsm addressing within a 32-row slab
    uint32_t b_off[2], b_sw[2];
    #pragma unroll
    for (int p = 0; p < 2; p++) {
        int r = p * 16 + ((lane >> 4) << 3) + (lane & 7);   // 0..31 local
        b_off[p] = pairU + r * 512;
        b_sw[p]  = (uint32_t)(r & 7);
    }
    const uint32_t b_chunk_add = (uint32_t)((lane >> 3) & 1);

    // per-thread row info
    const int q  = lane >> 2;
    const int qt = lane & 3;
    int row_gi[2][2];
    int lmv[2][2];
    #pragma unroll
    for (int mt = 0; mt < 2; mt++)
        #pragma unroll
        for (int hr = 0; hr < 2; hr++) {
            row_gi[mt][hr] = rowbase + m_base + mt * 16 + hr * 8 + q;
            lmv[mt][hr]    = label[row_gi[mt][hr]];
        }

    float fpU[2][2], cnU[2][2];
    #pragma unroll
    for (int mt = 0; mt < 2; mt++)
        #pragma unroll
        for (int hr = 0; hr < 2; hr++) { fpU[mt][hr] = NEGINF; cnU[mt][hr] = POSINF; }

    // ---- pair-private slab staging: 32 rows x 32 chunks, 64 threads ----
    auto stage_slab = [&](int t, int buf) {
        const char* gB = reinterpret_cast<const char*>(g_xB)
                       + (size_t)(t * 128 + n_base) * 512;
        uint32_t bb = pairU + buf * SLAB;
        #pragma unroll
        for (int it = 0; it < 16; it++) {
            int idx = it * 64 + pt;          // 0..1023
            int r = idx >> 5, cch = idx & 31;
            uint32_t dst = bb + (uint32_t)(r * 512 + ((cch ^ (r & 7)) << 4));
            cp16(dst, gB + (size_t)r * 512 + cch * 16);
        }
    };

    const int t_diag = (int)(blockIdx.x >> 1);   // tile containing this strip's rows

    stage_slab(0, 0);
    cp_commit();

    for (int t = 0; t < NSTEPS; t++) {
        const int buf = t & 1;
        const int n0  = t * 128;

        if (t + 1 < NSTEPS) {
            stage_slab(t + 1, buf ^ 1);
            cp_commit();
            cp_wait1();                  // tile t's group complete (mine)
        } else {
            cp_wait0();
        }
        bar_named(barid, 64);            // pair-wide visibility of tile t

        // mining metadata (L1-hot LDG)
        float xq[8]; int lb[8];
        #pragma unroll
        for (int k = 0; k < 8; k++) {
            int cl = n0 + n_base + (k >> 1) * 8 + qt * 2 + (k & 1);
            xq[k] = g_xsq[cl];
            lb[k] = label[cl];
        }

        float c[2][4][4];
        #pragma unroll
        for (int mt = 0; mt < 2; mt++)
            #pragma unroll
            for (int nt = 0; nt < 4; nt++)
                #pragma unroll
                for (int e = 0; e < 4; e++) c[mt][nt][e] = 0.f;

        const uint32_t bufAdd = (uint32_t)(buf * SLAB);
        #pragma unroll
        for (int s = 0; s < 8; s++) {
            uint32_t bfr[2][2][4];       // [half][pair][4]
            #pragma unroll
            for (int h = 0; h < 2; h++) {
                uint32_t chB = (uint32_t)(h * 16 + s * 2) + b_chunk_add;
                #pragma unroll
                for (int p = 0; p < 2; p++)
                    ldsm_x4(bfr[h][p], b_off[p] + bufAdd + ((chB ^ b_sw[p]) << 4));
            }
            #pragma unroll
            for (int mt = 0; mt < 2; mt++) {
                #pragma unroll
                for (int nt = 0; nt < 4; nt++) {
                    const uint32_t* bh = &bfr[0][nt >> 1][(nt & 1) * 2];
                    const uint32_t* bl = &bfr[1][nt >> 1][(nt & 1) * 2];
                    mma16816(c[mt][nt], aF[s][0][mt], bh);   // hi*hi
                    mma16816(c[mt][nt], aF[s][0][mt], bl);   // hi*lo
                    mma16816(c[mt][nt], aF[s][1][mt], bh);   // lo*hi
                }
            }
        }

        // ---- mining on u = xsq[col] + (-2 sem.x) ----
        if (t == t_diag) {
            #pragma unroll
            for (int mt = 0; mt < 2; mt++) {
                #pragma unroll
                for (int hr = 0; hr < 2; hr++) {
                    const int gi = row_gi[mt][hr];
                    const int lm = lmv[mt][hr];
                    float fb = fpU[mt][hr], cb = cnU[mt][hr];
                    #pragma unroll
                    for (int nt = 0; nt < 4; nt++) {
                        #pragma unroll
                        for (int w = 0; w < 2; w++) {
                            int k  = nt * 2 + w;
                            int cl = n0 + n_base + nt * 8 + qt * 2 + w;
                            float u = xq[k] + c[mt][nt][hr * 2 + w];
                            bool same = (lm == lb[k]);
                            bool self = (cl == gi);
                            fb = fmaxf(fb, (same && !self) ? u : NEGINF);
                            cb = fminf(cb, same ? POSINF : u);
                        }
                    }
                    fpU[mt][hr] = fb;
                    cnU[mt][hr] = cb;
                }
            }
        } else {
            #pragma unroll
            for (int mt = 0; mt < 2; mt++) {
                #pragma unroll
                for (int hr = 0; hr < 2; hr++) {
                    const int lm = lmv[mt][hr];
                    float fb = fpU[mt][hr], cb = cnU[mt][hr];
                    #pragma unroll
                    for (int nt = 0; nt < 4; nt++) {
                        #pragma unroll
                        for (int w = 0; w < 2; w++) {
                            int k = nt * 2 + w;
                            float u = xq[k] + c[mt][nt][hr * 2 + w];
                            bool same = (lm == lb[k]);
                            fb = fmaxf(fb, same ? u : NEGINF);
                            cb = fminf(cb, same ? POSINF : u);
                        }
                    }
                    fpU[mt][hr] = fb;
                    cnU[mt][hr] = cb;
                }
            }
        }

        bar_named(barid, 64);            // pair done reading buf before reuse
    }

    // ---- final reduction: quad lanes -> smem across wn warps -> softplus ----
    #pragma unroll
    for (int mt = 0; mt < 2; mt++) {
        #pragma unroll
        for (int hr = 0; hr < 2; hr++) {
            float fb = fpU[mt][hr], cb = cnU[mt][hr];
            #pragma unroll
            for (int o = 1; o <= 2; o <<= 1) {
                fb = fmaxf(fb, __shfl_xor_sync(0xFFFFFFFFu, fb, o));
                cb = fminf(cb, __shfl_xor_sync(0xFFFFFFFFu, cb, o));
            }
            if (qt == 0) {
                int r = m_base + mt * 16 + hr * 8 + q;
                aggF[wn * 64 + r] = fb;
                aggC[wn * 64 + r] = cb;
            }
        }
    }
    __syncthreads();

    if (tid < 64) {
        float fb = NEGINF, cb = POSINF;
        #pragma unroll
        for (int wnn = 0; wnn < 4; wnn++) {
            fb = fmaxf(fb, aggF[wnn * 64 + tid]);
            cb = fminf(cb, aggC[wnn * 64 + tid]);
        }
        float ssqm = g_ssq[rowbase + tid];
        float fp = (fb < -1e37f) ? 0.f : sqrtf(fmaxf(ssqm + fb, 0.f) + DEPS);
        float cn = sqrtf(fmaxf(ssqm + cb, 0.f) + DEPS);
        float z = fp - cn;
        diff_out[rowbase + tid] = fmaxf(z, 0.f) + log1pf(expf(-fabsf(z)));
    }
}

// ---------------------------------------------------------------------------
// Launch
// Inputs: x[N,128] f32, wv[N,300] f32, label[N] i32, alpha[N,1] f32,
//         W[128,300] f32, b[128] f32
// Output: diff[N] then sem[N,128] (float32, concatenated)
// ---------------------------------------------------------------------------
extern "C" void kernel_launch(void* const* d_in, const int* in_sizes, int n_in,
                              void* d_out, int out_size)
{
    const float* x     = (const float*)d_in[0];
    const float* wv    = (const float*)d_in[1];
    const int*   label = (const int*)  d_in[2];
    const float* alpha = (const float*)d_in[3];
    const float* W     = (const float*)d_in[4];
    const float* b     = (const float*)d_in[5];

    float* out  = (float*)d_out;
    float* diff = out;            // [N]
    float* sem  = out + NROWS;    // [N, 128]

    static bool attr_set = false;
    if (!attr_set) {
        cudaFuncSetAttribute(dist_persist,
                             cudaFuncAttributeMaxDynamicSharedMemorySize, DIST_DSMEM);
        cudaFuncSetAttribute(fc_mix_fused,
                             cudaFuncAttributeMaxDynamicSharedMemorySize, FC_SMEM);
        attr_set = true;
    }

    fc_mix_fused<<<NROWS / FC_ROWS, 256, FC_SMEM>>>(wv, W, b, alpha, x, sem);
    dist_persist<<<NROWS / 64, 256, DIST_DSMEM>>>(label, diff);
}

// round 11
// speedup vs baseline: 3.7058x; 1.2862x over previous
#include <cuda_runtime.h>
#include <cuda_fp16.h>
#include <math.h>
#include <stdint.h>

// Problem constants
#define NROWS 8192
#define DDIM  128
#define WVDIM 300
#define BIGF  1e8f
#define DEPS  1.28e-14f   // D * 1e-16
#define NEGINF -3.4e38f
#define POSINF  3.4e38f

// ---------------------------------------------------------------------------
// Scratch (__device__ globals; no allocation allowed)
// ---------------------------------------------------------------------------
__device__ float g_ssq[NROWS];
__device__ float g_xsq[NROWS];
// A side: fp16 hi/lo split of (-2*sem), row-major [row][0:128]=hi,[128:256]=lo
// (512 B/row, chunks 0..15 = hi, 16..31 = lo)
__device__ __half g_semA[NROWS * 256];
// B side: fp16 hi of x only, row-major (256 B/row, 16 chunks)
__device__ __half g_xH[NROWS * 128];

// ---------------------------------------------------------------------------
// PTX helpers
// ---------------------------------------------------------------------------
__device__ __forceinline__ uint32_t smem_u32(const void* p) {
    uint32_t a;
    asm("{ .reg .u64 t; cvta.to.shared.u64 t, %1; cvt.u32.u64 %0, t; }" : "=r"(a) : "l"(p));
    return a;
}
__device__ __forceinline__ void ldsm_x4(uint32_t* r, uint32_t addr) {
    asm("ldmatrix.sync.aligned.m8n8.x4.shared.b16 {%0,%1,%2,%3}, [%4];"
        : "=r"(r[0]), "=r"(r[1]), "=r"(r[2]), "=r"(r[3]) : "r"(addr) : "memory");
}
__device__ __forceinline__ void mma16816h(float* d, const uint32_t* a, const uint32_t* b) {
    asm("mma.sync.aligned.m16n8k16.row.col.f32.f16.f16.f32 "
        "{%0,%1,%2,%3}, {%4,%5,%6,%7}, {%8,%9}, {%0,%1,%2,%3};"
        : "+f"(d[0]), "+f"(d[1]), "+f"(d[2]), "+f"(d[3])
        : "r"(a[0]), "r"(a[1]), "r"(a[2]), "r"(a[3]), "r"(b[0]), "r"(b[1]));
}
__device__ __forceinline__ void cp16(uint32_t dst, const void* src) {
    asm volatile("cp.async.cg.shared.global [%0], [%1], 16;" :: "r"(dst), "l"(src) : "memory");
}
__device__ __forceinline__ void cp4(uint32_t dst, const void* src) {
    asm volatile("cp.async.ca.shared.global [%0], [%1], 4;" :: "r"(dst), "l"(src) : "memory");
}
__device__ __forceinline__ void cp_commit() {
    asm volatile("cp.async.commit_group;" ::: "memory");
}
__device__ __forceinline__ void cp_wait0() {
    asm volatile("cp.async.wait_group 0;" ::: "memory");
}
__device__ __forceinline__ void cp_wait1() {
    asm volatile("cp.async.wait_group 1;" ::: "memory");
}
__device__ __forceinline__ void bar_named(int id, int nthreads) {
    asm volatile("bar.sync %0, %1;" :: "r"(id), "r"(nthreads) : "memory");
}

// ---------------------------------------------------------------------------
// Kernel A (fused): sem = alpha*(wv@W^T + b) + (1-alpha)*x,  PLUS:
//   sem -> output, fp16 hi/lo of (-2*sem) -> g_semA, fp16 hi of x -> g_xH,
//   row norms.  (GEMM part identical to R8/R10.)
// ---------------------------------------------------------------------------
#define FC_ROWS   64
#define FC_KC     50
#define WT_PITCH  132
#define WV_PITCH  68
#define WT_FLOATS (FC_KC * WT_PITCH)
#define WV_FLOATS (FC_KC * WV_PITCH)
#define FC_SMEM   (2 * (WT_FLOATS + WV_FLOATS) * 4)   // 80000 B

__global__ __launch_bounds__(256) void fc_mix_fused(
    const float* __restrict__ wv, const float* __restrict__ W,
    const float* __restrict__ b, const float* __restrict__ alpha,
    const float* __restrict__ x, float* __restrict__ sem_out)
{
    extern __shared__ float fsm[];
    float* Wt  = fsm;
    float* wvt = fsm + 2 * WT_FLOATS;

    const int tid  = threadIdx.x;
    const int tx   = tid & 15;
    const int ty   = tid >> 4;
    const int row0 = blockIdx.x * FC_ROWS;
    const int d0   = tx * 8;

    auto stage_chunk = [&](int c, int buf) {
        float* Wd  = Wt  + buf * WT_FLOATS;
        float* wvd = wvt + buf * WV_FLOATS;
        for (int l = tid; l < DDIM * FC_KC; l += 256) {
            int d = l / FC_KC, k = l - d * FC_KC;
            cp4(smem_u32(&Wd[k * WT_PITCH + d]), &W[d * WVDIM + c * FC_KC + k]);
        }
        for (int l = tid; l < FC_ROWS * FC_KC; l += 256) {
            int m = l / FC_KC, k = l - m * FC_KC;
            cp4(smem_u32(&wvd[k * WV_PITCH + m]),
                &wv[(size_t)(row0 + m) * WVDIM + c * FC_KC + k]);
        }
    };

    float acc[4][8];
    #pragma unroll
    for (int i = 0; i < 4; i++)
        #pragma unroll
        for (int j = 0; j < 8; j++) acc[i][j] = 0.f;

    stage_chunk(0, 0);
    cp_commit();

    for (int c = 0; c < WVDIM / FC_KC; c++) {
        const int buf = c & 1;
        cp_wait0();
        __syncthreads();
        if (c + 1 < WVDIM / FC_KC) {
            stage_chunk(c + 1, buf ^ 1);
            cp_commit();
        }
        const float* Wd  = Wt  + buf * WT_FLOATS;
        const float* wvd = wvt + buf * WV_FLOATS;

        #pragma unroll 2
        for (int k = 0; k < FC_KC; k++) {
            float4 wvv = *reinterpret_cast<const float4*>(&wvd[k * WV_PITCH + ty * 4]);
            float4 w0  = *reinterpret_cast<const float4*>(&Wd[k * WT_PITCH + d0]);
            float4 w1  = *reinterpret_cast<const float4*>(&Wd[k * WT_PITCH + d0 + 4]);
            float wm[4] = {wvv.x, wvv.y, wvv.z, wvv.w};
            float wd[8] = {w0.x, w0.y, w0.z, w0.w, w1.x, w1.y, w1.z, w1.w};
            #pragma unroll
            for (int i = 0; i < 4; i++)
                #pragma unroll
                for (int j = 0; j < 8; j++)
                    acc[i][j] = fmaf(wm[i], wd[j], acc[i][j]);
        }
    }

    float bd[8];
    #pragma unroll
    for (int j = 0; j < 8; j++) bd[j] = b[d0 + j];

    #pragma unroll
    for (int i = 0; i < 4; i++) {
        const int row = row0 + ty * 4 + i;
        const float al = alpha[row];
        float4 xa = reinterpret_cast<const float4*>(x)[(size_t)row * 32 + tx * 2];
        float4 xb = reinterpret_cast<const float4*>(x)[(size_t)row * 32 + tx * 2 + 1];
        float xv[8] = {xa.x, xa.y, xa.z, xa.w, xb.x, xb.y, xb.z, xb.w};

        float sv[8];
        float pssq = 0.f, pxsq = 0.f;
        #pragma unroll
        for (int j = 0; j < 8; j++) {
            float s = al * (acc[i][j] + bd[j]) + (1.f - al) * xv[j];
            sv[j] = s;
            pssq = fmaf(s, s, pssq);
            pxsq = fmaf(xv[j], xv[j], pxsq);
        }

        float4 o0 = {sv[0], sv[1], sv[2], sv[3]};
        float4 o1 = {sv[4], sv[5], sv[6], sv[7]};
        reinterpret_cast<float4*>(sem_out)[(size_t)row * 32 + tx * 2]     = o0;
        reinterpret_cast<float4*>(sem_out)[(size_t)row * 32 + tx * 2 + 1] = o1;

        // A side: fp16 hi/lo split of (-2*sem)
        __half2 sh[4], sl[4], xh[4];
        #pragma unroll
        for (int j2 = 0; j2 < 4; j2++) {
            float a0 = -2.f * sv[2*j2], a1 = -2.f * sv[2*j2+1];
            __half h0 = __float2half(a0), h1 = __float2half(a1);
            sh[j2] = __halves2half2(h0, h1);
            sl[j2] = __halves2half2(__float2half(a0 - __half2float(h0)),
                                    __float2half(a1 - __half2float(h1)));
            xh[j2] = __halves2half2(__float2half(xv[2*j2]),
                                    __float2half(xv[2*j2+1]));
        }
        uint4* semA4 = reinterpret_cast<uint4*>(g_semA + (size_t)row * 256);
        semA4[tx]      = *reinterpret_cast<uint4*>(sh);   // hi chunks 0..15
        semA4[16 + tx] = *reinterpret_cast<uint4*>(sl);   // lo chunks 16..31
        reinterpret_cast<uint4*>(g_xH + (size_t)row * 128)[tx] =
            *reinterpret_cast<uint4*>(xh);

        #pragma unroll
        for (int o = 1; o <= 8; o <<= 1) {
            pssq += __shfl_xor_sync(0xFFFFFFFFu, pssq, o);
            pxsq += __shfl_xor_sync(0xFFFFFFFFu, pxsq, o);
        }
        if (tx == 0) {
            g_ssq[row] = pssq;
            g_xsq[row] = pxsq;
        }
    }
}

// ---------------------------------------------------------------------------
// Kernel B: persistent distance + batch-hard mining, pair-decoupled (R10),
// now fp16 2-term: dot = Ah*Bh + Al*Bh  (B = fp16(x) only -> half the B
// traffic: 8KB slabs, 2 ldsm/warp/kstep, 16 MMAs/warp/kstep).
// ---------------------------------------------------------------------------
#define A_BYTES    32768                    // 64 rows x 512 B (hi|lo)
#define SLAB       8192                     // 32 rows x 256 B (hi only)
#define PAIR_BYTES (2 * SLAB)
#define DIST_DSMEM (A_BYTES + 4 * PAIR_BYTES)   // 98304

#define NSTEPS 64

__global__ __launch_bounds__(256) void dist_persist(
    const int* __restrict__ label, float* __restrict__ diff_out)
{
    extern __shared__ char dyn[];
    __shared__ float aggF[4 * 64];
    __shared__ float aggC[4 * 64];

    const int tid  = threadIdx.x;
    const int wid  = tid >> 5;
    const int lane = tid & 31;
    const int rowbase = blockIdx.x * 64;

    // ---- stage A strip (64 rows x 32 chunks of 16B), swizzled ----
    {
        const uint4* gA = reinterpret_cast<const uint4*>(g_semA) + (size_t)rowbase * 32;
        #pragma unroll
        for (int it = 0; it < 8; it++) {
            int idx = it * 256 + tid;
            int r = idx >> 5, cch = idx & 31;
            uint32_t off = (uint32_t)(r * 512 + ((cch ^ (r & 7)) << 4));
            *reinterpret_cast<uint4*>(dyn + off) = gA[(size_t)r * 32 + cch];
        }
    }
    __syncthreads();

    const uint32_t AsU = smem_u32(dyn);

    const int wm = wid & 1;            // 2 m-slabs of 32
    const int wn = wid >> 1;           // 4 n-slabs of 32 (= pair id)
    const int m_base = wm * 32;
    const int n_base = wn * 32;
    const int pt     = wm * 32 + lane; // pair-local thread 0..63
    const int barid  = 1 + wn;

    const uint32_t pairU = AsU + A_BYTES + wn * PAIR_BYTES;

    // ---- preload ALL A fragments (hi+lo) into registers ----
    uint32_t aF[8][2][2][4];           // [kstep][half][mt][4]
    {
        const uint32_t a_chunk_add = (uint32_t)(lane >> 4);
        #pragma unroll
        for (int mt = 0; mt < 2; mt++) {
            int r = m_base + mt * 16 + (lane & 15);
            uint32_t base = AsU + r * 512;
            uint32_t sw   = (uint32_t)(r & 7);
            #pragma unroll
            for (int s = 0; s < 8; s++) {
                #pragma unroll
                for (int h = 0; h < 2; h++) {
                    uint32_t ch = (uint32_t)(h * 16 + s * 2) + a_chunk_add;
                    ldsm_x4(aF[s][h][mt], base + ((ch ^ sw) << 4));
                }
            }
        }
    }

    // B ldsm addressing within a 32-row x 256B slab (16 chunks, key r&7)
    uint32_t b_off[2], b_sw[2];
    #pragma unroll
    for (int p = 0; p < 2; p++) {
        int r = p * 16 + ((lane >> 4) << 3) + (lane & 7);   // 0..31 local
        b_off[p] = pairU + r * 256;
        b_sw[p]  = (uint32_t)(r & 7);
    }
    const uint32_t b_chunk_add = (uint32_t)((lane >> 3) & 1);

    // per-thread row info
    const int q  = lane >> 2;
    const int qt = lane & 3;
    int row_gi[2][2];
    int lmv[2][2];
    #pragma unroll
    for (int mt = 0; mt < 2; mt++)
        #pragma unroll
        for (int hr = 0; hr < 2; hr++) {
            row_gi[mt][hr] = rowbase + m_base + mt * 16 + hr * 8 + q;
            lmv[mt][hr]    = label[row_gi[mt][hr]];
        }

    float fpU[2][2], cnU[2][2];
    #pragma unroll
    for (int mt = 0; mt < 2; mt++)
        #pragma unroll
        for (int hr = 0; hr < 2; hr++) { fpU[mt][hr] = NEGINF; cnU[mt][hr] = POSINF; }

    // ---- pair-private slab staging: 32 rows x 16 chunks, 64 threads ----
    auto stage_slab = [&](int t, int buf) {
        const char* gB = reinterpret_cast<const char*>(g_xH)
                       + (size_t)(t * 128 + n_base) * 256;
        uint32_t bb = pairU + buf * SLAB;
        #pragma unroll
        for (int it = 0; it < 8; it++) {
            int idx = it * 64 + pt;          // 0..511
            int r = idx >> 4, cch = idx & 15;
            uint32_t dst = bb + (uint32_t)(r * 256 + ((cch ^ (r & 7)) << 4));
            cp16(dst, gB + (size_t)r * 256 + cch * 16);
        }
    };

    const int t_diag = (int)(blockIdx.x >> 1);

    stage_slab(0, 0);
    cp_commit();

    for (int t = 0; t < NSTEPS; t++) {
        const int buf = t & 1;
        const int n0  = t * 128;

        if (t + 1 < NSTEPS) {
            stage_slab(t + 1, buf ^ 1);
            cp_commit();
            cp_wait1();
        } else {
            cp_wait0();
        }
        bar_named(barid, 64);

        // mining metadata (L1-hot LDG)
        float xq[8]; int lb[8];
        #pragma unroll
        for (int k = 0; k < 8; k++) {
            int cl = n0 + n_base + (k >> 1) * 8 + qt * 2 + (k & 1);
            xq[k] = g_xsq[cl];
            lb[k] = label[cl];
        }

        float c[2][4][4];
        #pragma unroll
        for (int mt = 0; mt < 2; mt++)
            #pragma unroll
            for (int nt = 0; nt < 4; nt++)
                #pragma unroll
                for (int e = 0; e < 4; e++) c[mt][nt][e] = 0.f;

        const uint32_t bufAdd = (uint32_t)(buf * SLAB);
        #pragma unroll
        for (int s = 0; s < 8; s++) {
            uint32_t bfr[2][4];          // [pair][4] : Bh fragments only
            uint32_t chB = (uint32_t)(s * 2) + b_chunk_add;
            #pragma unroll
            for (int p = 0; p < 2; p++)
                ldsm_x4(bfr[p], b_off[p] + bufAdd + ((chB ^ b_sw[p]) << 4));

            #pragma unroll
            for (int mt = 0; mt < 2; mt++) {
                #pragma unroll
                for (int nt = 0; nt < 4; nt++) {
                    const uint32_t* bh = &bfr[nt >> 1][(nt & 1) * 2];
                    mma16816h(c[mt][nt], aF[s][0][mt], bh);   // Ah*Bh
                    mma16816h(c[mt][nt], aF[s][1][mt], bh);   // Al*Bh
                }
            }
        }

        // ---- mining on u = xsq[col] + (-2 sem.x) ----
        if (t == t_diag) {
            #pragma unroll
            for (int mt = 0; mt < 2; mt++) {
                #pragma unroll
                for (int hr = 0; hr < 2; hr++) {
                    const int gi = row_gi[mt][hr];
                    const int lm = lmv[mt][hr];
                    float fb = fpU[mt][hr], cb = cnU[mt][hr];
                    #pragma unroll
                    for (int nt = 0; nt < 4; nt++) {
                        #pragma unroll
                        for (int w = 0; w < 2; w++) {
                            int k  = nt * 2 + w;
                            int cl = n0 + n_base + nt * 8 + qt * 2 + w;
                            float u = xq[k] + c[mt][nt][hr * 2 + w];
                            bool same = (lm == lb[k]);
                            bool self = (cl == gi);
                            fb = fmaxf(fb, (same && !self) ? u : NEGINF);
                            cb = fminf(cb, same ? POSINF : u);
                        }
                    }
                    fpU[mt][hr] = fb;
                    cnU[mt][hr] = cb;
                }
            }
        } else {
            #pragma unroll
            for (int mt = 0; mt < 2; mt++) {
                #pragma unroll
                for (int hr = 0; hr < 2; hr++) {
                    const int lm = lmv[mt][hr];
                    float fb = fpU[mt][hr], cb = cnU[mt][hr];
                    #pragma unroll
                    for (int nt = 0; nt < 4; nt++) {
                        #pragma unroll
                        for (int w = 0; w < 2; w++) {
                            int k = nt * 2 + w;
                            float u = xq[k] + c[mt][nt][hr * 2 + w];
                            bool same = (lm == lb[k]);
                            fb = fmaxf(fb, same ? u : NEGINF);
                            cb = fminf(cb, same ? POSINF : u);
                        }
                    }
                    fpU[mt][hr] = fb;
                    cnU[mt][hr] = cb;
                }
            }
        }

        bar_named(barid, 64);
    }

    // ---- final reduction: quad lanes -> smem across wn warps -> softplus ----
    #pragma unroll
    for (int mt = 0; mt < 2; mt++) {
        #pragma unroll
        for (int hr = 0; hr < 2; hr++) {
            float fb = fpU[mt][hr], cb = cnU[mt][hr];
            #pragma unroll
            for (int o = 1; o <= 2; o <<= 1) {
                fb = fmaxf(fb, __shfl_xor_sync(0xFFFFFFFFu, fb, o));
                cb = fminf(cb, __shfl_xor_sync(0xFFFFFFFFu, cb, o));
            }
            if (qt == 0) {
                int r = m_base + mt * 16 + hr * 8 + q;
                aggF[wn * 64 + r] = fb;
                aggC[wn * 64 + r] = cb;
            }
        }
    }
    __syncthreads();

    if (tid < 64) {
        float fb = NEGINF, cb = POSINF;
        #pragma unroll
        for (int wnn = 0; wnn < 4; wnn++) {
            fb = fmaxf(fb, aggF[wnn * 64 + tid]);
            cb = fminf(cb, aggC[wnn * 64 + tid]);
        }
        float ssqm = g_ssq[rowbase + tid];
        float fp = (fb < -1e37f) ? 0.f : sqrtf(fmaxf(ssqm + fb, 0.f) + DEPS);
        float cn = sqrtf(fmaxf(ssqm + cb, 0.f) + DEPS);
        float z = fp - cn;
        diff_out[rowbase + tid] = fmaxf(z, 0.f) + log1pf(expf(-fabsf(z)));
    }
}

// ---------------------------------------------------------------------------
// Launch
// Inputs: x[N,128] f32, wv[N,300] f32, label[N] i32, alpha[N,1] f32,
//         W[128,300] f32, b[128] f32
// Output: diff[N] then sem[N,128] (float32, concatenated)
// ---------------------------------------------------------------------------
extern "C" void kernel_launch(void* const* d_in, const int* in_sizes, int n_in,
                              void* d_out, int out_size)
{
    const float* x     = (const float*)d_in[0];
    const float* wv    = (const float*)d_in[1];
    const int*   label = (const int*)  d_in[2];
    const float* alpha = (const float*)d_in[3];
    const float* W     = (const float*)d_in[4];
    const float* b     = (const float*)d_in[5];

    float* out  = (float*)d_out;
    float* diff = out;            // [N]
    float* sem  = out + NROWS;    // [N, 128]

    static bool attr_set = false;
    if (!attr_set) {
        cudaFuncSetAttribute(dist_persist,
                             cudaFuncAttributeMaxDynamicSharedMemorySize, DIST_DSMEM);
        cudaFuncSetAttribute(fc_mix_fused,
                             cudaFuncAttributeMaxDynamicSharedMemorySize, FC_SMEM);
        attr_set = true;
    }

    fc_mix_fused<<<NROWS / FC_ROWS, 256, FC_SMEM>>>(wv, W, b, alpha, x, sem);
    dist_persist<<<NROWS / 64, 256, DIST_DSMEM>>>(label, diff);
}

// round 12
// speedup vs baseline: 4.0469x; 1.0920x over previous
#include <cuda_runtime.h>
#include <cuda_fp16.h>
#include <math.h>
#include <stdint.h>

// Problem constants
#define NROWS 8192
#define DDIM  128
#define WVDIM 300
#define BIGF  1e8f
#define DEPS  1.28e-14f   // D * 1e-16
#define NEGINF -3.4e38f
#define POSINF  3.4e38f

// ---------------------------------------------------------------------------
// Scratch (__device__ globals; no allocation allowed)
// ---------------------------------------------------------------------------
__device__ float g_ssq[NROWS];
__device__ float g_xsq[NROWS];
// A side: fp16 of (-2*sem), row-major, 256 B/row (16 chunks of 16B)
__device__ __half g_semA[NROWS * 128];
// B side: fp16 of x, row-major, 256 B/row
__device__ __half g_xH[NROWS * 128];

// ---------------------------------------------------------------------------
// PTX helpers
// ---------------------------------------------------------------------------
__device__ __forceinline__ uint32_t smem_u32(const void* p) {
    uint32_t a;
    asm("{ .reg .u64 t; cvta.to.shared.u64 t, %1; cvt.u32.u64 %0, t; }" : "=r"(a) : "l"(p));
    return a;
}
__device__ __forceinline__ void ldsm_x4(uint32_t* r, uint32_t addr) {
    asm("ldmatrix.sync.aligned.m8n8.x4.shared.b16 {%0,%1,%2,%3}, [%4];"
        : "=r"(r[0]), "=r"(r[1]), "=r"(r[2]), "=r"(r[3]) : "r"(addr) : "memory");
}
__device__ __forceinline__ void mma16816h(float* d, const uint32_t* a, const uint32_t* b) {
    asm("mma.sync.aligned.m16n8k16.row.col.f32.f16.f16.f32 "
        "{%0,%1,%2,%3}, {%4,%5,%6,%7}, {%8,%9}, {%0,%1,%2,%3};"
        : "+f"(d[0]), "+f"(d[1]), "+f"(d[2]), "+f"(d[3])
        : "r"(a[0]), "r"(a[1]), "r"(a[2]), "r"(a[3]), "r"(b[0]), "r"(b[1]));
}
__device__ __forceinline__ void cp16(uint32_t dst, const void* src) {
    asm volatile("cp.async.cg.shared.global [%0], [%1], 16;" :: "r"(dst), "l"(src) : "memory");
}
__device__ __forceinline__ void cp4(uint32_t dst, const void* src) {
    asm volatile("cp.async.ca.shared.global [%0], [%1], 4;" :: "r"(dst), "l"(src) : "memory");
}
__device__ __forceinline__ void cp_commit() {
    asm volatile("cp.async.commit_group;" ::: "memory");
}
__device__ __forceinline__ void cp_wait0() {
    asm volatile("cp.async.wait_group 0;" ::: "memory");
}
__device__ __forceinline__ void cp_wait1() {
    asm volatile("cp.async.wait_group 1;" ::: "memory");
}
__device__ __forceinline__ void bar_named(int id, int nthreads) {
    asm volatile("bar.sync %0, %1;" :: "r"(id), "r"(nthreads) : "memory");
}

// ---------------------------------------------------------------------------
// Kernel A (fused): sem = alpha*(wv@W^T + b) + (1-alpha)*x,  PLUS:
//   sem -> output, fp16 of (-2*sem) -> g_semA, fp16 of x -> g_xH, row norms.
// FC_ROWS=32 -> 256 CTAs, 66KB smem -> 2 CTAs/SM, all resident in one wave.
// ---------------------------------------------------------------------------
#define FC_ROWS   32
#define FC_KC     50
#define WT_PITCH  132
#define WV_PITCH  36
#define WT_FLOATS (FC_KC * WT_PITCH)   // 6600
#define WV_FLOATS (FC_KC * WV_PITCH)   // 1800
#define FC_SMEM   (2 * (WT_FLOATS + WV_FLOATS) * 4)   // 67200 B

__global__ __launch_bounds__(256) void fc_mix_fused(
    const float* __restrict__ wv, const float* __restrict__ W,
    const float* __restrict__ b, const float* __restrict__ alpha,
    const float* __restrict__ x, float* __restrict__ sem_out)
{
    extern __shared__ float fsm[];
    float* Wt  = fsm;                     // [2][50][132]
    float* wvt = fsm + 2 * WT_FLOATS;     // [2][50][36]

    const int tid  = threadIdx.x;
    const int tx   = tid & 15;
    const int ty   = tid >> 4;
    const int row0 = blockIdx.x * FC_ROWS;
    const int d0   = tx * 8;

    auto stage_chunk = [&](int c, int buf) {
        float* Wd  = Wt  + buf * WT_FLOATS;
        float* wvd = wvt + buf * WV_FLOATS;
        for (int l = tid; l < DDIM * FC_KC; l += 256) {
            int d = l / FC_KC, k = l - d * FC_KC;
            cp4(smem_u32(&Wd[k * WT_PITCH + d]), &W[d * WVDIM + c * FC_KC + k]);
        }
        for (int l = tid; l < FC_ROWS * FC_KC; l += 256) {
            int m = l / FC_KC, k = l - m * FC_KC;
            cp4(smem_u32(&wvd[k * WV_PITCH + m]),
                &wv[(size_t)(row0 + m) * WVDIM + c * FC_KC + k]);
        }
    };

    float acc[2][8];
    #pragma unroll
    for (int i = 0; i < 2; i++)
        #pragma unroll
        for (int j = 0; j < 8; j++) acc[i][j] = 0.f;

    stage_chunk(0, 0);
    cp_commit();

    for (int c = 0; c < WVDIM / FC_KC; c++) {
        const int buf = c & 1;
        cp_wait0();
        __syncthreads();
        if (c + 1 < WVDIM / FC_KC) {
            stage_chunk(c + 1, buf ^ 1);
            cp_commit();
        }
        const float* Wd  = Wt  + buf * WT_FLOATS;
        const float* wvd = wvt + buf * WV_FLOATS;

        #pragma unroll 2
        for (int k = 0; k < FC_KC; k++) {
            float2 wvv = *reinterpret_cast<const float2*>(&wvd[k * WV_PITCH + ty * 2]);
            float4 w0  = *reinterpret_cast<const float4*>(&Wd[k * WT_PITCH + d0]);
            float4 w1  = *reinterpret_cast<const float4*>(&Wd[k * WT_PITCH + d0 + 4]);
            float wm[2] = {wvv.x, wvv.y};
            float wd[8] = {w0.x, w0.y, w0.z, w0.w, w1.x, w1.y, w1.z, w1.w};
            #pragma unroll
            for (int i = 0; i < 2; i++)
                #pragma unroll
                for (int j = 0; j < 8; j++)
                    acc[i][j] = fmaf(wm[i], wd[j], acc[i][j]);
        }
    }

    float bd[8];
    #pragma unroll
    for (int j = 0; j < 8; j++) bd[j] = b[d0 + j];

    #pragma unroll
    for (int i = 0; i < 2; i++) {
        const int row = row0 + ty * 2 + i;
        const float al = alpha[row];
        float4 xa = reinterpret_cast<const float4*>(x)[(size_t)row * 32 + tx * 2];
        float4 xb = reinterpret_cast<const float4*>(x)[(size_t)row * 32 + tx * 2 + 1];
        float xv[8] = {xa.x, xa.y, xa.z, xa.w, xb.x, xb.y, xb.z, xb.w};

        float sv[8];
        float pssq = 0.f, pxsq = 0.f;
        #pragma unroll
        for (int j = 0; j < 8; j++) {
            float s = al * (acc[i][j] + bd[j]) + (1.f - al) * xv[j];
            sv[j] = s;
            pssq = fmaf(s, s, pssq);
            pxsq = fmaf(xv[j], xv[j], pxsq);
        }

        float4 o0 = {sv[0], sv[1], sv[2], sv[3]};
        float4 o1 = {sv[4], sv[5], sv[6], sv[7]};
        reinterpret_cast<float4*>(sem_out)[(size_t)row * 32 + tx * 2]     = o0;
        reinterpret_cast<float4*>(sem_out)[(size_t)row * 32 + tx * 2 + 1] = o1;

        __half2 sh[4], xh[4];
        #pragma unroll
        for (int j2 = 0; j2 < 4; j2++) {
            sh[j2] = __halves2half2(__float2half(-2.f * sv[2*j2]),
                                    __float2half(-2.f * sv[2*j2+1]));
            xh[j2] = __halves2half2(__float2half(xv[2*j2]),
                                    __float2half(xv[2*j2+1]));
        }
        reinterpret_cast<uint4*>(g_semA + (size_t)row * 128)[tx] =
            *reinterpret_cast<uint4*>(sh);
        reinterpret_cast<uint4*>(g_xH + (size_t)row * 128)[tx] =
            *reinterpret_cast<uint4*>(xh);

        #pragma unroll
        for (int o = 1; o <= 8; o <<= 1) {
            pssq += __shfl_xor_sync(0xFFFFFFFFu, pssq, o);
            pxsq += __shfl_xor_sync(0xFFFFFFFFu, pxsq, o);
        }
        if (tx == 0) {
            g_ssq[row] = pssq;
            g_xsq[row] = pxsq;
        }
    }
}

// ---------------------------------------------------------------------------
// Kernel B: persistent distance + batch-hard mining, pair-decoupled,
// SINGLE-TERM fp16: dot = Ah*Bh.  8 MMAs + 2 ldsm per warp per k-step.
// A-fragments (hi only, all K) in registers.
// ---------------------------------------------------------------------------
#define A_BYTES    16384                    // 64 rows x 256 B
#define SLAB       8192                     // 32 rows x 256 B
#define PAIR_BYTES (2 * SLAB)
#define DIST_DSMEM (A_BYTES + 4 * PAIR_BYTES)   // 81920

#define NSTEPS 64

__global__ __launch_bounds__(256) void dist_persist(
    const int* __restrict__ label, float* __restrict__ diff_out)
{
    extern __shared__ char dyn[];
    __shared__ float aggF[4 * 64];
    __shared__ float aggC[4 * 64];

    const int tid  = threadIdx.x;
    const int wid  = tid >> 5;
    const int lane = tid & 31;
    const int rowbase = blockIdx.x * 64;

    // ---- stage A strip (64 rows x 16 chunks of 16B), swizzled key r&7 ----
    {
        const uint4* gA = reinterpret_cast<const uint4*>(g_semA) + (size_t)rowbase * 16;
        #pragma unroll
        for (int it = 0; it < 4; it++) {
            int idx = it * 256 + tid;          // 0..1023
            int r = idx >> 4, cch = idx & 15;
            uint32_t off = (uint32_t)(r * 256 + ((cch ^ (r & 7)) << 4));
            *reinterpret_cast<uint4*>(dyn + off) = gA[(size_t)r * 16 + cch];
        }
    }
    __syncthreads();

    const uint32_t AsU = smem_u32(dyn);

    const int wm = wid & 1;            // 2 m-slabs of 32
    const int wn = wid >> 1;           // 4 n-slabs of 32 (= pair id)
    const int m_base = wm * 32;
    const int n_base = wn * 32;
    const int pt     = wm * 32 + lane; // pair-local thread 0..63
    const int barid  = 1 + wn;

    const uint32_t pairU = AsU + A_BYTES + wn * PAIR_BYTES;

    // ---- preload ALL A fragments (hi only) into registers ----
    uint32_t aF[8][2][4];              // [kstep][mt][4]
    {
        const uint32_t a_chunk_add = (uint32_t)(lane >> 4);
        #pragma unroll
        for (int mt = 0; mt < 2; mt++) {
            int r = m_base + mt * 16 + (lane & 15);
            uint32_t base = AsU + r * 256;
            uint32_t sw   = (uint32_t)(r & 7);
            #pragma unroll
            for (int s = 0; s < 8; s++) {
                uint32_t ch = (uint32_t)(s * 2) + a_chunk_add;
                ldsm_x4(aF[s][mt], base + ((ch ^ sw) << 4));
            }
        }
    }

    // B ldsm addressing within a 32-row x 256B slab
    uint32_t b_off[2], b_sw[2];
    #pragma unroll
    for (int p = 0; p < 2; p++) {
        int r = p * 16 + ((lane >> 4) << 3) + (lane & 7);
        b_off[p] = pairU + r * 256;
        b_sw[p]  = (uint32_t)(r & 7);
    }
    const uint32_t b_chunk_add = (uint32_t)((lane >> 3) & 1);

    // per-thread row info
    const int q  = lane >> 2;
    const int qt = lane & 3;
    int row_gi[2][2];
    int lmv[2][2];
    #pragma unroll
    for (int mt = 0; mt < 2; mt++)
        #pragma unroll
        for (int hr = 0; hr < 2; hr++) {
            row_gi[mt][hr] = rowbase + m_base + mt * 16 + hr * 8 + q;
            lmv[mt][hr]    = label[row_gi[mt][hr]];
        }

    float fpU[2][2], cnU[2][2];
    #pragma unroll
    for (int mt = 0; mt < 2; mt++)
        #pragma unroll
        for (int hr = 0; hr < 2; hr++) { fpU[mt][hr] = NEGINF; cnU[mt][hr] = POSINF; }

    // ---- pair-private slab staging: 32 rows x 16 chunks, 64 threads ----
    auto stage_slab = [&](int t, int buf) {
        const char* gB = reinterpret_cast<const char*>(g_xH)
                       + (size_t)(t * 128 + n_base) * 256;
        uint32_t bb = pairU + buf * SLAB;
        #pragma unroll
        for (int it = 0; it < 8; it++) {
            int idx = it * 64 + pt;            // 0..511
            int r = idx >> 4, cch = idx & 15;
            uint32_t dst = bb + (uint32_t)(r * 256 + ((cch ^ (r & 7)) << 4));
            cp16(dst, gB + (size_t)r * 256 + cch * 16);
        }
    };

    const int t_diag = (int)(blockIdx.x >> 1);

    stage_slab(0, 0);
    cp_commit();

    for (int t = 0; t < NSTEPS; t++) {
        const int buf = t & 1;
        const int n0  = t * 128;

        if (t + 1 < NSTEPS) {
            stage_slab(t + 1, buf ^ 1);
            cp_commit();
            cp_wait1();
        } else {
            cp_wait0();
        }
        bar_named(barid, 64);

        // mining metadata (L1-hot LDG)
        float xq[8]; int lb[8];
        #pragma unroll
        for (int k = 0; k < 8; k++) {
            int cl = n0 + n_base + (k >> 1) * 8 + qt * 2 + (k & 1);
            xq[k] = g_xsq[cl];
            lb[k] = label[cl];
        }

        float c[2][4][4];
        #pragma unroll
        for (int mt = 0; mt < 2; mt++)
            #pragma unroll
            for (int nt = 0; nt < 4; nt++)
                #pragma unroll
                for (int e = 0; e < 4; e++) c[mt][nt][e] = 0.f;

        const uint32_t bufAdd = (uint32_t)(buf * SLAB);
        #pragma unroll
        for (int s = 0; s < 8; s++) {
            uint32_t bfr[2][4];
            uint32_t chB = (uint32_t)(s * 2) + b_chunk_add;
            #pragma unroll
            for (int p = 0; p < 2; p++)
                ldsm_x4(bfr[p], b_off[p] + bufAdd + ((chB ^ b_sw[p]) << 4));

            #pragma unroll
            for (int mt = 0; mt < 2; mt++) {
                #pragma unroll
                for (int nt = 0; nt < 4; nt++) {
                    const uint32_t* bh = &bfr[nt >> 1][(nt & 1) * 2];
                    mma16816h(c[mt][nt], aF[s][mt], bh);     // Ah*Bh
                }
            }
        }

        // ---- mining on u = xsq[col] + (-2 sem.x) ----
        if (t == t_diag) {
            #pragma unroll
            for (int mt = 0; mt < 2; mt++) {
                #pragma unroll
                for (int hr = 0; hr < 2; hr++) {
                    const int gi = row_gi[mt][hr];
                    const int lm = lmv[mt][hr];
                    float fb = fpU[mt][hr], cb = cnU[mt][hr];
                    #pragma unroll
                    for (int nt = 0; nt < 4; nt++) {
                        #pragma unroll
                        for (int w = 0; w < 2; w++) {
                            int k  = nt * 2 + w;
                            int cl = n0 + n_base + nt * 8 + qt * 2 + w;
                            float u = xq[k] + c[mt][nt][hr * 2 + w];
                            bool same = (lm == lb[k]);
                            bool self = (cl == gi);
                            fb = fmaxf(fb, (same && !self) ? u : NEGINF);
                            cb = fminf(cb, same ? POSINF : u);
                        }
                    }
                    fpU[mt][hr] = fb;
                    cnU[mt][hr] = cb;
                }
            }
        } else {
            #pragma unroll
            for (int mt = 0; mt < 2; mt++) {
                #pragma unroll
                for (int hr = 0; hr < 2; hr++) {
                    const int lm = lmv[mt][hr];
                    float fb = fpU[mt][hr], cb = cnU[mt][hr];
                    #pragma unroll
                    for (int nt = 0; nt < 4; nt++) {
                        #pragma unroll
                        for (int w = 0; w < 2; w++) {
                            int k = nt * 2 + w;
                            float u = xq[k] + c[mt][nt][hr * 2 + w];
                            bool same = (lm == lb[k]);
                            fb = fmaxf(fb, same ? u : NEGINF);
                            cb = fminf(cb, same ? POSINF : u);
                        }
                    }
                    fpU[mt][hr] = fb;
                    cnU[mt][hr] = cb;
                }
            }
        }

        bar_named(barid, 64);
    }

    // ---- final reduction: quad lanes -> smem across wn warps -> softplus ----
    #pragma unroll
    for (int mt = 0; mt < 2; mt++) {
        #pragma unroll
        for (int hr = 0; hr < 2; hr++) {
            float fb = fpU[mt][hr], cb = cnU[mt][hr];
            #pragma unroll
            for (int o = 1; o <= 2; o <<= 1) {
                fb = fmaxf(fb, __shfl_xor_sync(0xFFFFFFFFu, fb, o));
                cb = fminf(cb, __shfl_xor_sync(0xFFFFFFFFu, cb, o));
            }
            if (qt == 0) {
                int r = m_base + mt * 16 + hr * 8 + q;
                aggF[wn * 64 + r] = fb;
                aggC[wn * 64 + r] = cb;
            }
        }
    }
    __syncthreads();

    if (tid < 64) {
        float fb = NEGINF, cb = POSINF;
        #pragma unroll
        for (int wnn = 0; wnn < 4; wnn++) {
            fb = fmaxf(fb, aggF[wnn * 64 + tid]);
            cb = fminf(cb, aggC[wnn * 64 + tid]);
        }
        float ssqm = g_ssq[rowbase + tid];
        float fp = (fb < -1e37f) ? 0.f : sqrtf(fmaxf(ssqm + fb, 0.f) + DEPS);
        float cn = sqrtf(fmaxf(ssqm + cb, 0.f) + DEPS);
        float z = fp - cn;
        diff_out[rowbase + tid] = fmaxf(z, 0.f) + log1pf(expf(-fabsf(z)));
    }
}

// ---------------------------------------------------------------------------
// Launch
// Inputs: x[N,128] f32, wv[N,300] f32, label[N] i32, alpha[N,1] f32,
//         W[128,300] f32, b[128] f32
// Output: diff[N] then sem[N,128] (float32, concatenated)
// ---------------------------------------------------------------------------
extern "C" void kernel_launch(void* const* d_in, const int* in_sizes, int n_in,
                              void* d_out, int out_size)
{
    const float* x     = (const float*)d_in[0];
    const float* wv    = (const float*)d_in[1];
    const int*   label = (const int*)  d_in[2];
    const float* alpha = (const float*)d_in[3];
    const float* W     = (const float*)d_in[4];
    const float* b     = (const float*)d_in[5];

    float* out  = (float*)d_out;
    float* diff = out;            // [N]
    float* sem  = out + NROWS;    // [N, 128]

    static bool attr_set = false;
    if (!attr_set) {
        cudaFuncSetAttribute(dist_persist,
                             cudaFuncAttributeMaxDynamicSharedMemorySize, DIST_DSMEM);
        cudaFuncSetAttribute(fc_mix_fused,
                             cudaFuncAttributeMaxDynamicSharedMemorySize, FC_SMEM);
        attr_set = true;
    }

    fc_mix_fused<<<NROWS / FC_ROWS, 256, FC_SMEM>>>(wv, W, b, alpha, x, sem);
    dist_persist<<<NROWS / 64, 256, DIST_DSMEM>>>(label, diff);
}

// round 13
// speedup vs baseline: 4.1121x; 1.0161x over previous
#include <cuda_runtime.h>
#include <cuda_fp16.h>
#include <math.h>
#include <stdint.h>

// Problem constants
#define NROWS 8192
#define DDIM  128
#define WVDIM 300
#define BIGF  1e8f
#define DEPS  1.28e-14f   // D * 1e-16
#define NEGINF -3.4e38f
#define POSINF  3.4e38f

// ---------------------------------------------------------------------------
// Scratch (__device__ globals; no allocation allowed)
// ---------------------------------------------------------------------------
__device__ float g_ssq[NROWS];
__device__ float g_xsq[NROWS];
// A side: fp16 of (-2*sem), row-major, 256 B/row (16 chunks of 16B)
__device__ __half g_semA[NROWS * 128];
// B side: fp16 of x, row-major, 256 B/row
__device__ __half g_xH[NROWS * 128];

// ---------------------------------------------------------------------------
// PTX helpers
// ---------------------------------------------------------------------------
__device__ __forceinline__ uint32_t smem_u32(const void* p) {
    uint32_t a;
    asm("{ .reg .u64 t; cvta.to.shared.u64 t, %1; cvt.u32.u64 %0, t; }" : "=r"(a) : "l"(p));
    return a;
}
__device__ __forceinline__ void ldsm_x4(uint32_t* r, uint32_t addr) {
    asm("ldmatrix.sync.aligned.m8n8.x4.shared.b16 {%0,%1,%2,%3}, [%4];"
        : "=r"(r[0]), "=r"(r[1]), "=r"(r[2]), "=r"(r[3]) : "r"(addr) : "memory");
}
__device__ __forceinline__ void mma16816h(float* d, const uint32_t* a, const uint32_t* b) {
    asm("mma.sync.aligned.m16n8k16.row.col.f32.f16.f16.f32 "
        "{%0,%1,%2,%3}, {%4,%5,%6,%7}, {%8,%9}, {%0,%1,%2,%3};"
        : "+f"(d[0]), "+f"(d[1]), "+f"(d[2]), "+f"(d[3])
        : "r"(a[0]), "r"(a[1]), "r"(a[2]), "r"(a[3]), "r"(b[0]), "r"(b[1]));
}
__device__ __forceinline__ void cp16(uint32_t dst, const void* src) {
    asm volatile("cp.async.cg.shared.global [%0], [%1], 16;" :: "r"(dst), "l"(src) : "memory");
}
__device__ __forceinline__ void cp4(uint32_t dst, const void* src) {
    asm volatile("cp.async.ca.shared.global [%0], [%1], 4;" :: "r"(dst), "l"(src) : "memory");
}
__device__ __forceinline__ void cp_commit() {
    asm volatile("cp.async.commit_group;" ::: "memory");
}
__device__ __forceinline__ void cp_wait0() {
    asm volatile("cp.async.wait_group 0;" ::: "memory");
}
__device__ __forceinline__ void cp_wait1() {
    asm volatile("cp.async.wait_group 1;" ::: "memory");
}
__device__ __forceinline__ void bar_named(int id, int nthreads) {
    asm volatile("bar.sync %0, %1;" :: "r"(id), "r"(nthreads) : "memory");
}

// ---------------------------------------------------------------------------
// Kernel A (fused): sem = alpha*(wv@W^T + b) + (1-alpha)*x,  PLUS:
//   sem -> output, fp16 of (-2*sem) -> g_semA, fp16 of x -> g_xH, row norms.
// FC_ROWS=64 (W staged once per 64 rows), 512 threads (16 warps) for latency
// hiding: thread tile 2m x 8d, K=300 double-buffered via cp.async.
// ---------------------------------------------------------------------------
#define FC_ROWS   64
#define FC_KC     50
#define FC_THREADS 512
#define WT_PITCH  132
#define WV_PITCH  68
#define WT_FLOATS (FC_KC * WT_PITCH)   // 6600
#define WV_FLOATS (FC_KC * WV_PITCH)   // 3400
#define FC_SMEM   (2 * (WT_FLOATS + WV_FLOATS) * 4)   // 80000 B

__global__ __launch_bounds__(FC_THREADS) void fc_mix_fused(
    const float* __restrict__ wv, const float* __restrict__ W,
    const float* __restrict__ b, const float* __restrict__ alpha,
    const float* __restrict__ x, float* __restrict__ sem_out)
{
    extern __shared__ float fsm[];
    float* Wt  = fsm;                     // [2][50][132]
    float* wvt = fsm + 2 * WT_FLOATS;     // [2][50][68]

    const int tid  = threadIdx.x;
    const int tx   = tid & 15;            // d-group 0..15
    const int ty   = tid >> 4;            // m-group 0..31
    const int row0 = blockIdx.x * FC_ROWS;
    const int d0   = tx * 8;

    auto stage_chunk = [&](int c, int buf) {
        float* Wd  = Wt  + buf * WT_FLOATS;
        float* wvd = wvt + buf * WV_FLOATS;
        for (int l = tid; l < DDIM * FC_KC; l += FC_THREADS) {
            int d = l / FC_KC, k = l - d * FC_KC;
            cp4(smem_u32(&Wd[k * WT_PITCH + d]), &W[d * WVDIM + c * FC_KC + k]);
        }
        for (int l = tid; l < FC_ROWS * FC_KC; l += FC_THREADS) {
            int m = l / FC_KC, k = l - m * FC_KC;
            cp4(smem_u32(&wvd[k * WV_PITCH + m]),
                &wv[(size_t)(row0 + m) * WVDIM + c * FC_KC + k]);
        }
    };

    float acc[2][8];
    #pragma unroll
    for (int i = 0; i < 2; i++)
        #pragma unroll
        for (int j = 0; j < 8; j++) acc[i][j] = 0.f;

    stage_chunk(0, 0);
    cp_commit();

    for (int c = 0; c < WVDIM / FC_KC; c++) {
        const int buf = c & 1;
        cp_wait0();
        __syncthreads();
        if (c + 1 < WVDIM / FC_KC) {
            stage_chunk(c + 1, buf ^ 1);
            cp_commit();
        }
        const float* Wd  = Wt  + buf * WT_FLOATS;
        const float* wvd = wvt + buf * WV_FLOATS;

        #pragma unroll 2
        for (int k = 0; k < FC_KC; k++) {
            float2 wvv = *reinterpret_cast<const float2*>(&wvd[k * WV_PITCH + ty * 2]);
            float4 w0  = *reinterpret_cast<const float4*>(&Wd[k * WT_PITCH + d0]);
            float4 w1  = *reinterpret_cast<const float4*>(&Wd[k * WT_PITCH + d0 + 4]);
            float wm[2] = {wvv.x, wvv.y};
            float wd[8] = {w0.x, w0.y, w0.z, w0.w, w1.x, w1.y, w1.z, w1.w};
            #pragma unroll
            for (int i = 0; i < 2; i++)
                #pragma unroll
                for (int j = 0; j < 8; j++)
                    acc[i][j] = fmaf(wm[i], wd[j], acc[i][j]);
        }
    }

    float bd[8];
    #pragma unroll
    for (int j = 0; j < 8; j++) bd[j] = b[d0 + j];

    #pragma unroll
    for (int i = 0; i < 2; i++) {
        const int row = row0 + ty * 2 + i;
        const float al = alpha[row];
        float4 xa = reinterpret_cast<const float4*>(x)[(size_t)row * 32 + tx * 2];
        float4 xb = reinterpret_cast<const float4*>(x)[(size_t)row * 32 + tx * 2 + 1];
        float xv[8] = {xa.x, xa.y, xa.z, xa.w, xb.x, xb.y, xb.z, xb.w};

        float sv[8];
        float pssq = 0.f, pxsq = 0.f;
        #pragma unroll
        for (int j = 0; j < 8; j++) {
            float s = al * (acc[i][j] + bd[j]) + (1.f - al) * xv[j];
            sv[j] = s;
            pssq = fmaf(s, s, pssq);
            pxsq = fmaf(xv[j], xv[j], pxsq);
        }

        float4 o0 = {sv[0], sv[1], sv[2], sv[3]};
        float4 o1 = {sv[4], sv[5], sv[6], sv[7]};
        reinterpret_cast<float4*>(sem_out)[(size_t)row * 32 + tx * 2]     = o0;
        reinterpret_cast<float4*>(sem_out)[(size_t)row * 32 + tx * 2 + 1] = o1;

        __half2 sh[4], xh[4];
        #pragma unroll
        for (int j2 = 0; j2 < 4; j2++) {
            sh[j2] = __halves2half2(__float2half(-2.f * sv[2*j2]),
                                    __float2half(-2.f * sv[2*j2+1]));
            xh[j2] = __halves2half2(__float2half(xv[2*j2]),
                                    __float2half(xv[2*j2+1]));
        }
        reinterpret_cast<uint4*>(g_semA + (size_t)row * 128)[tx] =
            *reinterpret_cast<uint4*>(sh);
        reinterpret_cast<uint4*>(g_xH + (size_t)row * 128)[tx] =
            *reinterpret_cast<uint4*>(xh);

        #pragma unroll
        for (int o = 1; o <= 8; o <<= 1) {
            pssq += __shfl_xor_sync(0xFFFFFFFFu, pssq, o);
            pxsq += __shfl_xor_sync(0xFFFFFFFFu, pxsq, o);
        }
        if (tx == 0) {
            g_ssq[row] = pssq;
            g_xsq[row] = pxsq;
        }
    }
}

// ---------------------------------------------------------------------------
// Kernel B: persistent distance + batch-hard mining, pair-decoupled,
// single-term fp16: dot = Ah*Bh.  (UNCHANGED from R12 — 77.9 us measured.)
// ---------------------------------------------------------------------------
#define A_BYTES    16384                    // 64 rows x 256 B
#define SLAB       8192                     // 32 rows x 256 B
#define PAIR_BYTES (2 * SLAB)
#define DIST_DSMEM (A_BYTES + 4 * PAIR_BYTES)   // 81920

#define NSTEPS 64

__global__ __launch_bounds__(256) void dist_persist(
    const int* __restrict__ label, float* __restrict__ diff_out)
{
    extern __shared__ char dyn[];
    __shared__ float aggF[4 * 64];
    __shared__ float aggC[4 * 64];

    const int tid  = threadIdx.x;
    const int wid  = tid >> 5;
    const int lane = tid & 31;
    const int rowbase = blockIdx.x * 64;

    // ---- stage A strip (64 rows x 16 chunks of 16B), swizzled key r&7 ----
    {
        const uint4* gA = reinterpret_cast<const uint4*>(g_semA) + (size_t)rowbase * 16;
        #pragma unroll
        for (int it = 0; it < 4; it++) {
            int idx = it * 256 + tid;          // 0..1023
            int r = idx >> 4, cch = idx & 15;
            uint32_t off = (uint32_t)(r * 256 + ((cch ^ (r & 7)) << 4));
            *reinterpret_cast<uint4*>(dyn + off) = gA[(size_t)r * 16 + cch];
        }
    }
    __syncthreads();

    const uint32_t AsU = smem_u32(dyn);

    const int wm = wid & 1;            // 2 m-slabs of 32
    const int wn = wid >> 1;           // 4 n-slabs of 32 (= pair id)
    const int m_base = wm * 32;
    const int n_base = wn * 32;
    const int pt     = wm * 32 + lane; // pair-local thread 0..63
    const int barid  = 1 + wn;

    const uint32_t pairU = AsU + A_BYTES + wn * PAIR_BYTES;

    // ---- preload ALL A fragments (hi only) into registers ----
    uint32_t aF[8][2][4];              // [kstep][mt][4]
    {
        const uint32_t a_chunk_add = (uint32_t)(lane >> 4);
        #pragma unroll
        for (int mt = 0; mt < 2; mt++) {
            int r = m_base + mt * 16 + (lane & 15);
            uint32_t base = AsU + r * 256;
            uint32_t sw   = (uint32_t)(r & 7);
            #pragma unroll
            for (int s = 0; s < 8; s++) {
                uint32_t ch = (uint32_t)(s * 2) + a_chunk_add;
                ldsm_x4(aF[s][mt], base + ((ch ^ sw) << 4));
            }
        }
    }

    // B ldsm addressing within a 32-row x 256B slab
    uint32_t b_off[2], b_sw[2];
    #pragma unroll
    for (int p = 0; p < 2; p++) {
        int r = p * 16 + ((lane >> 4) << 3) + (lane & 7);
        b_off[p] = pairU + r * 256;
        b_sw[p]  = (uint32_t)(r & 7);
    }
    const uint32_t b_chunk_add = (uint32_t)((lane >> 3) & 1);

    // per-thread row info
    const int q  = lane >> 2;
    const int qt = lane & 3;
    int row_gi[2][2];
    int lmv[2][2];
    #pragma unroll
    for (int mt = 0; mt < 2; mt++)
        #pragma unroll
        for (int hr = 0; hr < 2; hr++) {
            row_gi[mt][hr] = rowbase + m_base + mt * 16 + hr * 8 + q;
            lmv[mt][hr]    = label[row_gi[mt][hr]];
        }

    float fpU[2][2], cnU[2][2];
    #pragma unroll
    for (int mt = 0; mt < 2; mt++)
        #pragma unroll
        for (int hr = 0; hr < 2; hr++) { fpU[mt][hr] = NEGINF; cnU[mt][hr] = POSINF; }

    // ---- pair-private slab staging: 32 rows x 16 chunks, 64 threads ----
    auto stage_slab = [&](int t, int buf) {
        const char* gB = reinterpret_cast<const char*>(g_xH)
                       + (size_t)(t * 128 + n_base) * 256;
        uint32_t bb = pairU + buf * SLAB;
        #pragma unroll
        for (int it = 0; it < 8; it++) {
            int idx = it * 64 + pt;            // 0..511
            int r = idx >> 4, cch = idx & 15;
            uint32_t dst = bb + (uint32_t)(r * 256 + ((cch ^ (r & 7)) << 4));
            cp16(dst, gB + (size_t)r * 256 + cch * 16);
        }
    };

    const int t_diag = (int)(blockIdx.x >> 1);

    stage_slab(0, 0);
    cp_commit();

    for (int t = 0; t < NSTEPS; t++) {
        const int buf = t & 1;
        const int n0  = t * 128;

        if (t + 1 < NSTEPS) {
            stage_slab(t + 1, buf ^ 1);
            cp_commit();
            cp_wait1();
        } else {
            cp_wait0();
        }
        bar_named(barid, 64);

        // mining metadata (L1-hot LDG)
        float xq[8]; int lb[8];
        #pragma unroll
        for (int k = 0; k < 8; k++) {
            int cl = n0 + n_base + (k >> 1) * 8 + qt * 2 + (k & 1);
            xq[k] = g_xsq[cl];
            lb[k] = label[cl];
        }

        float c[2][4][4];
        #pragma unroll
        for (int mt = 0; mt < 2; mt++)
            #pragma unroll
            for (int nt = 0; nt < 4; nt++)
                #pragma unroll
                for (int e = 0; e < 4; e++) c[mt][nt][e] = 0.f;

        const uint32_t bufAdd = (uint32_t)(buf * SLAB);
        #pragma unroll
        for (int s = 0; s < 8; s++) {
            uint32_t bfr[2][4];
            uint32_t chB = (uint32_t)(s * 2) + b_chunk_add;
            #pragma unroll
            for (int p = 0; p < 2; p++)
                ldsm_x4(bfr[p], b_off[p] + bufAdd + ((chB ^ b_sw[p]) << 4));

            #pragma unroll
            for (int mt = 0; mt < 2; mt++) {
                #pragma unroll
                for (int nt = 0; nt < 4; nt++) {
                    const uint32_t* bh = &bfr[nt >> 1][(nt & 1) * 2];
                    mma16816h(c[mt][nt], aF[s][mt], bh);     // Ah*Bh
                }
            }
        }

        // ---- mining on u = xsq[col] + (-2 sem.x) ----
        if (t == t_diag) {
            #pragma unroll
            for (int mt = 0; mt < 2; mt++) {
                #pragma unroll
                for (int hr = 0; hr < 2; hr++) {
                    const int gi = row_gi[mt][hr];
                    const int lm = lmv[mt][hr];
                    float fb = fpU[mt][hr], cb = cnU[mt][hr];
                    #pragma unroll
                    for (int nt = 0; nt < 4; nt++) {
                        #pragma unroll
                        for (int w = 0; w < 2; w++) {
                            int k  = nt * 2 + w;
                            int cl = n0 + n_base + nt * 8 + qt * 2 + w;
                            float u = xq[k] + c[mt][nt][hr * 2 + w];
                            bool same = (lm == lb[k]);
                            bool self = (cl == gi);
                            fb = fmaxf(fb, (same && !self) ? u : NEGINF);
                            cb = fminf(cb, same ? POSINF : u);
                        }
                    }
                    fpU[mt][hr] = fb;
                    cnU[mt][hr] = cb;
                }
            }
        } else {
            #pragma unroll
            for (int mt = 0; mt < 2; mt++) {
                #pragma unroll
                for (int hr = 0; hr < 2; hr++) {
                    const int lm = lmv[mt][hr];
                    float fb = fpU[mt][hr], cb = cnU[mt][hr];
                    #pragma unroll
                    for (int nt = 0; nt < 4; nt++) {
                        #pragma unroll
                        for (int w = 0; w < 2; w++) {
                            int k = nt * 2 + w;
                            float u = xq[k] + c[mt][nt][hr * 2 + w];
                            bool same = (lm == lb[k]);
                            fb = fmaxf(fb, same ? u : NEGINF);
                            cb = fminf(cb, same ? POSINF : u);
                        }
                    }
                    fpU[mt][hr] = fb;
                    cnU[mt][hr] = cb;
                }
            }
        }

        bar_named(barid, 64);
    }

    // ---- final reduction: quad lanes -> smem across wn warps -> softplus ----
    #pragma unroll
    for (int mt = 0; mt < 2; mt++) {
        #pragma unroll
        for (int hr = 0; hr < 2; hr++) {
            float fb = fpU[mt][hr], cb = cnU[mt][hr];
            #pragma unroll
            for (int o = 1; o <= 2; o <<= 1) {
                fb = fmaxf(fb, __shfl_xor_sync(0xFFFFFFFFu, fb, o));
                cb = fminf(cb, __shfl_xor_sync(0xFFFFFFFFu, cb, o));
            }
            if (qt == 0) {
                int r = m_base + mt * 16 + hr * 8 + q;
                aggF[wn * 64 + r] = fb;
                aggC[wn * 64 + r] = cb;
            }
        }
    }
    __syncthreads();

    if (tid < 64) {
        float fb = NEGINF, cb = POSINF;
        #pragma unroll
        for (int wnn = 0; wnn < 4; wnn++) {
            fb = fmaxf(fb, aggF[wnn * 64 + tid]);
            cb = fminf(cb, aggC[wnn * 64 + tid]);
        }
        float ssqm = g_ssq[rowbase + tid];
        float fp = (fb < -1e37f) ? 0.f : sqrtf(fmaxf(ssqm + fb, 0.f) + DEPS);
        float cn = sqrtf(fmaxf(ssqm + cb, 0.f) + DEPS);
        float z = fp - cn;
        diff_out[rowbase + tid] = fmaxf(z, 0.f) + log1pf(expf(-fabsf(z)));
    }
}

// ---------------------------------------------------------------------------
// Launch
// Inputs: x[N,128] f32, wv[N,300] f32, label[N] i32, alpha[N,1] f32,
//         W[128,300] f32, b[128] f32
// Output: diff[N] then sem[N,128] (float32, concatenated)
// ---------------------------------------------------------------------------
extern "C" void kernel_launch(void* const* d_in, const int* in_sizes, int n_in,
                              void* d_out, int out_size)
{
    const float* x     = (const float*)d_in[0];
    const float* wv    = (const float*)d_in[1];
    const int*   label = (const int*)  d_in[2];
    const float* alpha = (const float*)d_in[3];
    const float* W     = (const float*)d_in[4];
    const float* b     = (const float*)d_in[5];

    float* out  = (float*)d_out;
    float* diff = out;            // [N]
    float* sem  = out + NROWS;    // [N, 128]

    static bool attr_set = false;
    if (!attr_set) {
        cudaFuncSetAttribute(dist_persist,
                             cudaFuncAttributeMaxDynamicSharedMemorySize, DIST_DSMEM);
        cudaFuncSetAttribute(fc_mix_fused,
                             cudaFuncAttributeMaxDynamicSharedMemorySize, FC_SMEM);
        attr_set = true;
    }

    fc_mix_fused<<<NROWS / FC_ROWS, FC_THREADS, FC_SMEM>>>(wv, W, b, alpha, x, sem);
    dist_persist<<<NROWS / 64, 256, DIST_DSMEM>>>(label, diff);
}

// round 14
// speedup vs baseline: 5.4810x; 1.3329x over previous
#include <cuda_runtime.h>
#include <cuda_fp16.h>
#include <math.h>
#include <stdint.h>

// Problem constants
#define NROWS 8192
#define DDIM  128
#define WVDIM 300
#define BIGF  1e8f
#define DEPS  1.28e-14f   // D * 1e-16
#define NEGINF -3.4e38f
#define POSINF  3.4e38f

// ---------------------------------------------------------------------------
// Scratch (__device__ globals; no allocation allowed)
// ---------------------------------------------------------------------------
__device__ float g_ssq[NROWS];
__device__ float g_xsq[NROWS];
// A side: fp16 of (-2*sem), row-major, 256 B/row (16 chunks of 16B)
__device__ __half g_semA[NROWS * 128];
// B side: fp16 of x, row-major, 256 B/row
__device__ __half g_xH[NROWS * 128];

// ---------------------------------------------------------------------------
// PTX helpers
// ---------------------------------------------------------------------------
__device__ __forceinline__ uint32_t smem_u32(const void* p) {
    uint32_t a;
    asm("{ .reg .u64 t; cvta.to.shared.u64 t, %1; cvt.u32.u64 %0, t; }" : "=r"(a) : "l"(p));
    return a;
}
__device__ __forceinline__ void ldsm_x4(uint32_t* r, uint32_t addr) {
    asm("ldmatrix.sync.aligned.m8n8.x4.shared.b16 {%0,%1,%2,%3}, [%4];"
        : "=r"(r[0]), "=r"(r[1]), "=r"(r[2]), "=r"(r[3]) : "r"(addr) : "memory");
}
__device__ __forceinline__ void mma16816h(float* d, const uint32_t* a, const uint32_t* b) {
    asm("mma.sync.aligned.m16n8k16.row.col.f32.f16.f16.f32 "
        "{%0,%1,%2,%3}, {%4,%5,%6,%7}, {%8,%9}, {%0,%1,%2,%3};"
        : "+f"(d[0]), "+f"(d[1]), "+f"(d[2]), "+f"(d[3])
        : "r"(a[0]), "r"(a[1]), "r"(a[2]), "r"(a[3]), "r"(b[0]), "r"(b[1]));
}
__device__ __forceinline__ void cp16(uint32_t dst, const void* src) {
    asm volatile("cp.async.cg.shared.global [%0], [%1], 16;" :: "r"(dst), "l"(src) : "memory");
}
__device__ __forceinline__ void cp_commit() {
    asm volatile("cp.async.commit_group;" ::: "memory");
}
__device__ __forceinline__ void cp_wait0() {
    asm volatile("cp.async.wait_group 0;" ::: "memory");
}
__device__ __forceinline__ void cp_wait1() {
    asm volatile("cp.async.wait_group 1;" ::: "memory");
}
__device__ __forceinline__ void bar_named(int id, int nthreads) {
    asm volatile("bar.sync %0, %1;" :: "r"(id), "r"(nthreads) : "memory");
}

// ---------------------------------------------------------------------------
// Kernel A (fused): sem = alpha*(wv@W^T + b) + (1-alpha)*x,  PLUS:
//   sem -> output, fp16 of (-2*sem) -> g_semA, fp16 of x -> g_xH, row norms.
// ROW-MAJOR smem (no transpose): staging is pure 16B cp.async (14.4k ops vs
// 57.6k scalar before).  Conflict-free compute via strided-d thread mapping:
// thread owns d = tx+16j -> f4-addr (tx+16j)*25+k4, bank-group = tx mod 8.
// 64 rows x 128 d per CTA, 256 threads, thread tile 4m x 8d, K chunks of 100.
// ---------------------------------------------------------------------------
#define FC_ROWS    64
#define FC_KC      100
#define FC_CHUNKS  3
#define W_FLOATS   (DDIM * FC_KC)      // 12800
#define WVV_FLOATS (FC_ROWS * FC_KC)   // 6400
#define FC_SMEM    (2 * (W_FLOATS + WVV_FLOATS) * 4)   // 153600 B

__global__ __launch_bounds__(256) void fc_mix_fused(
    const float* __restrict__ wv, const float* __restrict__ W,
    const float* __restrict__ b, const float* __restrict__ alpha,
    const float* __restrict__ x, float* __restrict__ sem_out)
{
    extern __shared__ float fsm[];
    float* Wt  = fsm;                     // [2][128][100]  row-major
    float* wvt = fsm + 2 * W_FLOATS;      // [2][64][100]   row-major

    const int tid  = threadIdx.x;
    const int tx   = tid & 15;            // d-lane 0..15
    const int ty   = tid >> 4;            // m-group 0..15
    const int row0 = blockIdx.x * FC_ROWS;

    const uint32_t WtU  = smem_u32(Wt);
    const uint32_t wvtU = smem_u32(wvt);

    // linear 16B staging (dst contiguous; src rows are 16B-aligned slices)
    auto stage_chunk = [&](int c, int buf) {
        uint32_t wdst = WtU + (uint32_t)(buf * W_FLOATS * 4);
        const float* wsrc = W + c * FC_KC;
        #pragma unroll 4
        for (int l = tid; l < DDIM * (FC_KC / 4); l += 256) {   // 3200 f4
            int d = l / 25, f4 = l - d * 25;
            cp16(wdst + (uint32_t)l * 16, wsrc + (size_t)d * WVDIM + f4 * 4);
        }
        uint32_t vdst = wvtU + (uint32_t)(buf * WVV_FLOATS * 4);
        const float* vsrc = wv + (size_t)row0 * WVDIM + c * FC_KC;
        #pragma unroll 4
        for (int l = tid; l < FC_ROWS * (FC_KC / 4); l += 256) { // 1600 f4
            int m = l / 25, f4 = l - m * 25;
            cp16(vdst + (uint32_t)l * 16, vsrc + (size_t)m * WVDIM + f4 * 4);
        }
    };

    float acc[4][8];
    #pragma unroll
    for (int i = 0; i < 4; i++)
        #pragma unroll
        for (int j = 0; j < 8; j++) acc[i][j] = 0.f;

    stage_chunk(0, 0);
    cp_commit();

    for (int c = 0; c < FC_CHUNKS; c++) {
        const int buf = c & 1;
        cp_wait0();
        __syncthreads();
        if (c + 1 < FC_CHUNKS) {
            stage_chunk(c + 1, buf ^ 1);
            cp_commit();
        }
        const float4* Wd  = reinterpret_cast<const float4*>(Wt  + buf * W_FLOATS);
        const float4* wvd = reinterpret_cast<const float4*>(wvt + buf * WVV_FLOATS);

        #pragma unroll 5
        for (int k4 = 0; k4 < FC_KC / 4; k4++) {
            float4 wf[8], vf[4];
            #pragma unroll
            for (int j = 0; j < 8; j++) wf[j] = Wd[(tx + 16 * j) * 25 + k4];
            #pragma unroll
            for (int i = 0; i < 4; i++) vf[i] = wvd[(ty * 4 + i) * 25 + k4];
            #pragma unroll
            for (int i = 0; i < 4; i++) {
                #pragma unroll
                for (int j = 0; j < 8; j++) {
                    float s = acc[i][j];
                    s = fmaf(vf[i].x, wf[j].x, s);
                    s = fmaf(vf[i].y, wf[j].y, s);
                    s = fmaf(vf[i].z, wf[j].z, s);
                    s = fmaf(vf[i].w, wf[j].w, s);
                    acc[i][j] = s;
                }
            }
        }
    }

    // ---- fused epilogue: mix, fp16 conversions, norms (d = tx + 16j) ----
    float bd[8];
    #pragma unroll
    for (int j = 0; j < 8; j++) bd[j] = b[tx + 16 * j];

    #pragma unroll
    for (int i = 0; i < 4; i++) {
        const int row = row0 + ty * 4 + i;
        const float al = alpha[row];
        float xv[8];
        #pragma unroll
        for (int j = 0; j < 8; j++) xv[j] = x[(size_t)row * DDIM + tx + 16 * j];

        float sv[8];
        float pssq = 0.f, pxsq = 0.f;
        #pragma unroll
        for (int j = 0; j < 8; j++) {
            float s = al * (acc[i][j] + bd[j]) + (1.f - al) * xv[j];
            sv[j] = s;
            pssq = fmaf(s, s, pssq);
            pxsq = fmaf(xv[j], xv[j], pxsq);
        }

        #pragma unroll
        for (int j = 0; j < 8; j++) {
            sem_out[(size_t)row * DDIM + tx + 16 * j] = sv[j];
            g_semA[(size_t)row * DDIM + tx + 16 * j] = __float2half(-2.f * sv[j]);
            g_xH[(size_t)row * DDIM + tx + 16 * j]   = __float2half(xv[j]);
        }

        #pragma unroll
        for (int o = 1; o <= 8; o <<= 1) {
            pssq += __shfl_xor_sync(0xFFFFFFFFu, pssq, o);
            pxsq += __shfl_xor_sync(0xFFFFFFFFu, pxsq, o);
        }
        if (tx == 0) {
            g_ssq[row] = pssq;
            g_xsq[row] = pxsq;
        }
    }
}

// ---------------------------------------------------------------------------
// Kernel B: persistent distance + batch-hard mining, pair-decoupled,
// single-term fp16: dot = Ah*Bh.  (UNCHANGED — 78-80 us measured twice.)
// ---------------------------------------------------------------------------
#define A_BYTES    16384                    // 64 rows x 256 B
#define SLAB       8192                     // 32 rows x 256 B
#define PAIR_BYTES (2 * SLAB)
#define DIST_DSMEM (A_BYTES + 4 * PAIR_BYTES)   // 81920

#define NSTEPS 64

__global__ __launch_bounds__(256) void dist_persist(
    const int* __restrict__ label, float* __restrict__ diff_out)
{
    extern __shared__ char dyn[];
    __shared__ float aggF[4 * 64];
    __shared__ float aggC[4 * 64];

    const int tid  = threadIdx.x;
    const int wid  = tid >> 5;
    const int lane = tid & 31;
    const int rowbase = blockIdx.x * 64;

    // ---- stage A strip (64 rows x 16 chunks of 16B), swizzled key r&7 ----
    {
        const uint4* gA = reinterpret_cast<const uint4*>(g_semA) + (size_t)rowbase * 16;
        #pragma unroll
        for (int it = 0; it < 4; it++) {
            int idx = it * 256 + tid;          // 0..1023
            int r = idx >> 4, cch = idx & 15;
            uint32_t off = (uint32_t)(r * 256 + ((cch ^ (r & 7)) << 4));
            *reinterpret_cast<uint4*>(dyn + off) = gA[(size_t)r * 16 + cch];
        }
    }
    __syncthreads();

    const uint32_t AsU = smem_u32(dyn);

    const int wm = wid & 1;            // 2 m-slabs of 32
    const int wn = wid >> 1;           // 4 n-slabs of 32 (= pair id)
    const int m_base = wm * 32;
    const int n_base = wn * 32;
    const int pt     = wm * 32 + lane; // pair-local thread 0..63
    const int barid  = 1 + wn;

    const uint32_t pairU = AsU + A_BYTES + wn * PAIR_BYTES;

    // ---- preload ALL A fragments (hi only) into registers ----
    uint32_t aF[8][2][4];              // [kstep][mt][4]
    {
        const uint32_t a_chunk_add = (uint32_t)(lane >> 4);
        #pragma unroll
        for (int mt = 0; mt < 2; mt++) {
            int r = m_base + mt * 16 + (lane & 15);
            uint32_t base = AsU + r * 256;
            uint32_t sw   = (uint32_t)(r & 7);
            #pragma unroll
            for (int s = 0; s < 8; s++) {
                uint32_t ch = (uint32_t)(s * 2) + a_chunk_add;
                ldsm_x4(aF[s][mt], base + ((ch ^ sw) << 4));
            }
        }
    }

    // B ldsm addressing within a 32-row x 256B slab
    uint32_t b_off[2], b_sw[2];
    #pragma unroll
    for (int p = 0; p < 2; p++) {
        int r = p * 16 + ((lane >> 4) << 3) + (lane & 7);
        b_off[p] = pairU + r * 256;
        b_sw[p]  = (uint32_t)(r & 7);
    }
    const uint32_t b_chunk_add = (uint32_t)((lane >> 3) & 1);

    // per-thread row info
    const int q  = lane >> 2;
    const int qt = lane & 3;
    int row_gi[2][2];
    int lmv[2][2];
    #pragma unroll
    for (int mt = 0; mt < 2; mt++)
        #pragma unroll
        for (int hr = 0; hr < 2; hr++) {
            row_gi[mt][hr] = rowbase + m_base + mt * 16 + hr * 8 + q;
            lmv[mt][hr]    = label[row_gi[mt][hr]];
        }

    float fpU[2][2], cnU[2][2];
    #pragma unroll
    for (int mt = 0; mt < 2; mt++)
        #pragma unroll
        for (int hr = 0; hr < 2; hr++) { fpU[mt][hr] = NEGINF; cnU[mt][hr] = POSINF; }

    // ---- pair-private slab staging: 32 rows x 16 chunks, 64 threads ----
    auto stage_slab = [&](int t, int buf) {
        const char* gB = reinterpret_cast<const char*>(g_xH)
                       + (size_t)(t * 128 + n_base) * 256;
        uint32_t bb = pairU + buf * SLAB;
        #pragma unroll
        for (int it = 0; it < 8; it++) {
            int idx = it * 64 + pt;            // 0..511
            int r = idx >> 4, cch = idx & 15;
            uint32_t dst = bb + (uint32_t)(r * 256 + ((cch ^ (r & 7)) << 4));
            cp16(dst, gB + (size_t)r * 256 + cch * 16);
        }
    };

    const int t_diag = (int)(blockIdx.x >> 1);

    stage_slab(0, 0);
    cp_commit();

    for (int t = 0; t < NSTEPS; t++) {
        const int buf = t & 1;
        const int n0  = t * 128;

        if (t + 1 < NSTEPS) {
            stage_slab(t + 1, buf ^ 1);
            cp_commit();
            cp_wait1();
        } else {
            cp_wait0();
        }
        bar_named(barid, 64);

        // mining metadata (L1-hot LDG)
        float xq[8]; int lb[8];
        #pragma unroll
        for (int k = 0; k < 8; k++) {
            int cl = n0 + n_base + (k >> 1) * 8 + qt * 2 + (k & 1);
            xq[k] = g_xsq[cl];
            lb[k] = label[cl];
        }

        float c[2][4][4];
        #pragma unroll
        for (int mt = 0; mt < 2; mt++)
            #pragma unroll
            for (int nt = 0; nt < 4; nt++)
                #pragma unroll
                for (int e = 0; e < 4; e++) c[mt][nt][e] = 0.f;

        const uint32_t bufAdd = (uint32_t)(buf * SLAB);
        #pragma unroll
        for (int s = 0; s < 8; s++) {
            uint32_t bfr[2][4];
            uint32_t chB = (uint32_t)(s * 2) + b_chunk_add;
            #pragma unroll
            for (int p = 0; p < 2; p++)
                ldsm_x4(bfr[p], b_off[p] + bufAdd + ((chB ^ b_sw[p]) << 4));

            #pragma unroll
            for (int mt = 0; mt < 2; mt++) {
                #pragma unroll
                for (int nt = 0; nt < 4; nt++) {
                    const uint32_t* bh = &bfr[nt >> 1][(nt & 1) * 2];
                    mma16816h(c[mt][nt], aF[s][mt], bh);     // Ah*Bh
                }
            }
        }

        // ---- mining on u = xsq[col] + (-2 sem.x) ----
        if (t == t_diag) {
            #pragma unroll
            for (int mt = 0; mt < 2; mt++) {
                #pragma unroll
                for (int hr = 0; hr < 2; hr++) {
                    const int gi = row_gi[mt][hr];
                    const int lm = lmv[mt][hr];
                    float fb = fpU[mt][hr], cb = cnU[mt][hr];
                    #pragma unroll
                    for (int nt = 0; nt < 4; nt++) {
                        #pragma unroll
                        for (int w = 0; w < 2; w++) {
                            int k  = nt * 2 + w;
                            int cl = n0 + n_base + nt * 8 + qt * 2 + w;
                            float u = xq[k] + c[mt][nt][hr * 2 + w];
                            bool same = (lm == lb[k]);
                            bool self = (cl == gi);
                            fb = fmaxf(fb, (same && !self) ? u : NEGINF);
                            cb = fminf(cb, same ? POSINF : u);
                        }
                    }
                    fpU[mt][hr] = fb;
                    cnU[mt][hr] = cb;
                }
            }
        } else {
            #pragma unroll
            for (int mt = 0; mt < 2; mt++) {
                #pragma unroll
                for (int hr = 0; hr < 2; hr++) {
                    const int lm = lmv[mt][hr];
                    float fb = fpU[mt][hr], cb = cnU[mt][hr];
                    #pragma unroll
                    for (int nt = 0; nt < 4; nt++) {
                        #pragma unroll
                        for (int w = 0; w < 2; w++) {
                            int k = nt * 2 + w;
                            float u = xq[k] + c[mt][nt][hr * 2 + w];
                            bool same = (lm == lb[k]);
                            fb = fmaxf(fb, same ? u : NEGINF);
                            cb = fminf(cb, same ? POSINF : u);
                        }
                    }
                    fpU[mt][hr] = fb;
                    cnU[mt][hr] = cb;
                }
            }
        }

        bar_named(barid, 64);
    }

    // ---- final reduction: quad lanes -> smem across wn warps -> softplus ----
    #pragma unroll
    for (int mt = 0; mt < 2; mt++) {
        #pragma unroll
        for (int hr = 0; hr < 2; hr++) {
            float fb = fpU[mt][hr], cb = cnU[mt][hr];
            #pragma unroll
            for (int o = 1; o <= 2; o <<= 1) {
                fb = fmaxf(fb, __shfl_xor_sync(0xFFFFFFFFu, fb, o));
                cb = fminf(cb, __shfl_xor_sync(0xFFFFFFFFu, cb, o));
            }
            if (qt == 0) {
                int r = m_base + mt * 16 + hr * 8 + q;
                aggF[wn * 64 + r] = fb;
                aggC[wn * 64 + r] = cb;
            }
        }
    }
    __syncthreads();

    if (tid < 64) {
        float fb = NEGINF, cb = POSINF;
        #pragma unroll
        for (int wnn = 0; wnn < 4; wnn++) {
            fb = fmaxf(fb, aggF[wnn * 64 + tid]);
            cb = fminf(cb, aggC[wnn * 64 + tid]);
        }
        float ssqm = g_ssq[rowbase + tid];
        float fp = (fb < -1e37f) ? 0.f : sqrtf(fmaxf(ssqm + fb, 0.f) + DEPS);
        float cn = sqrtf(fmaxf(ssqm + cb, 0.f) + DEPS);
        float z = fp - cn;
        diff_out[rowbase + tid] = fmaxf(z, 0.f) + log1pf(expf(-fabsf(z)));
    }
}

// ---------------------------------------------------------------------------
// Launch
// Inputs: x[N,128] f32, wv[N,300] f32, label[N] i32, alpha[N,1] f32,
//         W[128,300] f32, b[128] f32
// Output: diff[N] then sem[N,128] (float32, concatenated)
// ---------------------------------------------------------------------------
extern "C" void kernel_launch(void* const* d_in, const int* in_sizes, int n_in,
                              void* d_out, int out_size)
{
    const float* x     = (const float*)d_in[0];
    const float* wv    = (const float*)d_in[1];
    const int*   label = (const int*)  d_in[2];
    const float* alpha = (const float*)d_in[3];
    const float* W     = (const float*)d_in[4];
    const float* b     = (const float*)d_in[5];

    float* out  = (float*)d_out;
    float* diff = out;            // [N]
    float* sem  = out + NROWS;    // [N, 128]

    static bool attr_set = false;
    if (!attr_set) {
        cudaFuncSetAttribute(dist_persist,
                             cudaFuncAttributeMaxDynamicSharedMemorySize, DIST_DSMEM);
        cudaFuncSetAttribute(fc_mix_fused,
                             cudaFuncAttributeMaxDynamicSharedMemorySize, FC_SMEM);
        attr_set = true;
    }

    fc_mix_fused<<<NROWS / FC_ROWS, 256, FC_SMEM>>>(wv, W, b, alpha, x, sem);
    dist_persist<<<NROWS / 64, 256, DIST_DSMEM>>>(label, diff);
}

// round 15
// speedup vs baseline: 5.9961x; 1.0940x over previous
#include <cuda_runtime.h>
#include <cuda_fp16.h>
#include <math.h>
#include <stdint.h>

// Problem constants
#define NROWS 8192
#define DDIM  128
#define WVDIM 300
#define BIGF  1e8f
#define DEPS  1.28e-14f   // D * 1e-16
#define NEGINF -3.4e38f
#define POSINF  3.4e38f

// ---------------------------------------------------------------------------
// Scratch (__device__ globals; no allocation allowed)
// ---------------------------------------------------------------------------
__device__ float g_ssq[NROWS];
__device__ float g_xsq[NROWS];
// A side: fp16 of (-2*sem), row-major, 256 B/row (16 chunks of 16B)
__device__ __half g_semA[NROWS * 128];
// B side: fp16 of x, row-major, 256 B/row
__device__ __half g_xH[NROWS * 128];

// ---------------------------------------------------------------------------
// PTX helpers
// ---------------------------------------------------------------------------
__device__ __forceinline__ uint32_t smem_u32(const void* p) {
    uint32_t a;
    asm("{ .reg .u64 t; cvta.to.shared.u64 t, %1; cvt.u32.u64 %0, t; }" : "=r"(a) : "l"(p));
    return a;
}
__device__ __forceinline__ void ldsm_x4(uint32_t* r, uint32_t addr) {
    asm("ldmatrix.sync.aligned.m8n8.x4.shared.b16 {%0,%1,%2,%3}, [%4];"
        : "=r"(r[0]), "=r"(r[1]), "=r"(r[2]), "=r"(r[3]) : "r"(addr) : "memory");
}
__device__ __forceinline__ void mma16816h(float* d, const uint32_t* a, const uint32_t* b) {
    asm("mma.sync.aligned.m16n8k16.row.col.f32.f16.f16.f32 "
        "{%0,%1,%2,%3}, {%4,%5,%6,%7}, {%8,%9}, {%0,%1,%2,%3};"
        : "+f"(d[0]), "+f"(d[1]), "+f"(d[2]), "+f"(d[3])
        : "r"(a[0]), "r"(a[1]), "r"(a[2]), "r"(a[3]), "r"(b[0]), "r"(b[1]));
}
__device__ __forceinline__ void cp16(uint32_t dst, const void* src) {
    asm volatile("cp.async.cg.shared.global [%0], [%1], 16;" :: "r"(dst), "l"(src) : "memory");
}
__device__ __forceinline__ void cp_commit() {
    asm volatile("cp.async.commit_group;" ::: "memory");
}
__device__ __forceinline__ void cp_wait0() {
    asm volatile("cp.async.wait_group 0;" ::: "memory");
}
__device__ __forceinline__ void cp_wait1() {
    asm volatile("cp.async.wait_group 1;" ::: "memory");
}
__device__ __forceinline__ void bar_named(int id, int nthreads) {
    asm volatile("bar.sync %0, %1;" :: "r"(id), "r"(nthreads) : "memory");
}

// ---------------------------------------------------------------------------
// Kernel A (fused): sem = alpha*(wv@W^T + b) + (1-alpha)*x,  PLUS:
//   sem -> output, fp16 of (-2*sem) -> g_semA, fp16 of x -> g_xH, row norms.
// ROW-MAJOR smem, linear 16B cp.async staging, strided-d conflict-free
// compute.  (UNCHANGED from R14 — 18.7 us measured.)
// ---------------------------------------------------------------------------
#define FC_ROWS    64
#define FC_KC      100
#define FC_CHUNKS  3
#define W_FLOATS   (DDIM * FC_KC)      // 12800
#define WVV_FLOATS (FC_ROWS * FC_KC)   // 6400
#define FC_SMEM    (2 * (W_FLOATS + WVV_FLOATS) * 4)   // 153600 B

__global__ __launch_bounds__(256) void fc_mix_fused(
    const float* __restrict__ wv, const float* __restrict__ W,
    const float* __restrict__ b, const float* __restrict__ alpha,
    const float* __restrict__ x, float* __restrict__ sem_out)
{
    extern __shared__ float fsm[];
    float* Wt  = fsm;                     // [2][128][100]  row-major
    float* wvt = fsm + 2 * W_FLOATS;      // [2][64][100]   row-major

    const int tid  = threadIdx.x;
    const int tx   = tid & 15;            // d-lane 0..15
    const int ty   = tid >> 4;            // m-group 0..15
    const int row0 = blockIdx.x * FC_ROWS;

    const uint32_t WtU  = smem_u32(Wt);
    const uint32_t wvtU = smem_u32(wvt);

    auto stage_chunk = [&](int c, int buf) {
        uint32_t wdst = WtU + (uint32_t)(buf * W_FLOATS * 4);
        const float* wsrc = W + c * FC_KC;
        #pragma unroll 4
        for (int l = tid; l < DDIM * (FC_KC / 4); l += 256) {   // 3200 f4
            int d = l / 25, f4 = l - d * 25;
            cp16(wdst + (uint32_t)l * 16, wsrc + (size_t)d * WVDIM + f4 * 4);
        }
        uint32_t vdst = wvtU + (uint32_t)(buf * WVV_FLOATS * 4);
        const float* vsrc = wv + (size_t)row0 * WVDIM + c * FC_KC;
        #pragma unroll 4
        for (int l = tid; l < FC_ROWS * (FC_KC / 4); l += 256) { // 1600 f4
            int m = l / 25, f4 = l - m * 25;
            cp16(vdst + (uint32_t)l * 16, vsrc + (size_t)m * WVDIM + f4 * 4);
        }
    };

    float acc[4][8];
    #pragma unroll
    for (int i = 0; i < 4; i++)
        #pragma unroll
        for (int j = 0; j < 8; j++) acc[i][j] = 0.f;

    stage_chunk(0, 0);
    cp_commit();

    for (int c = 0; c < FC_CHUNKS; c++) {
        const int buf = c & 1;
        cp_wait0();
        __syncthreads();
        if (c + 1 < FC_CHUNKS) {
            stage_chunk(c + 1, buf ^ 1);
            cp_commit();
        }
        const float4* Wd  = reinterpret_cast<const float4*>(Wt  + buf * W_FLOATS);
        const float4* wvd = reinterpret_cast<const float4*>(wvt + buf * WVV_FLOATS);

        #pragma unroll 5
        for (int k4 = 0; k4 < FC_KC / 4; k4++) {
            float4 wf[8], vf[4];
            #pragma unroll
            for (int j = 0; j < 8; j++) wf[j] = Wd[(tx + 16 * j) * 25 + k4];
            #pragma unroll
            for (int i = 0; i < 4; i++) vf[i] = wvd[(ty * 4 + i) * 25 + k4];
            #pragma unroll
            for (int i = 0; i < 4; i++) {
                #pragma unroll
                for (int j = 0; j < 8; j++) {
                    float s = acc[i][j];
                    s = fmaf(vf[i].x, wf[j].x, s);
                    s = fmaf(vf[i].y, wf[j].y, s);
                    s = fmaf(vf[i].z, wf[j].z, s);
                    s = fmaf(vf[i].w, wf[j].w, s);
                    acc[i][j] = s;
                }
            }
        }
    }

    float bd[8];
    #pragma unroll
    for (int j = 0; j < 8; j++) bd[j] = b[tx + 16 * j];

    #pragma unroll
    for (int i = 0; i < 4; i++) {
        const int row = row0 + ty * 4 + i;
        const float al = alpha[row];
        float xv[8];
        #pragma unroll
        for (int j = 0; j < 8; j++) xv[j] = x[(size_t)row * DDIM + tx + 16 * j];

        float sv[8];
        float pssq = 0.f, pxsq = 0.f;
        #pragma unroll
        for (int j = 0; j < 8; j++) {
            float s = al * (acc[i][j] + bd[j]) + (1.f - al) * xv[j];
            sv[j] = s;
            pssq = fmaf(s, s, pssq);
            pxsq = fmaf(xv[j], xv[j], pxsq);
        }

        #pragma unroll
        for (int j = 0; j < 8; j++) {
            sem_out[(size_t)row * DDIM + tx + 16 * j] = sv[j];
            g_semA[(size_t)row * DDIM + tx + 16 * j] = __float2half(-2.f * sv[j]);
            g_xH[(size_t)row * DDIM + tx + 16 * j]   = __float2half(xv[j]);
        }

        #pragma unroll
        for (int o = 1; o <= 8; o <<= 1) {
            pssq += __shfl_xor_sync(0xFFFFFFFFu, pssq, o);
            pxsq += __shfl_xor_sync(0xFFFFFFFFu, pxsq, o);
        }
        if (tx == 0) {
            g_ssq[row] = pssq;
            g_xsq[row] = pxsq;
        }
    }
}

// ---------------------------------------------------------------------------
// Kernel B: persistent distance + batch-hard mining, 512 THREADS (16 warps).
// 128 CTAs; CTA = 64-row m-strip, 64 n-tiles of 128 cols.
// Warp grid 2m x 8n: each warp 32 rows x 16 cols -> 4 MMA + 1 ldsm per
// k-step, c-acc 16 regs, metadata 8 regs.  8 pair-private 16-col slabs
// (4KB x 2 buffers each), named barrier per pair -> pairs drift freely.
// Same total work as R12-R14; 2x warps per SMSP to fill idle issue slots.
// ---------------------------------------------------------------------------
#define A_BYTES    16384                    // 64 rows x 256 B
#define SLAB       4096                     // 16 rows x 256 B
#define PAIR_BYTES (2 * SLAB)
#define DIST_DSMEM (A_BYTES + 8 * PAIR_BYTES)   // 81920

#define NSTEPS 64

__global__ __launch_bounds__(512, 1) void dist_persist(
    const int* __restrict__ label, float* __restrict__ diff_out)
{
    extern __shared__ char dyn[];
    __shared__ float aggF[8 * 64];
    __shared__ float aggC[8 * 64];

    const int tid  = threadIdx.x;
    const int wid  = tid >> 5;
    const int lane = tid & 31;
    const int rowbase = blockIdx.x * 64;

    // ---- stage A strip (64 rows x 16 chunks of 16B), swizzled key r&7 ----
    {
        const uint4* gA = reinterpret_cast<const uint4*>(g_semA) + (size_t)rowbase * 16;
        #pragma unroll
        for (int it = 0; it < 2; it++) {
            int idx = it * 512 + tid;          // 0..1023
            int r = idx >> 4, cch = idx & 15;
            uint32_t off = (uint32_t)(r * 256 + ((cch ^ (r & 7)) << 4));
            *reinterpret_cast<uint4*>(dyn + off) = gA[(size_t)r * 16 + cch];
        }
    }
    __syncthreads();

    const uint32_t AsU = smem_u32(dyn);

    const int wm = wid & 1;            // 2 m-slabs of 32
    const int wn = wid >> 1;           // 8 n-slabs of 16 (= pair id)
    const int m_base = wm * 32;
    const int n_base = wn * 16;
    const int pt     = wm * 32 + lane; // pair-local thread 0..63
    const int barid  = 1 + wn;         // named barriers 1..8

    const uint32_t pairU = AsU + A_BYTES + wn * PAIR_BYTES;

    // ---- preload ALL A fragments (hi only) into registers ----
    uint32_t aF[8][2][4];              // [kstep][mt][4]
    {
        const uint32_t a_chunk_add = (uint32_t)(lane >> 4);
        #pragma unroll
        for (int mt = 0; mt < 2; mt++) {
            int r = m_base + mt * 16 + (lane & 15);
            uint32_t base = AsU + r * 256;
            uint32_t sw   = (uint32_t)(r & 7);
            #pragma unroll
            for (int s = 0; s < 8; s++) {
                uint32_t ch = (uint32_t)(s * 2) + a_chunk_add;
                ldsm_x4(aF[s][mt], base + ((ch ^ sw) << 4));
            }
        }
    }

    // B ldsm addressing within a 16-row x 256B slab (one x4 = both n8 bricks)
    const int brow = ((lane >> 4) << 3) + (lane & 7);    // 0..15
    const uint32_t b_off = pairU + brow * 256;
    const uint32_t b_sw  = (uint32_t)(brow & 7);
    const uint32_t b_chunk_add = (uint32_t)((lane >> 3) & 1);

    // per-thread row info
    const int q  = lane >> 2;
    const int qt = lane & 3;
    int row_gi[2][2];
    int lmv[2][2];
    #pragma unroll
    for (int mt = 0; mt < 2; mt++)
        #pragma unroll
        for (int hr = 0; hr < 2; hr++) {
            row_gi[mt][hr] = rowbase + m_base + mt * 16 + hr * 8 + q;
            lmv[mt][hr]    = label[row_gi[mt][hr]];
        }

    float fpU[2][2], cnU[2][2];
    #pragma unroll
    for (int mt = 0; mt < 2; mt++)
        #pragma unroll
        for (int hr = 0; hr < 2; hr++) { fpU[mt][hr] = NEGINF; cnU[mt][hr] = POSINF; }

    // ---- pair-private slab staging: 16 rows x 16 chunks, 64 threads ----
    auto stage_slab = [&](int t, int buf) {
        const char* gB = reinterpret_cast<const char*>(g_xH)
                       + (size_t)(t * 128 + n_base) * 256;
        uint32_t bb = pairU + buf * SLAB;
        #pragma unroll
        for (int it = 0; it < 4; it++) {
            int idx = it * 64 + pt;            // 0..255
            int r = idx >> 4, cch = idx & 15;
            uint32_t dst = bb + (uint32_t)(r * 256 + ((cch ^ (r & 7)) << 4));
            cp16(dst, gB + (size_t)r * 256 + cch * 16);
        }
    };

    const int t_diag = (int)(blockIdx.x >> 1);

    stage_slab(0, 0);
    cp_commit();

    for (int t = 0; t < NSTEPS; t++) {
        const int buf = t & 1;
        const int n0  = t * 128;

        if (t + 1 < NSTEPS) {
            stage_slab(t + 1, buf ^ 1);
            cp_commit();
            cp_wait1();
        } else {
            cp_wait0();
        }
        bar_named(barid, 64);

        // mining metadata (L1-hot LDG): 4 cols per thread
        float xq[4]; int lb[4];
        #pragma unroll
        for (int k = 0; k < 4; k++) {
            int cl = n0 + n_base + (k >> 1) * 8 + qt * 2 + (k & 1);
            xq[k] = g_xsq[cl];
            lb[k] = label[cl];
        }

        float c[2][2][4];
        #pragma unroll
        for (int mt = 0; mt < 2; mt++)
            #pragma unroll
            for (int nt = 0; nt < 2; nt++)
                #pragma unroll
                for (int e = 0; e < 4; e++) c[mt][nt][e] = 0.f;

        const uint32_t bufAdd = (uint32_t)(buf * SLAB);
        #pragma unroll
        for (int s = 0; s < 8; s++) {
            uint32_t bfr[4];
            uint32_t chB = (uint32_t)(s * 2) + b_chunk_add;
            ldsm_x4(bfr, b_off + bufAdd + ((chB ^ b_sw) << 4));

            #pragma unroll
            for (int mt = 0; mt < 2; mt++) {
                #pragma unroll
                for (int nt = 0; nt < 2; nt++) {
                    mma16816h(c[mt][nt], aF[s][mt], &bfr[nt * 2]);   // Ah*Bh
                }
            }
        }

        // ---- mining on u = xsq[col] + (-2 sem.x) ----
        if (t == t_diag) {
            #pragma unroll
            for (int mt = 0; mt < 2; mt++) {
                #pragma unroll
                for (int hr = 0; hr < 2; hr++) {
                    const int gi = row_gi[mt][hr];
                    const int lm = lmv[mt][hr];
                    float fb = fpU[mt][hr], cb = cnU[mt][hr];
                    #pragma unroll
                    for (int nt = 0; nt < 2; nt++) {
                        #pragma unroll
                        for (int w = 0; w < 2; w++) {
                            int k  = nt * 2 + w;
                            int cl = n0 + n_base + nt * 8 + qt * 2 + w;
                            float u = xq[k] + c[mt][nt][hr * 2 + w];
                            bool same = (lm == lb[k]);
                            bool self = (cl == gi);
                            fb = fmaxf(fb, (same && !self) ? u : NEGINF);
                            cb = fminf(cb, same ? POSINF : u);
                        }
                    }
                    fpU[mt][hr] = fb;
                    cnU[mt][hr] = cb;
                }
            }
        } else {
            #pragma unroll
            for (int mt = 0; mt < 2; mt++) {
                #pragma unroll
                for (int hr = 0; hr < 2; hr++) {
                    const int lm = lmv[mt][hr];
                    float fb = fpU[mt][hr], cb = cnU[mt][hr];
                    #pragma unroll
                    for (int nt = 0; nt < 2; nt++) {
                        #pragma unroll
                        for (int w = 0; w < 2; w++) {
                            int k = nt * 2 + w;
                            float u = xq[k] + c[mt][nt][hr * 2 + w];
                            bool same = (lm == lb[k]);
                            fb = fmaxf(fb, same ? u : NEGINF);
                            cb = fminf(cb, same ? POSINF : u);
                        }
                    }
                    fpU[mt][hr] = fb;
                    cnU[mt][hr] = cb;
                }
            }
        }

        bar_named(barid, 64);
    }

    // ---- final reduction: quad lanes -> smem across wn warps -> softplus ----
    #pragma unroll
    for (int mt = 0; mt < 2; mt++) {
        #pragma unroll
        for (int hr = 0; hr < 2; hr++) {
            float fb = fpU[mt][hr], cb = cnU[mt][hr];
            #pragma unroll
            for (int o = 1; o <= 2; o <<= 1) {
                fb = fmaxf(fb, __shfl_xor_sync(0xFFFFFFFFu, fb, o));
                cb = fminf(cb, __shfl_xor_sync(0xFFFFFFFFu, cb, o));
            }
            if (qt == 0) {
                int r = m_base + mt * 16 + hr * 8 + q;
                aggF[wn * 64 + r] = fb;
                aggC[wn * 64 + r] = cb;
            }
        }
    }
    __syncthreads();

    if (tid < 64) {
        float fb = NEGINF, cb = POSINF;
        #pragma unroll
        for (int wnn = 0; wnn < 8; wnn++) {
            fb = fmaxf(fb, aggF[wnn * 64 + tid]);
            cb = fminf(cb, aggC[wnn * 64 + tid]);
        }
        float ssqm = g_ssq[rowbase + tid];
        float fp = (fb < -1e37f) ? 0.f : sqrtf(fmaxf(ssqm + fb, 0.f) + DEPS);
        float cn = sqrtf(fmaxf(ssqm + cb, 0.f) + DEPS);
        float z = fp - cn;
        diff_out[rowbase + tid] = fmaxf(z, 0.f) + log1pf(expf(-fabsf(z)));
    }
}

// ---------------------------------------------------------------------------
// Launch
// Inputs: x[N,128] f32, wv[N,300] f32, label[N] i32, alpha[N,1] f32,
//         W[128,300] f32, b[128] f32
// Output: diff[N] then sem[N,128] (float32, concatenated)
// ---------------------------------------------------------------------------
extern "C" void kernel_launch(void* const* d_in, const int* in_sizes, int n_in,
                              void* d_out, int out_size)
{
    const float* x     = (const float*)d_in[0];
    const float* wv    = (const float*)d_in[1];
    const int*   label = (const int*)  d_in[2];
    const float* alpha = (const float*)d_in[3];
    const float* W     = (const float*)d_in[4];
    const float* b     = (const float*)d_in[5];

    float* out  = (float*)d_out;
    float* diff = out;            // [N]
    float* sem  = out + NROWS;    // [N, 128]

    static bool attr_set = false;
    if (!attr_set) {
        cudaFuncSetAttribute(dist_persist,
                             cudaFuncAttributeMaxDynamicSharedMemorySize, DIST_DSMEM);
        cudaFuncSetAttribute(fc_mix_fused,
                             cudaFuncAttributeMaxDynamicSharedMemorySize, FC_SMEM);
        attr_set = true;
    }

    fc_mix_fused<<<NROWS / FC_ROWS, 256, FC_SMEM>>>(wv, W, b, alpha, x, sem);
    dist_persist<<<NROWS / 64, 512, DIST_DSMEM>>>(label, diff);
}